// round 2
// baseline (speedup 1.0000x reference)
#include <cuda_runtime.h>
#include <math.h>

// Problem constants
#define Bc 4
#define Sc 2048
#define Ic 512
#define Dc 512
#define Hc 8
#define HDc 64
#define Pc 720

// Scratch (device globals — no allocation allowed)
__device__ float g_qkv[Bc*Sc*3*Dc];      // [b,s, q(512)|k(512)|v(512)]
__device__ float g_kT [Bc*Hc*HDc*Sc];    // [b,h,d,s]
__device__ float g_comb[Bc*Sc*Dc];       // [b,s,d] concat heads
__device__ float g_up [Bc*Pc*Dc];        // [b,p,d]
__device__ float g_wcat[Ic*3*Dc];        // [i][n] n = sec*512 + h*64 + d
__device__ float g_bcat[3*Dc];
__device__ float g_woT[Dc*Ic];           // [d][o] = Wo[o][d]

// ---------------------------------------------------------------------------
// Pack weights: concat Wq|Wk|Wv into [K=512, N=1536], bias cat, transpose Wo
// ---------------------------------------------------------------------------
__global__ void pack_kernel(const float* __restrict__ Wq, const float* __restrict__ bq,
                            const float* __restrict__ Wk, const float* __restrict__ bk,
                            const float* __restrict__ Wv, const float* __restrict__ bv,
                            const float* __restrict__ Wo)
{
    const int NW  = Ic*3*Dc;     // 786432
    const int NWO = Dc*Ic;       // 262144
    int gid = blockIdx.x*blockDim.x + threadIdx.x;
    if (gid < NW) {
        int i = gid / (3*Dc);
        int n = gid % (3*Dc);
        int sec = n / Dc;
        int nn  = n % Dc;           // = h*64 + d
        const float* W = (sec==0) ? Wq : (sec==1) ? Wk : Wv;
        // W is [H, I, HD]: element (h, i, d)
        int h = nn / HDc, d = nn % HDc;
        g_wcat[gid] = W[(h*Ic + i)*HDc + d];
    } else if (gid < NW + NWO) {
        int t = gid - NW;
        int d = t / Ic, o = t % Ic;
        g_woT[t] = Wo[o*Dc + d];
    } else if (gid < NW + NWO + 3*Dc) {
        int n = gid - NW - NWO;
        int sec = n / Dc, nn = n % Dc;
        const float* bv_ = (sec==0) ? bq : (sec==1) ? bk : bv;
        g_bcat[n] = bv_[nn];
    }
}

// ---------------------------------------------------------------------------
// Generic SGEMM: C[M,N] = A[M,K] * B[K,N] (+bias), 128x64 tile, BK=16
// biasMode: 0 none, 1 per-column (bias[n]), 2 per-row (bias[m])
// ---------------------------------------------------------------------------
__global__ __launch_bounds__(256)
void sgemm_kernel(const float* __restrict__ A, long long strideA,
                  const float* __restrict__ Bm, long long strideB,
                  float* __restrict__ C, long long strideC,
                  int M, int N, int K,
                  const float* __restrict__ bias, int biasMode)
{
    A  += (long long)blockIdx.z * strideA;
    Bm += (long long)blockIdx.z * strideB;
    C  += (long long)blockIdx.z * strideC;

    __shared__ float As[16][128];   // [k][m]
    __shared__ float Bs[16][64];    // [k][n]

    int tid = threadIdx.x;
    int tx = tid & 15;      // 0..15 -> 4 cols each
    int ty = tid >> 4;      // 0..15 -> 8 rows each
    int m0 = blockIdx.y * 128;
    int n0 = blockIdx.x * 64;

    float acc[8][4];
#pragma unroll
    for (int i = 0; i < 8; i++)
#pragma unroll
        for (int j = 0; j < 4; j++) acc[i][j] = 0.f;

    for (int k0 = 0; k0 < K; k0 += 16) {
        // Load A tile (128x16), transposed into As[k][m]
#pragma unroll
        for (int l = 0; l < 2; l++) {
            int lin = tid + l*256;            // 0..511 float4 slots
            int row = lin >> 2;               // 0..127
            int kc  = (lin & 3) << 2;         // 0,4,8,12
            float4 v = make_float4(0.f,0.f,0.f,0.f);
            if (m0 + row < M)
                v = *(const float4*)&A[(long long)(m0+row)*K + k0 + kc];
            As[kc+0][row] = v.x;
            As[kc+1][row] = v.y;
            As[kc+2][row] = v.z;
            As[kc+3][row] = v.w;
        }
        // Load B tile (16x64)
        {
            int kr = tid >> 4;                // 0..15
            int nc = (tid & 15) << 2;         // 0..60
            *(float4*)&Bs[kr][nc] = *(const float4*)&Bm[(long long)(k0+kr)*N + n0 + nc];
        }
        __syncthreads();
#pragma unroll
        for (int k = 0; k < 16; k++) {
            float a[8], bb[4];
            *(float4*)&a[0] = *(float4*)&As[k][ty*8];
            *(float4*)&a[4] = *(float4*)&As[k][ty*8+4];
            *(float4*)&bb[0] = *(float4*)&Bs[k][tx*4];
#pragma unroll
            for (int i = 0; i < 8; i++)
#pragma unroll
                for (int j = 0; j < 4; j++)
                    acc[i][j] = fmaf(a[i], bb[j], acc[i][j]);
        }
        __syncthreads();
    }

#pragma unroll
    for (int i = 0; i < 8; i++) {
        int m = m0 + ty*8 + i;
        if (m >= M) continue;
        float brow = (biasMode == 2) ? bias[m] : 0.f;
        float4 out;
        float v0 = acc[i][0] + brow;
        float v1 = acc[i][1] + brow;
        float v2 = acc[i][2] + brow;
        float v3 = acc[i][3] + brow;
        if (biasMode == 1) {
            v0 += bias[n0 + tx*4 + 0];
            v1 += bias[n0 + tx*4 + 1];
            v2 += bias[n0 + tx*4 + 2];
            v3 += bias[n0 + tx*4 + 3];
        }
        out.x = v0; out.y = v1; out.z = v2; out.w = v3;
        *(float4*)&C[(long long)m*N + n0 + tx*4] = out;
    }
}

// ---------------------------------------------------------------------------
// Transpose K: g_qkv k-section [b,s,h,d] -> g_kT [b,h,d,s]
// grid: (S/32, HD/32=2, B*H), block (32,8)
// ---------------------------------------------------------------------------
__global__ void transposeK_kernel()
{
    __shared__ float tile[32][33];
    int bh = blockIdx.z;
    int b = bh / Hc, h = bh % Hc;
    int s0 = blockIdx.x * 32;
    int d0 = blockIdx.y * 32;
    int tx = threadIdx.x, ty = threadIdx.y;

#pragma unroll
    for (int r = ty; r < 32; r += 8) {
        int s = s0 + r;
        tile[r][tx] = g_qkv[((long long)(b*Sc + s))*(3*Dc) + Dc + h*HDc + d0 + tx];
    }
    __syncthreads();
#pragma unroll
    for (int r = ty; r < 32; r += 8) {
        int d = d0 + r;
        g_kT[(((long long)bh)*HDc + d)*Sc + s0 + tx] = tile[tx][r];
    }
}

// ---------------------------------------------------------------------------
// Flash attention (fp32): 32 query rows per block, 64-key tiles, HD=64.
// Writes combined [b,s, h*64+d].
// grid: (S/32, H, B), 256 threads (tx=tid&15: 4 cols, ty=tid>>4: 2 rows)
// ---------------------------------------------------------------------------
__global__ __launch_bounds__(256)
void attn_kernel()
{
    __shared__ float Qs[64][32];     // [feat][qrow], q pre-scaled by 1/64
    __shared__ float KP[64*64];      // K as [feat][key] (ld 64); P as [key][qrow] (ld 33)
    __shared__ float Vs[64][64];     // [key][feat]

    int tid = threadIdx.x;
    int tx = tid & 15;   // 4 feat/key cols each
    int ty = tid >> 4;   // 2 q rows each
    int q0 = blockIdx.x * 32;
    int h  = blockIdx.y;
    int b  = blockIdx.z;

    // Load + transpose + scale Q tile (32 rows x 64 feats)
#pragma unroll
    for (int l = 0; l < 2; l++) {
        int lin = tid + l*256;          // 0..511 float4 slots
        int row = lin >> 4;             // 0..31
        int c4  = (lin & 15) << 2;      // 0..60
        float4 v = *(const float4*)&g_qkv[((long long)(b*Sc + q0 + row))*(3*Dc) + h*HDc + c4];
        const float sc = 1.0f / (float)HDc;
        Qs[c4+0][row] = v.x * sc;
        Qs[c4+1][row] = v.y * sc;
        Qs[c4+2][row] = v.z * sc;
        Qs[c4+3][row] = v.w * sc;
    }

    float o[2][4];
#pragma unroll
    for (int r = 0; r < 2; r++)
#pragma unroll
        for (int j = 0; j < 4; j++) o[r][j] = 0.f;
    float mrun[2] = {-1e30f, -1e30f};
    float lrun[2] = {0.f, 0.f};

    for (int t0 = 0; t0 < Sc; t0 += 64) {
        __syncthreads();  // prev-iter P/V reads done; Q ready on iter 0

        // Load K tile from pre-transposed g_kT: [feat d][key t]
#pragma unroll
        for (int lq = 0; lq < 4; lq++) {
            int lin = tid + lq*256;
            int d  = lin >> 4;              // 0..63
            int c4 = (lin & 15) << 2;       // 0..60
            *(float4*)&KP[d*64 + c4] =
                *(const float4*)&g_kT[((long long)(b*Hc + h)*HDc + d)*Sc + t0 + c4];
        }
        // Load V tile: [key t][feat]
#pragma unroll
        for (int lq = 0; lq < 4; lq++) {
            int lin = tid + lq*256;
            int t  = lin >> 4;
            int c4 = (lin & 15) << 2;
            *(float4*)&Vs[t][c4] =
                *(const float4*)&g_qkv[((long long)(b*Sc + t0 + t))*(3*Dc) + 2*Dc + h*HDc + c4];
        }
        __syncthreads();

        // Scores: s[r][c] = sum_k Qs[k][row] * K[k][col]   (2x4 per thread)
        float sc_[2][4];
#pragma unroll
        for (int r = 0; r < 2; r++)
#pragma unroll
            for (int j = 0; j < 4; j++) sc_[r][j] = 0.f;
#pragma unroll
        for (int k = 0; k < 64; k++) {
            float qa = Qs[k][ty*2 + 0];
            float qb = Qs[k][ty*2 + 1];
            float4 kv = *(float4*)&KP[k*64 + tx*4];
            sc_[0][0] = fmaf(qa, kv.x, sc_[0][0]);
            sc_[0][1] = fmaf(qa, kv.y, sc_[0][1]);
            sc_[0][2] = fmaf(qa, kv.z, sc_[0][2]);
            sc_[0][3] = fmaf(qa, kv.w, sc_[0][3]);
            sc_[1][0] = fmaf(qb, kv.x, sc_[1][0]);
            sc_[1][1] = fmaf(qb, kv.y, sc_[1][1]);
            sc_[1][2] = fmaf(qb, kv.z, sc_[1][2]);
            sc_[1][3] = fmaf(qb, kv.w, sc_[1][3]);
        }

        // Online softmax update (reduce across the 16 tx lanes)
#pragma unroll
        for (int r = 0; r < 2; r++) {
            float mm = fmaxf(fmaxf(sc_[r][0], sc_[r][1]), fmaxf(sc_[r][2], sc_[r][3]));
#pragma unroll
            for (int w = 1; w < 16; w <<= 1)
                mm = fmaxf(mm, __shfl_xor_sync(0xffffffffu, mm, w));
            float newm = fmaxf(mrun[r], mm);
            float scale = __expf(mrun[r] - newm);
            float sum = 0.f;
#pragma unroll
            for (int j = 0; j < 4; j++) {
                sc_[r][j] = __expf(sc_[r][j] - newm);
                sum += sc_[r][j];
            }
#pragma unroll
            for (int w = 1; w < 16; w <<= 1)
                sum += __shfl_xor_sync(0xffffffffu, sum, w);
            lrun[r] = lrun[r]*scale + sum;
#pragma unroll
            for (int j = 0; j < 4; j++) o[r][j] *= scale;
            mrun[r] = newm;
        }

        __syncthreads();   // all K reads done, safe to overwrite with P

        // Write P (exp scores) as [key][qrow], ld 33
#pragma unroll
        for (int r = 0; r < 2; r++)
#pragma unroll
            for (int j = 0; j < 4; j++)
                KP[(tx*4 + j)*33 + ty*2 + r] = sc_[r][j];
        __syncthreads();

        // AV: o[r][c] += sum_t P[t][row] * V[t][col]
#pragma unroll
        for (int t = 0; t < 64; t++) {
            float p0 = KP[t*33 + ty*2 + 0];
            float p1 = KP[t*33 + ty*2 + 1];
            float4 vv = *(float4*)&Vs[t][tx*4];
            o[0][0] = fmaf(p0, vv.x, o[0][0]);
            o[0][1] = fmaf(p0, vv.y, o[0][1]);
            o[0][2] = fmaf(p0, vv.z, o[0][2]);
            o[0][3] = fmaf(p0, vv.w, o[0][3]);
            o[1][0] = fmaf(p1, vv.x, o[1][0]);
            o[1][1] = fmaf(p1, vv.y, o[1][1]);
            o[1][2] = fmaf(p1, vv.z, o[1][2]);
            o[1][3] = fmaf(p1, vv.w, o[1][3]);
        }
    }

    // Epilogue: normalize and write combined [b, s, h*64 + feat]
#pragma unroll
    for (int r = 0; r < 2; r++) {
        float inv = 1.0f / lrun[r];
        int s = q0 + ty*2 + r;
        float4 out;
        out.x = o[r][0] * inv;
        out.y = o[r][1] * inv;
        out.z = o[r][2] * inv;
        out.w = o[r][3] * inv;
        *(float4*)&g_comb[((long long)(b*Sc + s))*Dc + h*HDc + tx*4] = out;
    }
}

// ---------------------------------------------------------------------------
// Launch
// ---------------------------------------------------------------------------
extern "C" void kernel_launch(void* const* d_in, const int* in_sizes, int n_in,
                              void* d_out, int out_size)
{
    const float* inputs = (const float*)d_in[0];
    const float* Wq = (const float*)d_in[1];
    const float* bq = (const float*)d_in[2];
    const float* Wk = (const float*)d_in[3];
    const float* bk = (const float*)d_in[4];
    const float* Wv = (const float*)d_in[5];
    const float* bv = (const float*)d_in[6];
    const float* Wt = (const float*)d_in[7];
    const float* bt = (const float*)d_in[8];
    const float* Wo = (const float*)d_in[9];
    const float* bo = (const float*)d_in[10];
    float* out = (float*)d_out;

    float *p_qkv, *p_kT, *p_comb, *p_up, *p_wcat, *p_bcat, *p_woT;
    cudaGetSymbolAddress((void**)&p_qkv,  g_qkv);
    cudaGetSymbolAddress((void**)&p_kT,   g_kT);
    cudaGetSymbolAddress((void**)&p_comb, g_comb);
    cudaGetSymbolAddress((void**)&p_up,   g_up);
    cudaGetSymbolAddress((void**)&p_wcat, g_wcat);
    cudaGetSymbolAddress((void**)&p_bcat, g_bcat);
    cudaGetSymbolAddress((void**)&p_woT,  g_woT);
    (void)p_kT; (void)in_sizes; (void)n_in; (void)out_size;

    // 1. Pack weights
    {
        int total = Ic*3*Dc + Dc*Ic + 3*Dc;
        pack_kernel<<<(total + 255)/256, 256>>>(Wq, bq, Wk, bk, Wv, bv, Wo);
    }

    // 2. QKV GEMM: [8192, 512] x [512, 1536] -> g_qkv
    {
        dim3 grid(3*Dc/64, (Bc*Sc)/128, 1);   // 24 x 64
        sgemm_kernel<<<grid, 256>>>(inputs, 0, p_wcat, 0, p_qkv, 0,
                                    Bc*Sc, 3*Dc, Ic, p_bcat, 1);
    }

    // 3. Transpose K to [b,h,d,s]
    transposeK_kernel<<<dim3(Sc/32, HDc/32, Bc*Hc), dim3(32, 8)>>>();

    // 4. Attention -> g_comb
    attn_kernel<<<dim3(Sc/32, Hc, Bc), 256>>>();

    // 5. Temporal GEMM per batch: Wt[720,2048] x comb_b[2048,512] -> up_b[720,512] (+bt per-row)
    {
        dim3 grid(Dc/64, (Pc + 127)/128, Bc);  // 8 x 6 x 4
        sgemm_kernel<<<grid, 256>>>(Wt, 0,
                                    p_comb, (long long)Sc*Dc,
                                    p_up,   (long long)Pc*Dc,
                                    Pc, Dc, Sc, bt, 2);
    }

    // 6. Output GEMM: up[2880,512] x WoT[512,512] -> out[2880,512] (+bo per-col)
    {
        dim3 grid(Ic/64, (Bc*Pc + 127)/128, 1);  // 8 x 23
        sgemm_kernel<<<grid, 256>>>(p_up, 0, p_woT, 0, out, 0,
                                    Bc*Pc, Ic, Dc, bo, 1);
    }
}

// round 4
// speedup vs baseline: 1.3733x; 1.3733x over previous
#include <cuda_runtime.h>
#include <math.h>

// Problem constants
#define Bc 4
#define Sc 2048
#define Ic 512
#define Dc 512
#define Hc 8
#define HDc 64
#define Pc 720

// Scratch (device globals — no allocation allowed)
__device__ float g_qkv[Bc*Sc*3*Dc];      // [b,s, q(512)|k(512)|v(512)]
__device__ float g_kT [Bc*Hc*HDc*Sc];    // [b,h,d,s]
__device__ float g_comb[Bc*Sc*Dc];       // [b,s,d] concat heads
__device__ float g_up [Bc*Pc*Dc];        // [b,p,d]
__device__ float g_wcat[Ic*3*Dc];        // [i][n] n = sec*512 + h*64 + d
__device__ float g_bcat[3*Dc];
__device__ float g_woT[Dc*Ic];           // [d][o] = Wo[o][d]

// ---------------------------------------------------------------------------
// Pack weights
// ---------------------------------------------------------------------------
__global__ void pack_kernel(const float* __restrict__ Wq, const float* __restrict__ bq,
                            const float* __restrict__ Wk, const float* __restrict__ bk,
                            const float* __restrict__ Wv, const float* __restrict__ bv,
                            const float* __restrict__ Wo)
{
    const int NW  = Ic*3*Dc;
    const int NWO = Dc*Ic;
    int gid = blockIdx.x*blockDim.x + threadIdx.x;
    if (gid < NW) {
        int i = gid / (3*Dc);
        int n = gid % (3*Dc);
        int sec = n / Dc;
        int nn  = n % Dc;
        const float* W = (sec==0) ? Wq : (sec==1) ? Wk : Wv;
        int h = nn / HDc, d = nn % HDc;
        g_wcat[gid] = W[(h*Ic + i)*HDc + d];
    } else if (gid < NW + NWO) {
        int t = gid - NW;
        int d = t / Ic, o = t % Ic;
        g_woT[t] = Wo[o*Dc + d];
    } else if (gid < NW + NWO + 3*Dc) {
        int n = gid - NW - NWO;
        int sec = n / Dc, nn = n % Dc;
        const float* bv_ = (sec==0) ? bq : (sec==1) ? bk : bv;
        g_bcat[n] = bv_[nn];
    }
}

// ---------------------------------------------------------------------------
// SGEMM 128x128 tile, BK=16, 8x8 per thread, 256 threads
// biasMode: 0 none, 1 per-column, 2 per-row
// ---------------------------------------------------------------------------
__global__ __launch_bounds__(256)
void sgemm128_kernel(const float* __restrict__ A, long long strideA,
                     const float* __restrict__ Bm, long long strideB,
                     float* __restrict__ C, long long strideC,
                     int M, int N, int K,
                     const float* __restrict__ bias, int biasMode)
{
    A  += (long long)blockIdx.z * strideA;
    Bm += (long long)blockIdx.z * strideB;
    C  += (long long)blockIdx.z * strideC;

    __shared__ float As[16][132];   // [k][m], padded
    __shared__ float Bs[16][128];   // [k][n]

    int tid = threadIdx.x;
    int tx = tid & 15;      // 8 cols each
    int ty = tid >> 4;      // 8 rows each
    int m0 = blockIdx.y * 128;
    int n0 = blockIdx.x * 128;

    float acc[8][8];
#pragma unroll
    for (int i = 0; i < 8; i++)
#pragma unroll
        for (int j = 0; j < 8; j++) acc[i][j] = 0.f;

    for (int k0 = 0; k0 < K; k0 += 16) {
        // A tile (128x16) -> As[k][m]
#pragma unroll
        for (int l = 0; l < 2; l++) {
            int lin = tid + l*256;            // 0..511 float4 slots
            int row = lin >> 2;               // 0..127
            int kc  = (lin & 3) << 2;         // 0,4,8,12
            float4 v = make_float4(0.f,0.f,0.f,0.f);
            if (m0 + row < M)
                v = *(const float4*)&A[(long long)(m0+row)*K + k0 + kc];
            As[kc+0][row] = v.x;
            As[kc+1][row] = v.y;
            As[kc+2][row] = v.z;
            As[kc+3][row] = v.w;
        }
        // B tile (16x128)
#pragma unroll
        for (int l = 0; l < 2; l++) {
            int lin = tid + l*256;
            int kr = lin >> 5;                // 0..15
            int nc = (lin & 31) << 2;         // 0..124
            *(float4*)&Bs[kr][nc] = *(const float4*)&Bm[(long long)(k0+kr)*N + n0 + nc];
        }
        __syncthreads();
#pragma unroll
        for (int k = 0; k < 16; k++) {
            float a[8], bb[8];
            *(float4*)&a[0]  = *(float4*)&As[k][ty*8];
            *(float4*)&a[4]  = *(float4*)&As[k][ty*8+4];
            *(float4*)&bb[0] = *(float4*)&Bs[k][tx*8];
            *(float4*)&bb[4] = *(float4*)&Bs[k][tx*8+4];
#pragma unroll
            for (int i = 0; i < 8; i++)
#pragma unroll
                for (int j = 0; j < 8; j++)
                    acc[i][j] = fmaf(a[i], bb[j], acc[i][j]);
        }
        __syncthreads();
    }

#pragma unroll
    for (int i = 0; i < 8; i++) {
        int m = m0 + ty*8 + i;
        if (m >= M) continue;
        float brow = (biasMode == 2) ? bias[m] : 0.f;
        float v[8];
#pragma unroll
        for (int j = 0; j < 8; j++) {
            v[j] = acc[i][j] + brow;
            if (biasMode == 1) v[j] += bias[n0 + tx*8 + j];
        }
        *(float4*)&C[(long long)m*N + n0 + tx*8]     = *(float4*)&v[0];
        *(float4*)&C[(long long)m*N + n0 + tx*8 + 4] = *(float4*)&v[4];
    }
}

// ---------------------------------------------------------------------------
// Transpose K: g_qkv k-section [b,s,h,d] -> g_kT [b,h,d,s]
// ---------------------------------------------------------------------------
__global__ void transposeK_kernel()
{
    __shared__ float tile[32][33];
    int bh = blockIdx.z;
    int b = bh / Hc, h = bh % Hc;
    int s0 = blockIdx.x * 32;
    int d0 = blockIdx.y * 32;
    int tx = threadIdx.x, ty = threadIdx.y;

#pragma unroll
    for (int r = ty; r < 32; r += 8) {
        int s = s0 + r;
        tile[r][tx] = g_qkv[((long long)(b*Sc + s))*(3*Dc) + Dc + h*HDc + d0 + tx];
    }
    __syncthreads();
#pragma unroll
    for (int r = ty; r < 32; r += 8) {
        int d = d0 + r;
        g_kT[(((long long)bh)*HDc + d)*Sc + s0 + tx] = tile[tx][r];
    }
}

// ---------------------------------------------------------------------------
// Flash attention fp32: 128 query rows/block, 64-key tiles, HD=64.
// 256 threads: tx=tid&15 (4 key-cols / 4 out-feats), ty=tid>>4 (8 q-rows).
// Dynamic smem: Qs[64][132] | Ks[64][64] | Vs[64][64] | Ps[128][68]
// ---------------------------------------------------------------------------
#define QS_LD 132
#define PS_LD 68
#define SM_Q  0
#define SM_K  (64*QS_LD)
#define SM_V  (SM_K + 64*64)
#define SM_P  (SM_V + 64*64)
#define SM_TOT (SM_P + 128*PS_LD)   // 25344 floats = 101376 bytes

__global__ __launch_bounds__(256)
void attn_kernel()
{
    extern __shared__ float sm[];
    float* Qs = sm + SM_Q;   // [feat][qrow] ld 132, pre-scaled 1/64
    float* Ks = sm + SM_K;   // [feat][key]  ld 64
    float* Vs = sm + SM_V;   // [key][feat]  ld 64
    float* Ps = sm + SM_P;   // [qrow][key]  ld 68

    int tid = threadIdx.x;
    int tx = tid & 15;
    int ty = tid >> 4;
    int q0 = blockIdx.x * 128;
    int h  = blockIdx.y;
    int b  = blockIdx.z;
    int bh = b*Hc + h;

    // Load + transpose + scale Q tile (128 rows x 64 feats): 2048 float4 slots
#pragma unroll
    for (int l = 0; l < 8; l++) {
        int lin = tid + l*256;
        int row = lin >> 4;             // 0..127
        int c4  = (lin & 15) << 2;      // 0..60
        float4 v = *(const float4*)&g_qkv[((long long)(b*Sc + q0 + row))*(3*Dc) + h*HDc + c4];
        const float s = 1.0f / (float)HDc;
        Qs[(c4+0)*QS_LD + row] = v.x * s;
        Qs[(c4+1)*QS_LD + row] = v.y * s;
        Qs[(c4+2)*QS_LD + row] = v.z * s;
        Qs[(c4+3)*QS_LD + row] = v.w * s;
    }

    float o[8][4];
    float mrun[8], lrun[8];
#pragma unroll
    for (int r = 0; r < 8; r++) {
        mrun[r] = -1e30f; lrun[r] = 0.f;
#pragma unroll
        for (int j = 0; j < 4; j++) o[r][j] = 0.f;
    }

    for (int t0 = 0; t0 < Sc; t0 += 64) {
        __syncthreads();   // prev AV done (also: Q stores done on iter 0)

        // K tile: [feat d][key], from pre-transposed g_kT, 1024 slots
#pragma unroll
        for (int l = 0; l < 4; l++) {
            int lin = tid + l*256;
            int d  = lin >> 4;
            int c4 = (lin & 15) << 2;
            *(float4*)&Ks[d*64 + c4] =
                *(const float4*)&g_kT[((long long)bh*HDc + d)*Sc + t0 + c4];
        }
        // V tile: [key][feat], 1024 slots
#pragma unroll
        for (int l = 0; l < 4; l++) {
            int lin = tid + l*256;
            int t  = lin >> 4;
            int c4 = (lin & 15) << 2;
            *(float4*)&Vs[t*64 + c4] =
                *(const float4*)&g_qkv[((long long)(b*Sc + t0 + t))*(3*Dc) + 2*Dc + h*HDc + c4];
        }
        __syncthreads();

        // QK^T: acc[r][c] = sum_k Qs[k][ty*8+r] * Ks[k][tx*4+c]
        float acc[8][4];
#pragma unroll
        for (int r = 0; r < 8; r++)
#pragma unroll
            for (int j = 0; j < 4; j++) acc[r][j] = 0.f;

#pragma unroll
        for (int k = 0; k < 64; k++) {
            float a[8];
            *(float4*)&a[0] = *(float4*)&Qs[k*QS_LD + ty*8];
            *(float4*)&a[4] = *(float4*)&Qs[k*QS_LD + ty*8 + 4];
            float4 kv = *(float4*)&Ks[k*64 + tx*4];
#pragma unroll
            for (int r = 0; r < 8; r++) {
                acc[r][0] = fmaf(a[r], kv.x, acc[r][0]);
                acc[r][1] = fmaf(a[r], kv.y, acc[r][1]);
                acc[r][2] = fmaf(a[r], kv.z, acc[r][2]);
                acc[r][3] = fmaf(a[r], kv.w, acc[r][3]);
            }
        }

        // Online softmax (reduce across 16 tx lanes)
#pragma unroll
        for (int r = 0; r < 8; r++) {
            float mm = fmaxf(fmaxf(acc[r][0], acc[r][1]), fmaxf(acc[r][2], acc[r][3]));
#pragma unroll
            for (int w = 1; w < 16; w <<= 1)
                mm = fmaxf(mm, __shfl_xor_sync(0xffffffffu, mm, w));
            float newm = fmaxf(mrun[r], mm);
            float corr = __expf(mrun[r] - newm);
            float sum = 0.f;
#pragma unroll
            for (int j = 0; j < 4; j++) {
                acc[r][j] = __expf(acc[r][j] - newm);
                sum += acc[r][j];
            }
#pragma unroll
            for (int w = 1; w < 16; w <<= 1)
                sum += __shfl_xor_sync(0xffffffffu, sum, w);
            lrun[r] = lrun[r]*corr + sum;
            mrun[r] = newm;
#pragma unroll
            for (int j = 0; j < 4; j++) o[r][j] *= corr;
        }

        // Write P [qrow][key] (vectorized, conflict-free)
#pragma unroll
        for (int r = 0; r < 8; r++)
            *(float4*)&Ps[(ty*8+r)*PS_LD + tx*4] = *(float4*)&acc[r][0];
        __syncthreads();

        // AV: o[r][c] += sum_t P[row][t] * Vs[t][c], chunks of 4 keys x 4 rows
#pragma unroll
        for (int tc = 0; tc < 16; tc++) {
            float4 v0 = *(float4*)&Vs[(tc*4+0)*64 + tx*4];
            float4 v1 = *(float4*)&Vs[(tc*4+1)*64 + tx*4];
            float4 v2 = *(float4*)&Vs[(tc*4+2)*64 + tx*4];
            float4 v3 = *(float4*)&Vs[(tc*4+3)*64 + tx*4];
#pragma unroll
            for (int rr = 0; rr < 8; rr += 4) {
                float4 p[4];
#pragma unroll
                for (int r = 0; r < 4; r++)
                    p[r] = *(float4*)&Ps[(ty*8+rr+r)*PS_LD + tc*4];
#pragma unroll
                for (int r = 0; r < 4; r++) {
                    o[rr+r][0] = fmaf(p[r].x, v0.x, o[rr+r][0]);
                    o[rr+r][1] = fmaf(p[r].x, v0.y, o[rr+r][1]);
                    o[rr+r][2] = fmaf(p[r].x, v0.z, o[rr+r][2]);
                    o[rr+r][3] = fmaf(p[r].x, v0.w, o[rr+r][3]);
                    o[rr+r][0] = fmaf(p[r].y, v1.x, o[rr+r][0]);
                    o[rr+r][1] = fmaf(p[r].y, v1.y, o[rr+r][1]);
                    o[rr+r][2] = fmaf(p[r].y, v1.z, o[rr+r][2]);
                    o[rr+r][3] = fmaf(p[r].y, v1.w, o[rr+r][3]);
                    o[rr+r][0] = fmaf(p[r].z, v2.x, o[rr+r][0]);
                    o[rr+r][1] = fmaf(p[r].z, v2.y, o[rr+r][1]);
                    o[rr+r][2] = fmaf(p[r].z, v2.z, o[rr+r][2]);
                    o[rr+r][3] = fmaf(p[r].z, v2.w, o[rr+r][3]);
                    o[rr+r][0] = fmaf(p[r].w, v3.x, o[rr+r][0]);
                    o[rr+r][1] = fmaf(p[r].w, v3.y, o[rr+r][1]);
                    o[rr+r][2] = fmaf(p[r].w, v3.z, o[rr+r][2]);
                    o[rr+r][3] = fmaf(p[r].w, v3.w, o[rr+r][3]);
                }
            }
        }
    }

    // Epilogue: normalize, write combined [b, s, h*64 + tx*4]
#pragma unroll
    for (int r = 0; r < 8; r++) {
        float inv = 1.0f / lrun[r];
        int s = q0 + ty*8 + r;
        float4 out;
        out.x = o[r][0] * inv;
        out.y = o[r][1] * inv;
        out.z = o[r][2] * inv;
        out.w = o[r][3] * inv;
        *(float4*)&g_comb[((long long)(b*Sc + s))*Dc + h*HDc + tx*4] = out;
    }
}

// ---------------------------------------------------------------------------
// Launch
// ---------------------------------------------------------------------------
extern "C" void kernel_launch(void* const* d_in, const int* in_sizes, int n_in,
                              void* d_out, int out_size)
{
    const float* inputs = (const float*)d_in[0];
    const float* Wq = (const float*)d_in[1];
    const float* bq = (const float*)d_in[2];
    const float* Wk = (const float*)d_in[3];
    const float* bk = (const float*)d_in[4];
    const float* Wv = (const float*)d_in[5];
    const float* bv = (const float*)d_in[6];
    const float* Wt = (const float*)d_in[7];
    const float* bt = (const float*)d_in[8];
    const float* Wo = (const float*)d_in[9];
    const float* bo = (const float*)d_in[10];
    float* out = (float*)d_out;

    float *p_qkv, *p_comb, *p_up, *p_wcat, *p_bcat, *p_woT;
    cudaGetSymbolAddress((void**)&p_qkv,  g_qkv);
    cudaGetSymbolAddress((void**)&p_comb, g_comb);
    cudaGetSymbolAddress((void**)&p_up,   g_up);
    cudaGetSymbolAddress((void**)&p_wcat, g_wcat);
    cudaGetSymbolAddress((void**)&p_bcat, g_bcat);
    cudaGetSymbolAddress((void**)&p_woT,  g_woT);
    (void)in_sizes; (void)n_in; (void)out_size;

    const int attn_smem = SM_TOT * (int)sizeof(float);   // 101376 B
    cudaFuncSetAttribute(attn_kernel, cudaFuncAttributeMaxDynamicSharedMemorySize, attn_smem);

    // 1. Pack weights
    {
        int total = Ic*3*Dc + Dc*Ic + 3*Dc;
        pack_kernel<<<(total + 255)/256, 256>>>(Wq, bq, Wk, bk, Wv, bv, Wo);
    }

    // 2. QKV GEMM: [8192,512] x [512,1536] -> g_qkv
    {
        dim3 grid(3*Dc/128, (Bc*Sc)/128, 1);   // 12 x 64
        sgemm128_kernel<<<grid, 256>>>(inputs, 0, p_wcat, 0, p_qkv, 0,
                                       Bc*Sc, 3*Dc, Ic, p_bcat, 1);
    }

    // 3. Transpose K to [b,h,d,s]
    transposeK_kernel<<<dim3(Sc/32, HDc/32, Bc*Hc), dim3(32, 8)>>>();

    // 4. Attention -> g_comb
    attn_kernel<<<dim3(Sc/128, Hc, Bc), 256, attn_smem>>>();

    // 5. Temporal GEMM per batch: Wt[720,2048] x comb_b[2048,512] -> up_b[720,512]
    {
        dim3 grid(Dc/128, (Pc + 127)/128, Bc);   // 4 x 6 x 4
        sgemm128_kernel<<<grid, 256>>>(Wt, 0,
                                       p_comb, (long long)Sc*Dc,
                                       p_up,   (long long)Pc*Dc,
                                       Pc, Dc, Sc, bt, 2);
    }

    // 6. Output GEMM: up[2880,512] x WoT[512,512] -> out
    {
        dim3 grid(Ic/128, (Bc*Pc + 127)/128, 1); // 4 x 23
        sgemm128_kernel<<<grid, 256>>>(p_up, 0, p_woT, 0, out, 0,
                                       Bc*Pc, Ic, Dc, bo, 1);
    }
}

// round 6
// speedup vs baseline: 1.4455x; 1.0526x over previous
#include <cuda_runtime.h>
#include <math.h>

// Problem constants
#define Bc 4
#define Sc 2048
#define Ic 512
#define Dc 512
#define Hc 8
#define HDc 64
#define Pc 720

typedef unsigned long long u64;

// Packed f32x2 helpers (sm_103a dual-fp32 pipe)
__device__ __forceinline__ u64 dup2(float x) {
    u64 r; asm("mov.b64 %0, {%1, %1};" : "=l"(r) : "f"(x)); return r;
}
__device__ __forceinline__ void ffma2(u64& d, u64 a, u64 b) {
    asm("fma.rn.f32x2 %0, %1, %2, %0;" : "+l"(d) : "l"(a), "l"(b));
}
__device__ __forceinline__ u64 mul2(u64 a, u64 b) {
    u64 r; asm("mul.rn.f32x2 %0, %1, %2;" : "=l"(r) : "l"(a), "l"(b)); return r;
}
__device__ __forceinline__ void unpack2(float& lo, float& hi, u64 v) {
    asm("mov.b64 {%0, %1}, %2;" : "=f"(lo), "=f"(hi) : "l"(v));
}

// Scratch (device globals — no allocation allowed)
__device__ float g_qkv[Bc*Sc*3*Dc];      // [b,s, q|k|v]
__device__ float g_kT [Bc*Hc*HDc*Sc];    // [b,h,d,s]
__device__ float g_comb[Bc*Sc*Dc];       // [b,s,d]
__device__ float g_up [Bc*Pc*Dc];        // [b,p,d]
__device__ float g_part[16*Pc*Dc];       // split-K partials (reused for output GEMM)
__device__ float g_wcat[Ic*3*Dc];
__device__ float g_bcat[3*Dc];
__device__ float g_woT[Dc*Ic];

// ---------------------------------------------------------------------------
// Pack weights
// ---------------------------------------------------------------------------
__global__ void pack_kernel(const float* __restrict__ Wq, const float* __restrict__ bq,
                            const float* __restrict__ Wk, const float* __restrict__ bk,
                            const float* __restrict__ Wv, const float* __restrict__ bv,
                            const float* __restrict__ Wo)
{
    const int NW  = Ic*3*Dc;
    const int NWO = Dc*Ic;
    int gid = blockIdx.x*blockDim.x + threadIdx.x;
    if (gid < NW) {
        int i = gid / (3*Dc);
        int n = gid % (3*Dc);
        int sec = n / Dc;
        int nn  = n % Dc;
        const float* W = (sec==0) ? Wq : (sec==1) ? Wk : Wv;
        int h = nn / HDc, d = nn % HDc;
        g_wcat[gid] = W[(h*Ic + i)*HDc + d];
    } else if (gid < NW + NWO) {
        int t = gid - NW;
        int d = t / Ic, o = t % Ic;
        g_woT[t] = Wo[o*Dc + d];
    } else if (gid < NW + NWO + 3*Dc) {
        int n = gid - NW - NWO;
        int sec = n / Dc, nn = n % Dc;
        const float* bv_ = (sec==0) ? bq : (sec==1) ? bk : bv;
        g_bcat[n] = bv_[nn];
    }
}

// ---------------------------------------------------------------------------
// SGEMM 128x128, BK=16, 8x8/thread via f32x2, generalized lda/ldb/ldc + split-K.
// blockIdx.z = b*nsplit + kc; A+=b*strideA + kc*K (col); B+=b*strideB + kc*K*ldb;
// C += blockIdx.z*strideC. biasMode: 0 none, 1 per-col, 2 per-row.
// ---------------------------------------------------------------------------
__global__ __launch_bounds__(256)
void sgemm128_kernel(const float* __restrict__ A, int lda, long long strideA,
                     const float* __restrict__ Bm, int ldb, long long strideB,
                     float* __restrict__ C, int ldc, long long strideC,
                     int M, int N, int K,
                     const float* __restrict__ bias, int biasMode, int nsplit)
{
    int bz = blockIdx.z / nsplit;
    int kc = blockIdx.z % nsplit;
    A  += (long long)bz * strideA + (long long)kc * K;
    Bm += (long long)bz * strideB + (long long)kc * K * ldb;
    C  += (long long)blockIdx.z * strideC;

    __shared__ float As[16][132];   // [k][m]
    __shared__ float Bs[16][128];   // [k][n]

    int tid = threadIdx.x;
    int tx = tid & 15;
    int ty = tid >> 4;
    int m0 = blockIdx.y * 128;
    int n0 = blockIdx.x * 128;

    u64 acc2[8][4];
#pragma unroll
    for (int i = 0; i < 8; i++)
#pragma unroll
        for (int j = 0; j < 4; j++) acc2[i][j] = 0ull;

    for (int k0 = 0; k0 < K; k0 += 16) {
#pragma unroll
        for (int l = 0; l < 2; l++) {
            int lin = tid + l*256;
            int row = lin >> 2;
            int kcol = (lin & 3) << 2;
            float4 v = make_float4(0.f,0.f,0.f,0.f);
            if (m0 + row < M)
                v = *(const float4*)&A[(long long)(m0+row)*lda + k0 + kcol];
            As[kcol+0][row] = v.x;
            As[kcol+1][row] = v.y;
            As[kcol+2][row] = v.z;
            As[kcol+3][row] = v.w;
        }
#pragma unroll
        for (int l = 0; l < 2; l++) {
            int lin = tid + l*256;
            int kr = lin >> 5;
            int nc = (lin & 31) << 2;
            *(float4*)&Bs[kr][nc] = *(const float4*)&Bm[(long long)(k0+kr)*ldb + n0 + nc];
        }
        __syncthreads();
#pragma unroll
        for (int k = 0; k < 16; k++) {
            float a[8];
            *(float4*)&a[0] = *(float4*)&As[k][ty*8];
            *(float4*)&a[4] = *(float4*)&As[k][ty*8+4];
            ulonglong2 b0 = *(ulonglong2*)&Bs[k][tx*8];
            ulonglong2 b1 = *(ulonglong2*)&Bs[k][tx*8+4];
#pragma unroll
            for (int i = 0; i < 8; i++) {
                u64 ad = dup2(a[i]);
                ffma2(acc2[i][0], ad, b0.x);
                ffma2(acc2[i][1], ad, b0.y);
                ffma2(acc2[i][2], ad, b1.x);
                ffma2(acc2[i][3], ad, b1.y);
            }
        }
        __syncthreads();
    }

#pragma unroll
    for (int i = 0; i < 8; i++) {
        int m = m0 + ty*8 + i;
        if (m >= M) continue;
        float brow = (biasMode == 2) ? bias[m] : 0.f;
        float v[8];
        unpack2(v[0], v[1], acc2[i][0]);
        unpack2(v[2], v[3], acc2[i][1]);
        unpack2(v[4], v[5], acc2[i][2]);
        unpack2(v[6], v[7], acc2[i][3]);
#pragma unroll
        for (int j = 0; j < 8; j++) {
            v[j] += brow;
            if (biasMode == 1) v[j] += bias[n0 + tx*8 + j];
        }
        *(float4*)&C[(long long)m*ldc + n0 + tx*8]     = *(float4*)&v[0];
        *(float4*)&C[(long long)m*ldc + n0 + tx*8 + 4] = *(float4*)&v[4];
    }
}

// ---------------------------------------------------------------------------
// Reduce split-K partials: dst[b][i] = bias + sum_g part[(b*G+g)*MN + i]
// ---------------------------------------------------------------------------
__global__ void reduce_kernel(float* __restrict__ dst, const float* __restrict__ part,
                              const float* __restrict__ bias, int biasMode,
                              int N, int MN, int G, int total4)
{
    int e = blockIdx.x*256 + threadIdx.x;
    if (e >= total4) return;
    int MN4 = MN >> 2;
    int b = e / MN4, i4 = e - b*MN4;
    int i = i4 << 2;
    float4 s;
    if (biasMode == 1) {
        s = *(const float4*)&bias[i % N];
    } else if (biasMode == 2) {
        float bv = bias[i / N];
        s = make_float4(bv, bv, bv, bv);
    } else {
        s = make_float4(0.f,0.f,0.f,0.f);
    }
#pragma unroll 4
    for (int g = 0; g < G; g++) {
        float4 p = *(const float4*)&part[((long long)(b*G+g))*MN + i];
        s.x += p.x; s.y += p.y; s.z += p.z; s.w += p.w;
    }
    *(float4*)&dst[(long long)b*MN + i] = s;
}

// ---------------------------------------------------------------------------
// Transpose K: g_qkv k-section [b,s,h,d] -> g_kT [b,h,d,s]
// ---------------------------------------------------------------------------
__global__ void transposeK_kernel()
{
    __shared__ float tile[32][33];
    int bh = blockIdx.z;
    int b = bh / Hc, h = bh % Hc;
    int s0 = blockIdx.x * 32;
    int d0 = blockIdx.y * 32;
    int tx = threadIdx.x, ty = threadIdx.y;

#pragma unroll
    for (int r = ty; r < 32; r += 8) {
        int s = s0 + r;
        tile[r][tx] = g_qkv[((long long)(b*Sc + s))*(3*Dc) + Dc + h*HDc + d0 + tx];
    }
    __syncthreads();
#pragma unroll
    for (int r = ty; r < 32; r += 8) {
        int d = d0 + r;
        g_kT[(((long long)bh)*HDc + d)*Sc + s0 + tx] = tile[tx][r];
    }
}

// ---------------------------------------------------------------------------
// Flash attention fp32 with f32x2 FMA: 128 q-rows/block, 64-key tiles, HD=64.
// 256 threads: tx=tid&15 (4 key-cols / 4 out-feats), ty=tid>>4 (8 q-rows).
// ---------------------------------------------------------------------------
#define QS_LD 132
#define PS_LD 68
#define SM_Q  0
#define SM_K  (64*QS_LD)
#define SM_V  (SM_K + 64*64)
#define SM_P  (SM_V + 64*64)
#define SM_TOT (SM_P + 128*PS_LD)   // 25344 floats = 101376 bytes

__global__ __launch_bounds__(256)
void attn_kernel()
{
    extern __shared__ float sm[];
    float* Qs = sm + SM_Q;   // [feat][qrow] ld 132, pre-scaled 1/64
    float* Ks = sm + SM_K;   // [feat][key]  ld 64
    float* Vs = sm + SM_V;   // [key][feat]  ld 64
    float* Ps = sm + SM_P;   // [qrow][key]  ld 68

    int tid = threadIdx.x;
    int tx = tid & 15;
    int ty = tid >> 4;
    int q0 = blockIdx.x * 128;
    int h  = blockIdx.y;
    int b  = blockIdx.z;
    int bh = b*Hc + h;

    // Load + transpose + scale Q tile
#pragma unroll
    for (int l = 0; l < 8; l++) {
        int lin = tid + l*256;
        int row = lin >> 4;
        int c4  = (lin & 15) << 2;
        float4 v = *(const float4*)&g_qkv[((long long)(b*Sc + q0 + row))*(3*Dc) + h*HDc + c4];
        const float s = 1.0f / (float)HDc;
        Qs[(c4+0)*QS_LD + row] = v.x * s;
        Qs[(c4+1)*QS_LD + row] = v.y * s;
        Qs[(c4+2)*QS_LD + row] = v.z * s;
        Qs[(c4+3)*QS_LD + row] = v.w * s;
    }

    // o packed across feat pairs: o2[r][0]=(f0,f1), o2[r][1]=(f2,f3)
    u64 o2[8][2];
    float mrun[8], lrun[8];
#pragma unroll
    for (int r = 0; r < 8; r++) {
        mrun[r] = -1e30f; lrun[r] = 0.f;
        o2[r][0] = 0ull; o2[r][1] = 0ull;
    }

    for (int t0 = 0; t0 < Sc; t0 += 64) {
        __syncthreads();

        // K tile [feat][key]
#pragma unroll
        for (int l = 0; l < 4; l++) {
            int lin = tid + l*256;
            int d  = lin >> 4;
            int c4 = (lin & 15) << 2;
            *(float4*)&Ks[d*64 + c4] =
                *(const float4*)&g_kT[((long long)bh*HDc + d)*Sc + t0 + c4];
        }
        // V tile [key][feat]
#pragma unroll
        for (int l = 0; l < 4; l++) {
            int lin = tid + l*256;
            int t  = lin >> 4;
            int c4 = (lin & 15) << 2;
            *(float4*)&Vs[t*64 + c4] =
                *(const float4*)&g_qkv[((long long)(b*Sc + t0 + t))*(3*Dc) + 2*Dc + h*HDc + c4];
        }
        __syncthreads();

        // QK^T: accumulators packed across q-row pairs.
        u64 acc2q[4][4];
#pragma unroll
        for (int rp = 0; rp < 4; rp++)
#pragma unroll
            for (int c = 0; c < 4; c++) acc2q[rp][c] = 0ull;

#pragma unroll
        for (int k = 0; k < 64; k++) {
            ulonglong2 a01 = *(ulonglong2*)&Qs[k*QS_LD + ty*8];      // rows 0-3
            ulonglong2 a23 = *(ulonglong2*)&Qs[k*QS_LD + ty*8 + 4];  // rows 4-7
            float4 kv = *(float4*)&Ks[k*64 + tx*4];
            u64 k0 = dup2(kv.x), k1 = dup2(kv.y), k2 = dup2(kv.z), k3 = dup2(kv.w);
            ffma2(acc2q[0][0], a01.x, k0); ffma2(acc2q[0][1], a01.x, k1);
            ffma2(acc2q[0][2], a01.x, k2); ffma2(acc2q[0][3], a01.x, k3);
            ffma2(acc2q[1][0], a01.y, k0); ffma2(acc2q[1][1], a01.y, k1);
            ffma2(acc2q[1][2], a01.y, k2); ffma2(acc2q[1][3], a01.y, k3);
            ffma2(acc2q[2][0], a23.x, k0); ffma2(acc2q[2][1], a23.x, k1);
            ffma2(acc2q[2][2], a23.x, k2); ffma2(acc2q[2][3], a23.x, k3);
            ffma2(acc2q[3][0], a23.y, k0); ffma2(acc2q[3][1], a23.y, k1);
            ffma2(acc2q[3][2], a23.y, k2); ffma2(acc2q[3][3], a23.y, k3);
        }

        // Unpack scores
        float acc[8][4];
#pragma unroll
        for (int rp = 0; rp < 4; rp++)
#pragma unroll
            for (int c = 0; c < 4; c++)
                unpack2(acc[2*rp][c], acc[2*rp+1][c], acc2q[rp][c]);

        // Online softmax
#pragma unroll
        for (int r = 0; r < 8; r++) {
            float mm = fmaxf(fmaxf(acc[r][0], acc[r][1]), fmaxf(acc[r][2], acc[r][3]));
#pragma unroll
            for (int w = 1; w < 16; w <<= 1)
                mm = fmaxf(mm, __shfl_xor_sync(0xffffffffu, mm, w));
            float newm = fmaxf(mrun[r], mm);
            float corr = __expf(mrun[r] - newm);
            float sum = 0.f;
#pragma unroll
            for (int j = 0; j < 4; j++) {
                acc[r][j] = __expf(acc[r][j] - newm);
                sum += acc[r][j];
            }
#pragma unroll
            for (int w = 1; w < 16; w <<= 1)
                sum += __shfl_xor_sync(0xffffffffu, sum, w);
            lrun[r] = lrun[r]*corr + sum;
            mrun[r] = newm;
            u64 cd = dup2(corr);
            o2[r][0] = mul2(o2[r][0], cd);
            o2[r][1] = mul2(o2[r][1], cd);
        }

        // Write P [qrow][key]
#pragma unroll
        for (int r = 0; r < 8; r++)
            *(float4*)&Ps[(ty*8+r)*PS_LD + tx*4] = *(float4*)&acc[r][0];
        __syncthreads();

        // AV with f32x2: per 4-key chunk
#pragma unroll
        for (int tc = 0; tc < 16; tc++) {
            ulonglong2 v0 = *(ulonglong2*)&Vs[(tc*4+0)*64 + tx*4];
            ulonglong2 v1 = *(ulonglong2*)&Vs[(tc*4+1)*64 + tx*4];
            ulonglong2 v2 = *(ulonglong2*)&Vs[(tc*4+2)*64 + tx*4];
            ulonglong2 v3 = *(ulonglong2*)&Vs[(tc*4+3)*64 + tx*4];
#pragma unroll
            for (int r = 0; r < 8; r++) {
                float4 p = *(float4*)&Ps[(ty*8+r)*PS_LD + tc*4];
                u64 p0 = dup2(p.x), p1 = dup2(p.y), p2 = dup2(p.z), p3 = dup2(p.w);
                ffma2(o2[r][0], p0, v0.x); ffma2(o2[r][1], p0, v0.y);
                ffma2(o2[r][0], p1, v1.x); ffma2(o2[r][1], p1, v1.y);
                ffma2(o2[r][0], p2, v2.x); ffma2(o2[r][1], p2, v2.y);
                ffma2(o2[r][0], p3, v3.x); ffma2(o2[r][1], p3, v3.y);
            }
        }
    }

    // Epilogue
#pragma unroll
    for (int r = 0; r < 8; r++) {
        float inv = 1.0f / lrun[r];
        int s = q0 + ty*8 + r;
        float4 out;
        unpack2(out.x, out.y, o2[r][0]);
        unpack2(out.z, out.w, o2[r][1]);
        out.x *= inv; out.y *= inv; out.z *= inv; out.w *= inv;
        *(float4*)&g_comb[((long long)(b*Sc + s))*Dc + h*HDc + tx*4] = out;
    }
}

// ---------------------------------------------------------------------------
// Launch
// ---------------------------------------------------------------------------
extern "C" void kernel_launch(void* const* d_in, const int* in_sizes, int n_in,
                              void* d_out, int out_size)
{
    const float* inputs = (const float*)d_in[0];
    const float* Wq = (const float*)d_in[1];
    const float* bq = (const float*)d_in[2];
    const float* Wk = (const float*)d_in[3];
    const float* bk = (const float*)d_in[4];
    const float* Wv = (const float*)d_in[5];
    const float* bv = (const float*)d_in[6];
    const float* Wt = (const float*)d_in[7];
    const float* bt = (const float*)d_in[8];
    const float* Wo = (const float*)d_in[9];
    const float* bo = (const float*)d_in[10];
    float* out = (float*)d_out;

    float *p_qkv, *p_comb, *p_up, *p_part, *p_wcat, *p_bcat, *p_woT;
    cudaGetSymbolAddress((void**)&p_qkv,  g_qkv);
    cudaGetSymbolAddress((void**)&p_comb, g_comb);
    cudaGetSymbolAddress((void**)&p_up,   g_up);
    cudaGetSymbolAddress((void**)&p_part, g_part);
    cudaGetSymbolAddress((void**)&p_wcat, g_wcat);
    cudaGetSymbolAddress((void**)&p_bcat, g_bcat);
    cudaGetSymbolAddress((void**)&p_woT,  g_woT);
    (void)in_sizes; (void)n_in; (void)out_size;

    const int attn_smem = SM_TOT * (int)sizeof(float);
    cudaFuncSetAttribute(attn_kernel, cudaFuncAttributeMaxDynamicSharedMemorySize, attn_smem);

    // 1. Pack weights
    {
        int total = Ic*3*Dc + Dc*Ic + 3*Dc;
        pack_kernel<<<(total + 255)/256, 256>>>(Wq, bq, Wk, bk, Wv, bv, Wo);
    }

    // 2. QKV GEMM: inputs[8192,512] x wcat[512,1536] -> g_qkv (+bcat per-col)
    {
        dim3 grid(3*Dc/128, (Bc*Sc)/128, 1);
        sgemm128_kernel<<<grid, 256>>>(inputs, Ic, 0,
                                       p_wcat, 3*Dc, 0,
                                       p_qkv, 3*Dc, 0,
                                       Bc*Sc, 3*Dc, Ic, p_bcat, 1, 1);
    }

    // 3. Transpose K
    transposeK_kernel<<<dim3(Sc/32, HDc/32, Bc*Hc), dim3(32, 8)>>>();

    // 4. Attention -> g_comb
    attn_kernel<<<dim3(Sc/128, Hc, Bc), 256, attn_smem>>>();

    // 5. Temporal GEMM, split-K x4: Wt[720,2048] x comb_b[2048,512] -> partials
    {
        dim3 grid(Dc/128, (Pc + 127)/128, Bc*4);   // 4 x 6 x 16 = 384 CTAs
        sgemm128_kernel<<<grid, 256>>>(Wt, Sc, 0,
                                       p_comb, Dc, (long long)Sc*Dc,
                                       p_part, Dc, (long long)Pc*Dc,
                                       Pc, Dc, Sc/4, (const float*)0, 0, 4);
        int MN = Pc*Dc;
        int total4 = Bc*MN/4;
        reduce_kernel<<<(total4 + 255)/256, 256>>>(p_up, p_part, bt, 2, Dc, MN, 4, total4);
    }

    // 6. Output GEMM, split-K x2: up[2880,512] x woT[512,512] -> out (+bo)
    {
        dim3 grid(Ic/128, (Bc*Pc + 127)/128, 2);   // 4 x 23 x 2 = 184 CTAs
        sgemm128_kernel<<<grid, 256>>>(p_up, Dc, 0,
                                       p_woT, Ic, 0,
                                       p_part, Ic, (long long)(Bc*Pc)*Ic,
                                       Bc*Pc, Ic, Dc/2, (const float*)0, 0, 2);
        int MN = Bc*Pc*Ic;
        int total4 = MN/4;
        reduce_kernel<<<(total4 + 255)/256, 256>>>(out, p_part, bo, 1, Ic, MN, 2, total4);
    }
}

// round 7
// speedup vs baseline: 2.2007x; 1.5224x over previous
#include <cuda_runtime.h>
#include <math.h>

// Problem constants
#define Bc 4
#define Sc 2048
#define Ic 512
#define Dc 512
#define Hc 8
#define HDc 64
#define Pc 720

typedef unsigned long long u64;
typedef unsigned int u32;

// Packed f32x2 helpers (sm_103a dual-fp32 pipe)
__device__ __forceinline__ u64 dup2(float x) {
    u64 r; asm("mov.b64 %0, {%1, %1};" : "=l"(r) : "f"(x)); return r;
}
__device__ __forceinline__ void ffma2(u64& d, u64 a, u64 b) {
    asm("fma.rn.f32x2 %0, %1, %2, %0;" : "+l"(d) : "l"(a), "l"(b));
}
__device__ __forceinline__ void unpack2(float& lo, float& hi, u64 v) {
    asm("mov.b64 {%0, %1}, %2;" : "=f"(lo), "=f"(hi) : "l"(v));
}

// tf32 helpers
__device__ __forceinline__ u32 f2tf32(float x) {
    u32 r; asm("cvt.rna.tf32.f32 %0, %1;" : "=r"(r) : "f"(x)); return r;
}
__device__ __forceinline__ void mma_tf32(float d[4], const u32 a[4], u32 b0, u32 b1) {
    asm volatile(
        "mma.sync.aligned.m16n8k8.row.col.f32.tf32.tf32.f32 "
        "{%0,%1,%2,%3}, {%4,%5,%6,%7}, {%8,%9}, {%0,%1,%2,%3};\n"
        : "+f"(d[0]), "+f"(d[1]), "+f"(d[2]), "+f"(d[3])
        : "r"(a[0]), "r"(a[1]), "r"(a[2]), "r"(a[3]), "r"(b0), "r"(b1));
}

// Scratch (device globals — no allocation allowed)
__device__ float g_qkv[Bc*Sc*3*Dc];      // [b,s, q|k|v]
__device__ float g_kT [Bc*Hc*HDc*Sc];    // [b,h,d,s]
__device__ float g_comb[Bc*Sc*Dc];       // [b,s,d]
__device__ float g_up [Bc*Pc*Dc];        // [b,p,d]
__device__ float g_part[16*Pc*Dc];       // split-K partials
__device__ float g_wcat[Ic*3*Dc];
__device__ float g_bcat[3*Dc];
__device__ float g_woT[Dc*Ic];

// ---------------------------------------------------------------------------
// Pack weights
// ---------------------------------------------------------------------------
__global__ void pack_kernel(const float* __restrict__ Wq, const float* __restrict__ bq,
                            const float* __restrict__ Wk, const float* __restrict__ bk,
                            const float* __restrict__ Wv, const float* __restrict__ bv,
                            const float* __restrict__ Wo)
{
    const int NW  = Ic*3*Dc;
    const int NWO = Dc*Ic;
    int gid = blockIdx.x*blockDim.x + threadIdx.x;
    if (gid < NW) {
        int i = gid / (3*Dc);
        int n = gid % (3*Dc);
        int sec = n / Dc;
        int nn  = n % Dc;
        const float* W = (sec==0) ? Wq : (sec==1) ? Wk : Wv;
        int h = nn / HDc, d = nn % HDc;
        g_wcat[gid] = W[(h*Ic + i)*HDc + d];
    } else if (gid < NW + NWO) {
        int t = gid - NW;
        int d = t / Ic, o = t % Ic;
        g_woT[t] = Wo[o*Dc + d];
    } else if (gid < NW + NWO + 3*Dc) {
        int n = gid - NW - NWO;
        int sec = n / Dc, nn = n % Dc;
        const float* bv_ = (sec==0) ? bq : (sec==1) ? bk : bv;
        g_bcat[n] = bv_[nn];
    }
}

// ---------------------------------------------------------------------------
// SGEMM 128x128, BK=16, 8x8/thread via f32x2, split-K (unchanged from R6)
// ---------------------------------------------------------------------------
__global__ __launch_bounds__(256)
void sgemm128_kernel(const float* __restrict__ A, int lda, long long strideA,
                     const float* __restrict__ Bm, int ldb, long long strideB,
                     float* __restrict__ C, int ldc, long long strideC,
                     int M, int N, int K,
                     const float* __restrict__ bias, int biasMode, int nsplit)
{
    int bz = blockIdx.z / nsplit;
    int kc = blockIdx.z % nsplit;
    A  += (long long)bz * strideA + (long long)kc * K;
    Bm += (long long)bz * strideB + (long long)kc * K * ldb;
    C  += (long long)blockIdx.z * strideC;

    __shared__ float As[16][132];
    __shared__ float Bs[16][128];

    int tid = threadIdx.x;
    int tx = tid & 15;
    int ty = tid >> 4;
    int m0 = blockIdx.y * 128;
    int n0 = blockIdx.x * 128;

    u64 acc2[8][4];
#pragma unroll
    for (int i = 0; i < 8; i++)
#pragma unroll
        for (int j = 0; j < 4; j++) acc2[i][j] = 0ull;

    for (int k0 = 0; k0 < K; k0 += 16) {
#pragma unroll
        for (int l = 0; l < 2; l++) {
            int lin = tid + l*256;
            int row = lin >> 2;
            int kcol = (lin & 3) << 2;
            float4 v = make_float4(0.f,0.f,0.f,0.f);
            if (m0 + row < M)
                v = *(const float4*)&A[(long long)(m0+row)*lda + k0 + kcol];
            As[kcol+0][row] = v.x;
            As[kcol+1][row] = v.y;
            As[kcol+2][row] = v.z;
            As[kcol+3][row] = v.w;
        }
#pragma unroll
        for (int l = 0; l < 2; l++) {
            int lin = tid + l*256;
            int kr = lin >> 5;
            int nc = (lin & 31) << 2;
            *(float4*)&Bs[kr][nc] = *(const float4*)&Bm[(long long)(k0+kr)*ldb + n0 + nc];
        }
        __syncthreads();
#pragma unroll
        for (int k = 0; k < 16; k++) {
            float a[8];
            *(float4*)&a[0] = *(float4*)&As[k][ty*8];
            *(float4*)&a[4] = *(float4*)&As[k][ty*8+4];
            ulonglong2 b0 = *(ulonglong2*)&Bs[k][tx*8];
            ulonglong2 b1 = *(ulonglong2*)&Bs[k][tx*8+4];
#pragma unroll
            for (int i = 0; i < 8; i++) {
                u64 ad = dup2(a[i]);
                ffma2(acc2[i][0], ad, b0.x);
                ffma2(acc2[i][1], ad, b0.y);
                ffma2(acc2[i][2], ad, b1.x);
                ffma2(acc2[i][3], ad, b1.y);
            }
        }
        __syncthreads();
    }

#pragma unroll
    for (int i = 0; i < 8; i++) {
        int m = m0 + ty*8 + i;
        if (m >= M) continue;
        float brow = (biasMode == 2) ? bias[m] : 0.f;
        float v[8];
        unpack2(v[0], v[1], acc2[i][0]);
        unpack2(v[2], v[3], acc2[i][1]);
        unpack2(v[4], v[5], acc2[i][2]);
        unpack2(v[6], v[7], acc2[i][3]);
#pragma unroll
        for (int j = 0; j < 8; j++) {
            v[j] += brow;
            if (biasMode == 1) v[j] += bias[n0 + tx*8 + j];
        }
        *(float4*)&C[(long long)m*ldc + n0 + tx*8]     = *(float4*)&v[0];
        *(float4*)&C[(long long)m*ldc + n0 + tx*8 + 4] = *(float4*)&v[4];
    }
}

// ---------------------------------------------------------------------------
// Reduce split-K partials
// ---------------------------------------------------------------------------
__global__ void reduce_kernel(float* __restrict__ dst, const float* __restrict__ part,
                              const float* __restrict__ bias, int biasMode,
                              int N, int MN, int G, int total4)
{
    int e = blockIdx.x*256 + threadIdx.x;
    if (e >= total4) return;
    int MN4 = MN >> 2;
    int b = e / MN4, i4 = e - b*MN4;
    int i = i4 << 2;
    float4 s;
    if (biasMode == 1) {
        s = *(const float4*)&bias[i % N];
    } else if (biasMode == 2) {
        float bv = bias[i / N];
        s = make_float4(bv, bv, bv, bv);
    } else {
        s = make_float4(0.f,0.f,0.f,0.f);
    }
#pragma unroll 4
    for (int g = 0; g < G; g++) {
        float4 p = *(const float4*)&part[((long long)(b*G+g))*MN + i];
        s.x += p.x; s.y += p.y; s.z += p.z; s.w += p.w;
    }
    *(float4*)&dst[(long long)b*MN + i] = s;
}

// ---------------------------------------------------------------------------
// Transpose K: g_qkv k-section [b,s,h,d] -> g_kT [b,h,d,s]
// ---------------------------------------------------------------------------
__global__ void transposeK_kernel()
{
    __shared__ float tile[32][33];
    int bh = blockIdx.z;
    int b = bh / Hc, h = bh % Hc;
    int s0 = blockIdx.x * 32;
    int d0 = blockIdx.y * 32;
    int tx = threadIdx.x, ty = threadIdx.y;

#pragma unroll
    for (int r = ty; r < 32; r += 8) {
        int s = s0 + r;
        tile[r][tx] = g_qkv[((long long)(b*Sc + s))*(3*Dc) + Dc + h*HDc + d0 + tx];
    }
    __syncthreads();
#pragma unroll
    for (int r = ty; r < 32; r += 8) {
        int d = d0 + r;
        g_kT[(((long long)bh)*HDc + d)*Sc + s0 + tx] = tile[tx][r];
    }
}

// ---------------------------------------------------------------------------
// Flash attention, tf32 mma.sync (m16n8k8): 128 q-rows/CTA, 64-key tiles.
// 8 warps; warp w owns q-rows [16w, 16w+16). Softmax fp32 in C-fragments.
// smem (tf32 bits): Qs[128][68] | Ks[64][72] | Vs[64][72] | Ps[128][68]
// ---------------------------------------------------------------------------
#define AQ_LD 68
#define AK_LD 72
#define AVS_LD 72
#define AP_LD 68
#define ASM_Q 0
#define ASM_K (128*AQ_LD)
#define ASM_V (ASM_K + 64*AK_LD)
#define ASM_P (ASM_V + 64*AVS_LD)
#define ASM_TOT (ASM_P + 128*AP_LD)   // 26624 u32 = 106496 bytes

__global__ __launch_bounds__(256, 2)
void attn_kernel()
{
    extern __shared__ u32 smu[];
    u32* Qb = smu + ASM_Q;
    u32* Kb = smu + ASM_K;
    u32* Vb = smu + ASM_V;
    u32* Pb = smu + ASM_P;

    int tid  = threadIdx.x;
    int warp = tid >> 5;
    int lane = tid & 31;
    int g = lane >> 2;      // groupID (row within fragment)
    int t = lane & 3;       // threadID in group (col/k within fragment)
    int q0 = blockIdx.x * 128;
    int h  = blockIdx.y;
    int b  = blockIdx.z;
    int bh = b*Hc + h;
    int r0 = warp*16 + g;   // local q-row (fragment row g)
    int r1 = r0 + 8;        // fragment row g+8

    // Load Q tile (scale by 1/64, cvt to tf32), layout [row][feat]
    const float qsc = 1.0f / (float)HDc;
#pragma unroll
    for (int l = 0; l < 8; l++) {
        int lin = tid + l*256;
        int row = lin >> 4;
        int c4  = (lin & 15) << 2;
        float4 v = *(const float4*)&g_qkv[((long long)(b*Sc + q0 + row))*(3*Dc) + h*HDc + c4];
        uint4 u;
        u.x = f2tf32(v.x * qsc);
        u.y = f2tf32(v.y * qsc);
        u.z = f2tf32(v.z * qsc);
        u.w = f2tf32(v.w * qsc);
        *(uint4*)&Qb[row*AQ_LD + c4] = u;
    }

    // Output accumulators in C-fragment layout: 8 n-tiles x 4 regs
    float o[8][4];
#pragma unroll
    for (int n = 0; n < 8; n++)
#pragma unroll
        for (int j = 0; j < 4; j++) o[n][j] = 0.f;
    float mr0 = -1e30f, mr1 = -1e30f, lr0 = 0.f, lr1 = 0.f;

    for (int t0 = 0; t0 < Sc; t0 += 64) {
        __syncthreads();   // prior QK/AV reads of Kb/Vb done

        // K tile: [feat][key] from g_kT
#pragma unroll
        for (int l = 0; l < 4; l++) {
            int lin = tid + l*256;
            int d  = lin >> 4;
            int c4 = (lin & 15) << 2;
            float4 v = *(const float4*)&g_kT[((long long)bh*HDc + d)*Sc + t0 + c4];
            uint4 u;
            u.x = f2tf32(v.x); u.y = f2tf32(v.y);
            u.z = f2tf32(v.z); u.w = f2tf32(v.w);
            *(uint4*)&Kb[d*AK_LD + c4] = u;
        }
        // V tile: [key][feat]
#pragma unroll
        for (int l = 0; l < 4; l++) {
            int lin = tid + l*256;
            int tr = lin >> 4;
            int c4 = (lin & 15) << 2;
            float4 v = *(const float4*)&g_qkv[((long long)(b*Sc + t0 + tr))*(3*Dc) + 2*Dc + h*HDc + c4];
            uint4 u;
            u.x = f2tf32(v.x); u.y = f2tf32(v.y);
            u.z = f2tf32(v.z); u.w = f2tf32(v.w);
            *(uint4*)&Vb[tr*AVS_LD + c4] = u;
        }
        __syncthreads();

        // --- QK^T: S[16 x 64] per warp ---
        float sacc[8][4];
#pragma unroll
        for (int n = 0; n < 8; n++)
#pragma unroll
            for (int j = 0; j < 4; j++) sacc[n][j] = 0.f;

#pragma unroll
        for (int kc = 0; kc < 8; kc++) {
            int k0 = kc*8;
            u32 a[4];
            a[0] = Qb[r0*AQ_LD + k0 + t];
            a[1] = Qb[r1*AQ_LD + k0 + t];
            a[2] = Qb[r0*AQ_LD + k0 + t + 4];
            a[3] = Qb[r1*AQ_LD + k0 + t + 4];
#pragma unroll
            for (int n = 0; n < 8; n++) {
                u32 b0 = Kb[(k0 + t)*AK_LD + n*8 + g];
                u32 b1 = Kb[(k0 + t + 4)*AK_LD + n*8 + g];
                mma_tf32(sacc[n], a, b0, b1);
            }
        }

        // --- Online softmax (rows r0: regs 0,1; r1: regs 2,3) ---
        float m0 = -1e30f, m1 = -1e30f;
#pragma unroll
        for (int n = 0; n < 8; n++) {
            m0 = fmaxf(m0, fmaxf(sacc[n][0], sacc[n][1]));
            m1 = fmaxf(m1, fmaxf(sacc[n][2], sacc[n][3]));
        }
        m0 = fmaxf(m0, __shfl_xor_sync(0xffffffffu, m0, 1));
        m0 = fmaxf(m0, __shfl_xor_sync(0xffffffffu, m0, 2));
        m1 = fmaxf(m1, __shfl_xor_sync(0xffffffffu, m1, 1));
        m1 = fmaxf(m1, __shfl_xor_sync(0xffffffffu, m1, 2));

        float nm0 = fmaxf(mr0, m0), nm1 = fmaxf(mr1, m1);
        float c0 = __expf(mr0 - nm0), c1 = __expf(mr1 - nm1);
        mr0 = nm0; mr1 = nm1;

        float s0 = 0.f, s1 = 0.f;
#pragma unroll
        for (int n = 0; n < 8; n++) {
            sacc[n][0] = __expf(sacc[n][0] - nm0);
            sacc[n][1] = __expf(sacc[n][1] - nm0);
            sacc[n][2] = __expf(sacc[n][2] - nm1);
            sacc[n][3] = __expf(sacc[n][3] - nm1);
            s0 += sacc[n][0] + sacc[n][1];
            s1 += sacc[n][2] + sacc[n][3];
        }
        s0 += __shfl_xor_sync(0xffffffffu, s0, 1);
        s0 += __shfl_xor_sync(0xffffffffu, s0, 2);
        s1 += __shfl_xor_sync(0xffffffffu, s1, 1);
        s1 += __shfl_xor_sync(0xffffffffu, s1, 2);
        lr0 = lr0*c0 + s0;
        lr1 = lr1*c1 + s1;

#pragma unroll
        for (int n = 0; n < 8; n++) {
            o[n][0] *= c0; o[n][1] *= c0;
            o[n][2] *= c1; o[n][3] *= c1;
        }

        // Store P (tf32) [row][key]
#pragma unroll
        for (int n = 0; n < 8; n++) {
            uint2 p0, p1;
            p0.x = f2tf32(sacc[n][0]); p0.y = f2tf32(sacc[n][1]);
            p1.x = f2tf32(sacc[n][2]); p1.y = f2tf32(sacc[n][3]);
            *(uint2*)&Pb[r0*AP_LD + n*8 + 2*t] = p0;
            *(uint2*)&Pb[r1*AP_LD + n*8 + 2*t] = p1;
        }
        __syncwarp();   // P is warp-private: warp-level sync suffices

        // --- AV: O[16 x 64] += P[16 x 64] * V[64 x 64] ---
#pragma unroll
        for (int kc = 0; kc < 8; kc++) {
            int k0 = kc*8;
            u32 a[4];
            a[0] = Pb[r0*AP_LD + k0 + t];
            a[1] = Pb[r1*AP_LD + k0 + t];
            a[2] = Pb[r0*AP_LD + k0 + t + 4];
            a[3] = Pb[r1*AP_LD + k0 + t + 4];
#pragma unroll
            for (int n = 0; n < 8; n++) {
                u32 b0 = Vb[(k0 + t)*AVS_LD + n*8 + g];
                u32 b1 = Vb[(k0 + t + 4)*AVS_LD + n*8 + g];
                mma_tf32(o[n], a, b0, b1);
            }
        }
    }

    // Epilogue: normalize, write combined [b, s, h*64 + col]
    float inv0 = 1.0f / lr0;
    float inv1 = 1.0f / lr1;
    int srow0 = q0 + r0;
    int srow1 = q0 + r1;
#pragma unroll
    for (int n = 0; n < 8; n++) {
        float2 w0, w1;
        w0.x = o[n][0]*inv0; w0.y = o[n][1]*inv0;
        w1.x = o[n][2]*inv1; w1.y = o[n][3]*inv1;
        *(float2*)&g_comb[((long long)(b*Sc + srow0))*Dc + h*HDc + n*8 + 2*t] = w0;
        *(float2*)&g_comb[((long long)(b*Sc + srow1))*Dc + h*HDc + n*8 + 2*t] = w1;
    }
}

// ---------------------------------------------------------------------------
// Launch
// ---------------------------------------------------------------------------
extern "C" void kernel_launch(void* const* d_in, const int* in_sizes, int n_in,
                              void* d_out, int out_size)
{
    const float* inputs = (const float*)d_in[0];
    const float* Wq = (const float*)d_in[1];
    const float* bq = (const float*)d_in[2];
    const float* Wk = (const float*)d_in[3];
    const float* bk = (const float*)d_in[4];
    const float* Wv = (const float*)d_in[5];
    const float* bv = (const float*)d_in[6];
    const float* Wt = (const float*)d_in[7];
    const float* bt = (const float*)d_in[8];
    const float* Wo = (const float*)d_in[9];
    const float* bo = (const float*)d_in[10];
    float* out = (float*)d_out;

    float *p_qkv, *p_comb, *p_up, *p_part, *p_wcat, *p_bcat, *p_woT;
    cudaGetSymbolAddress((void**)&p_qkv,  g_qkv);
    cudaGetSymbolAddress((void**)&p_comb, g_comb);
    cudaGetSymbolAddress((void**)&p_up,   g_up);
    cudaGetSymbolAddress((void**)&p_part, g_part);
    cudaGetSymbolAddress((void**)&p_wcat, g_wcat);
    cudaGetSymbolAddress((void**)&p_bcat, g_bcat);
    cudaGetSymbolAddress((void**)&p_woT,  g_woT);
    (void)in_sizes; (void)n_in; (void)out_size;

    const int attn_smem = ASM_TOT * (int)sizeof(u32);   // 106496 B
    cudaFuncSetAttribute(attn_kernel, cudaFuncAttributeMaxDynamicSharedMemorySize, attn_smem);

    // 1. Pack weights
    {
        int total = Ic*3*Dc + Dc*Ic + 3*Dc;
        pack_kernel<<<(total + 255)/256, 256>>>(Wq, bq, Wk, bk, Wv, bv, Wo);
    }

    // 2. QKV GEMM: inputs[8192,512] x wcat[512,1536] -> g_qkv (+bcat per-col)
    {
        dim3 grid(3*Dc/128, (Bc*Sc)/128, 1);
        sgemm128_kernel<<<grid, 256>>>(inputs, Ic, 0,
                                       p_wcat, 3*Dc, 0,
                                       p_qkv, 3*Dc, 0,
                                       Bc*Sc, 3*Dc, Ic, p_bcat, 1, 1);
    }

    // 3. Transpose K
    transposeK_kernel<<<dim3(Sc/32, HDc/32, Bc*Hc), dim3(32, 8)>>>();

    // 4. Attention (tf32 mma) -> g_comb
    attn_kernel<<<dim3(Sc/128, Hc, Bc), 256, attn_smem>>>();

    // 5. Temporal GEMM, split-K x4
    {
        dim3 grid(Dc/128, (Pc + 127)/128, Bc*4);
        sgemm128_kernel<<<grid, 256>>>(Wt, Sc, 0,
                                       p_comb, Dc, (long long)Sc*Dc,
                                       p_part, Dc, (long long)Pc*Dc,
                                       Pc, Dc, Sc/4, (const float*)0, 0, 4);
        int MN = Pc*Dc;
        int total4 = Bc*MN/4;
        reduce_kernel<<<(total4 + 255)/256, 256>>>(p_up, p_part, bt, 2, Dc, MN, 4, total4);
    }

    // 6. Output GEMM, split-K x2
    {
        dim3 grid(Ic/128, (Bc*Pc + 127)/128, 2);
        sgemm128_kernel<<<grid, 256>>>(p_up, Dc, 0,
                                       p_woT, Ic, 0,
                                       p_part, Ic, (long long)(Bc*Pc)*Ic,
                                       Bc*Pc, Ic, Dc/2, (const float*)0, 0, 2);
        int MN = Bc*Pc*Ic;
        int total4 = MN/4;
        reduce_kernel<<<(total4 + 255)/256, 256>>>(out, p_part, bo, 1, Ic, MN, 2, total4);
    }
}

// round 8
// speedup vs baseline: 3.0301x; 1.3769x over previous
#include <cuda_runtime.h>
#include <math.h>

// Problem constants
#define Bc 4
#define Sc 2048
#define Ic 512
#define Dc 512
#define Hc 8
#define HDc 64
#define Pc 720

typedef unsigned long long u64;
typedef unsigned int u32;

// Packed f32x2 helpers (sm_103a dual-fp32 pipe)
__device__ __forceinline__ u64 dup2(float x) {
    u64 r; asm("mov.b64 %0, {%1, %1};" : "=l"(r) : "f"(x)); return r;
}
__device__ __forceinline__ void ffma2(u64& d, u64 a, u64 b) {
    asm("fma.rn.f32x2 %0, %1, %2, %0;" : "+l"(d) : "l"(a), "l"(b));
}
__device__ __forceinline__ void unpack2(float& lo, float& hi, u64 v) {
    asm("mov.b64 {%0, %1}, %2;" : "=f"(lo), "=f"(hi) : "l"(v));
}

// tf32 helpers
__device__ __forceinline__ u32 f2tf32(float x) {
    u32 r; asm("cvt.rna.tf32.f32 %0, %1;" : "=r"(r) : "f"(x)); return r;
}
__device__ __forceinline__ void mma_tf32(float d[4], const u32 a[4], u32 b0, u32 b1) {
    asm volatile(
        "mma.sync.aligned.m16n8k8.row.col.f32.tf32.tf32.f32 "
        "{%0,%1,%2,%3}, {%4,%5,%6,%7}, {%8,%9}, {%0,%1,%2,%3};\n"
        : "+f"(d[0]), "+f"(d[1]), "+f"(d[2]), "+f"(d[3])
        : "r"(a[0]), "r"(a[1]), "r"(a[2]), "r"(a[3]), "r"(b0), "r"(b1));
}

// Scratch (device globals — no allocation allowed)
__device__ float g_qkv[Bc*Sc*3*Dc];      // [b,s, q|k|v]
__device__ float g_comb[Bc*Sc*Dc];       // [b,s,d]
__device__ float g_up [Bc*Pc*Dc];        // [b,p,d]
__device__ float g_part[16*Pc*Dc];       // split-K partials
__device__ float g_wcat[Ic*3*Dc];
__device__ float g_bcat[3*Dc];
__device__ float g_woT[Dc*Ic];

// ---------------------------------------------------------------------------
// Pack weights
// ---------------------------------------------------------------------------
__global__ void pack_kernel(const float* __restrict__ Wq, const float* __restrict__ bq,
                            const float* __restrict__ Wk, const float* __restrict__ bk,
                            const float* __restrict__ Wv, const float* __restrict__ bv,
                            const float* __restrict__ Wo)
{
    const int NW  = Ic*3*Dc;
    const int NWO = Dc*Ic;
    int gid = blockIdx.x*blockDim.x + threadIdx.x;
    if (gid < NW) {
        int i = gid / (3*Dc);
        int n = gid % (3*Dc);
        int sec = n / Dc;
        int nn  = n % Dc;
        const float* W = (sec==0) ? Wq : (sec==1) ? Wk : Wv;
        int h = nn / HDc, d = nn % HDc;
        g_wcat[gid] = W[(h*Ic + i)*HDc + d];
    } else if (gid < NW + NWO) {
        int t = gid - NW;
        int d = t / Ic, o = t % Ic;
        g_woT[t] = Wo[o*Dc + d];
    } else if (gid < NW + NWO + 3*Dc) {
        int n = gid - NW - NWO;
        int sec = n / Dc, nn = n % Dc;
        const float* bv_ = (sec==0) ? bq : (sec==1) ? bk : bv;
        g_bcat[n] = bv_[nn];
    }
}

// ---------------------------------------------------------------------------
// tf32 tensor GEMM: C[M,N] = A[M,K] x B[K,N], 128x128 tile, BK=16.
// 8 warps as 2x4; each warp: 64x32 (4 m-tiles x 4 n-tiles of m16n8k8).
// Split-K via blockIdx.z = bz*nsplit + kc. biasMode: 0 none, 1 per-col, 2 per-row.
// ---------------------------------------------------------------------------
#define TA_LD 20
#define TB_LD 136
__global__ __launch_bounds__(256)
void tgemm_kernel(const float* __restrict__ A, int lda, long long strideA,
                  const float* __restrict__ Bm, int ldb, long long strideB,
                  float* __restrict__ C, int ldc, long long strideC,
                  int M, int N, int K,
                  const float* __restrict__ bias, int biasMode, int nsplit)
{
    int bz = blockIdx.z / nsplit;
    int kcs = blockIdx.z % nsplit;
    A  += (long long)bz * strideA + (long long)kcs * K;
    Bm += (long long)bz * strideB + (long long)kcs * K * ldb;
    C  += (long long)blockIdx.z * strideC;

    __shared__ u32 As[128*TA_LD];   // [m][k], ld 20
    __shared__ u32 Bs[16*TB_LD];    // [k][n], ld 136

    int tid  = threadIdx.x;
    int warp = tid >> 5;
    int lane = tid & 31;
    int g = lane >> 2;
    int t = lane & 3;
    int wm = warp >> 2;     // 0..1
    int wn = warp & 3;      // 0..3
    int m0 = blockIdx.y * 128;
    int n0 = blockIdx.x * 128;

    float acc[4][4][4];
#pragma unroll
    for (int mt = 0; mt < 4; mt++)
#pragma unroll
        for (int nt = 0; nt < 4; nt++)
#pragma unroll
            for (int j = 0; j < 4; j++) acc[mt][nt][j] = 0.f;

    for (int k0 = 0; k0 < K; k0 += 16) {
        // A tile 128x16
#pragma unroll
        for (int l = 0; l < 2; l++) {
            int lin = tid + l*256;
            int row = lin >> 2;
            int kc4 = (lin & 3) << 2;
            float4 v = make_float4(0.f,0.f,0.f,0.f);
            if (m0 + row < M)
                v = *(const float4*)&A[(long long)(m0+row)*lda + k0 + kc4];
            uint4 u;
            u.x = f2tf32(v.x); u.y = f2tf32(v.y);
            u.z = f2tf32(v.z); u.w = f2tf32(v.w);
            *(uint4*)&As[row*TA_LD + kc4] = u;
        }
        // B tile 16x128
#pragma unroll
        for (int l = 0; l < 2; l++) {
            int lin = tid + l*256;
            int kr = lin >> 5;
            int nc = (lin & 31) << 2;
            float4 v = *(const float4*)&Bm[(long long)(k0+kr)*ldb + n0 + nc];
            uint4 u;
            u.x = f2tf32(v.x); u.y = f2tf32(v.y);
            u.z = f2tf32(v.z); u.w = f2tf32(v.w);
            *(uint4*)&Bs[kr*TB_LD + nc] = u;
        }
        __syncthreads();

#pragma unroll
        for (int kc = 0; kc < 2; kc++) {
            int kk = kc*8;
            u32 a[4][4];
#pragma unroll
            for (int mt = 0; mt < 4; mt++) {
                int mrow = wm*64 + mt*16;
                a[mt][0] = As[(mrow + g    )*TA_LD + kk + t];
                a[mt][1] = As[(mrow + g + 8)*TA_LD + kk + t];
                a[mt][2] = As[(mrow + g    )*TA_LD + kk + t + 4];
                a[mt][3] = As[(mrow + g + 8)*TA_LD + kk + t + 4];
            }
#pragma unroll
            for (int nt = 0; nt < 4; nt++) {
                int ncol = wn*32 + nt*8;
                u32 b0 = Bs[(kk + t    )*TB_LD + ncol + g];
                u32 b1 = Bs[(kk + t + 4)*TB_LD + ncol + g];
#pragma unroll
                for (int mt = 0; mt < 4; mt++)
                    mma_tf32(acc[mt][nt], a[mt], b0, b1);
            }
        }
        __syncthreads();
    }

    // Epilogue
#pragma unroll
    for (int mt = 0; mt < 4; mt++) {
#pragma unroll
        for (int hrow = 0; hrow < 2; hrow++) {
            int m = m0 + wm*64 + mt*16 + g + hrow*8;
            if (m >= M) continue;
            float brow = (biasMode == 2) ? bias[m] : 0.f;
#pragma unroll
            for (int nt = 0; nt < 4; nt++) {
                int c = n0 + wn*32 + nt*8 + 2*t;
                float2 w;
                w.x = acc[mt][nt][hrow*2 + 0] + brow;
                w.y = acc[mt][nt][hrow*2 + 1] + brow;
                if (biasMode == 1) { w.x += bias[c]; w.y += bias[c+1]; }
                *(float2*)&C[(long long)m*ldc + c] = w;
            }
        }
    }
}

// ---------------------------------------------------------------------------
// SGEMM f32x2 (kept for output GEMM: fp32 accuracy anchor)
// ---------------------------------------------------------------------------
__global__ __launch_bounds__(256)
void sgemm128_kernel(const float* __restrict__ A, int lda, long long strideA,
                     const float* __restrict__ Bm, int ldb, long long strideB,
                     float* __restrict__ C, int ldc, long long strideC,
                     int M, int N, int K,
                     const float* __restrict__ bias, int biasMode, int nsplit)
{
    int bz = blockIdx.z / nsplit;
    int kc = blockIdx.z % nsplit;
    A  += (long long)bz * strideA + (long long)kc * K;
    Bm += (long long)bz * strideB + (long long)kc * K * ldb;
    C  += (long long)blockIdx.z * strideC;

    __shared__ float As[16][132];
    __shared__ float Bs[16][128];

    int tid = threadIdx.x;
    int tx = tid & 15;
    int ty = tid >> 4;
    int m0 = blockIdx.y * 128;
    int n0 = blockIdx.x * 128;

    u64 acc2[8][4];
#pragma unroll
    for (int i = 0; i < 8; i++)
#pragma unroll
        for (int j = 0; j < 4; j++) acc2[i][j] = 0ull;

    for (int k0 = 0; k0 < K; k0 += 16) {
#pragma unroll
        for (int l = 0; l < 2; l++) {
            int lin = tid + l*256;
            int row = lin >> 2;
            int kcol = (lin & 3) << 2;
            float4 v = make_float4(0.f,0.f,0.f,0.f);
            if (m0 + row < M)
                v = *(const float4*)&A[(long long)(m0+row)*lda + k0 + kcol];
            As[kcol+0][row] = v.x;
            As[kcol+1][row] = v.y;
            As[kcol+2][row] = v.z;
            As[kcol+3][row] = v.w;
        }
#pragma unroll
        for (int l = 0; l < 2; l++) {
            int lin = tid + l*256;
            int kr = lin >> 5;
            int nc = (lin & 31) << 2;
            *(float4*)&Bs[kr][nc] = *(const float4*)&Bm[(long long)(k0+kr)*ldb + n0 + nc];
        }
        __syncthreads();
#pragma unroll
        for (int k = 0; k < 16; k++) {
            float a[8];
            *(float4*)&a[0] = *(float4*)&As[k][ty*8];
            *(float4*)&a[4] = *(float4*)&As[k][ty*8+4];
            ulonglong2 b0 = *(ulonglong2*)&Bs[k][tx*8];
            ulonglong2 b1 = *(ulonglong2*)&Bs[k][tx*8+4];
#pragma unroll
            for (int i = 0; i < 8; i++) {
                u64 ad = dup2(a[i]);
                ffma2(acc2[i][0], ad, b0.x);
                ffma2(acc2[i][1], ad, b0.y);
                ffma2(acc2[i][2], ad, b1.x);
                ffma2(acc2[i][3], ad, b1.y);
            }
        }
        __syncthreads();
    }

#pragma unroll
    for (int i = 0; i < 8; i++) {
        int m = m0 + ty*8 + i;
        if (m >= M) continue;
        float brow = (biasMode == 2) ? bias[m] : 0.f;
        float v[8];
        unpack2(v[0], v[1], acc2[i][0]);
        unpack2(v[2], v[3], acc2[i][1]);
        unpack2(v[4], v[5], acc2[i][2]);
        unpack2(v[6], v[7], acc2[i][3]);
#pragma unroll
        for (int j = 0; j < 8; j++) {
            v[j] += brow;
            if (biasMode == 1) v[j] += bias[n0 + tx*8 + j];
        }
        *(float4*)&C[(long long)m*ldc + n0 + tx*8]     = *(float4*)&v[0];
        *(float4*)&C[(long long)m*ldc + n0 + tx*8 + 4] = *(float4*)&v[4];
    }
}

// ---------------------------------------------------------------------------
// Reduce split-K partials
// ---------------------------------------------------------------------------
__global__ void reduce_kernel(float* __restrict__ dst, const float* __restrict__ part,
                              const float* __restrict__ bias, int biasMode,
                              int N, int MN, int G, int total4)
{
    int e = blockIdx.x*256 + threadIdx.x;
    if (e >= total4) return;
    int MN4 = MN >> 2;
    int b = e / MN4, i4 = e - b*MN4;
    int i = i4 << 2;
    float4 s;
    if (biasMode == 1) {
        s = *(const float4*)&bias[i % N];
    } else if (biasMode == 2) {
        float bv = bias[i / N];
        s = make_float4(bv, bv, bv, bv);
    } else {
        s = make_float4(0.f,0.f,0.f,0.f);
    }
#pragma unroll 4
    for (int g = 0; g < G; g++) {
        float4 p = *(const float4*)&part[((long long)(b*G+g))*MN + i];
        s.x += p.x; s.y += p.y; s.z += p.z; s.w += p.w;
    }
    *(float4*)&dst[(long long)b*MN + i] = s;
}

// ---------------------------------------------------------------------------
// Flash attention, tf32 mma.sync: 128 q-rows/CTA, 64-key tiles.
// K is read directly from g_qkv in [key][feat] layout (no pre-transpose).
// smem: Qb[128][68] | Kb[64][76] | Vb[64][72] | Pb[128][68]
// ---------------------------------------------------------------------------
#define AQ_LD 68
#define AK_LD 76
#define AVS_LD 72
#define AP_LD 68
#define ASM_Q 0
#define ASM_K (128*AQ_LD)
#define ASM_V (ASM_K + 64*AK_LD)
#define ASM_P (ASM_V + 64*AVS_LD)
#define ASM_TOT (ASM_P + 128*AP_LD)   // 26880 u32 = 107520 bytes

__global__ __launch_bounds__(256, 2)
void attn_kernel()
{
    extern __shared__ u32 smu[];
    u32* Qb = smu + ASM_Q;
    u32* Kb = smu + ASM_K;   // [key][feat] ld 76
    u32* Vb = smu + ASM_V;   // [key][feat] ld 72
    u32* Pb = smu + ASM_P;   // [row][key]  ld 68

    int tid  = threadIdx.x;
    int warp = tid >> 5;
    int lane = tid & 31;
    int g = lane >> 2;
    int t = lane & 3;
    int q0 = blockIdx.x * 128;
    int h  = blockIdx.y;
    int b  = blockIdx.z;
    int r0 = warp*16 + g;
    int r1 = r0 + 8;

    // Load Q tile (scale by 1/64, cvt tf32), [row][feat]
    const float qsc = 1.0f / (float)HDc;
#pragma unroll
    for (int l = 0; l < 8; l++) {
        int lin = tid + l*256;
        int row = lin >> 4;
        int c4  = (lin & 15) << 2;
        float4 v = *(const float4*)&g_qkv[((long long)(b*Sc + q0 + row))*(3*Dc) + h*HDc + c4];
        uint4 u;
        u.x = f2tf32(v.x * qsc);
        u.y = f2tf32(v.y * qsc);
        u.z = f2tf32(v.z * qsc);
        u.w = f2tf32(v.w * qsc);
        *(uint4*)&Qb[row*AQ_LD + c4] = u;
    }

    float o[8][4];
#pragma unroll
    for (int n = 0; n < 8; n++)
#pragma unroll
        for (int j = 0; j < 4; j++) o[n][j] = 0.f;
    float mr0 = -1e30f, mr1 = -1e30f, lr0 = 0.f, lr1 = 0.f;

    for (int t0 = 0; t0 < Sc; t0 += 64) {
        __syncthreads();

        // K tile [key][feat] directly from g_qkv
#pragma unroll
        for (int l = 0; l < 4; l++) {
            int lin = tid + l*256;
            int tr = lin >> 4;
            int c4 = (lin & 15) << 2;
            float4 v = *(const float4*)&g_qkv[((long long)(b*Sc + t0 + tr))*(3*Dc) + Dc + h*HDc + c4];
            uint4 u;
            u.x = f2tf32(v.x); u.y = f2tf32(v.y);
            u.z = f2tf32(v.z); u.w = f2tf32(v.w);
            *(uint4*)&Kb[tr*AK_LD + c4] = u;
        }
        // V tile [key][feat]
#pragma unroll
        for (int l = 0; l < 4; l++) {
            int lin = tid + l*256;
            int tr = lin >> 4;
            int c4 = (lin & 15) << 2;
            float4 v = *(const float4*)&g_qkv[((long long)(b*Sc + t0 + tr))*(3*Dc) + 2*Dc + h*HDc + c4];
            uint4 u;
            u.x = f2tf32(v.x); u.y = f2tf32(v.y);
            u.z = f2tf32(v.z); u.w = f2tf32(v.w);
            *(uint4*)&Vb[tr*AVS_LD + c4] = u;
        }
        __syncthreads();

        // --- QK^T: S[16 x 64] per warp. b-operand from [key][feat]:
        // b0 = K[n=key][k=feat]  -> Kb[(key)*AK_LD + feat]
        float sacc[8][4];
#pragma unroll
        for (int n = 0; n < 8; n++)
#pragma unroll
            for (int j = 0; j < 4; j++) sacc[n][j] = 0.f;

#pragma unroll
        for (int kc = 0; kc < 8; kc++) {
            int k0 = kc*8;
            u32 a[4];
            a[0] = Qb[r0*AQ_LD + k0 + t];
            a[1] = Qb[r1*AQ_LD + k0 + t];
            a[2] = Qb[r0*AQ_LD + k0 + t + 4];
            a[3] = Qb[r1*AQ_LD + k0 + t + 4];
#pragma unroll
            for (int n = 0; n < 8; n++) {
                u32 b0 = Kb[(n*8 + g)*AK_LD + k0 + t];
                u32 b1 = Kb[(n*8 + g)*AK_LD + k0 + t + 4];
                mma_tf32(sacc[n], a, b0, b1);
            }
        }

        // --- Online softmax ---
        float m0 = -1e30f, m1 = -1e30f;
#pragma unroll
        for (int n = 0; n < 8; n++) {
            m0 = fmaxf(m0, fmaxf(sacc[n][0], sacc[n][1]));
            m1 = fmaxf(m1, fmaxf(sacc[n][2], sacc[n][3]));
        }
        m0 = fmaxf(m0, __shfl_xor_sync(0xffffffffu, m0, 1));
        m0 = fmaxf(m0, __shfl_xor_sync(0xffffffffu, m0, 2));
        m1 = fmaxf(m1, __shfl_xor_sync(0xffffffffu, m1, 1));
        m1 = fmaxf(m1, __shfl_xor_sync(0xffffffffu, m1, 2));

        float nm0 = fmaxf(mr0, m0), nm1 = fmaxf(mr1, m1);
        float c0 = __expf(mr0 - nm0), c1 = __expf(mr1 - nm1);
        mr0 = nm0; mr1 = nm1;

        float s0 = 0.f, s1 = 0.f;
#pragma unroll
        for (int n = 0; n < 8; n++) {
            sacc[n][0] = __expf(sacc[n][0] - nm0);
            sacc[n][1] = __expf(sacc[n][1] - nm0);
            sacc[n][2] = __expf(sacc[n][2] - nm1);
            sacc[n][3] = __expf(sacc[n][3] - nm1);
            s0 += sacc[n][0] + sacc[n][1];
            s1 += sacc[n][2] + sacc[n][3];
        }
        s0 += __shfl_xor_sync(0xffffffffu, s0, 1);
        s0 += __shfl_xor_sync(0xffffffffu, s0, 2);
        s1 += __shfl_xor_sync(0xffffffffu, s1, 1);
        s1 += __shfl_xor_sync(0xffffffffu, s1, 2);
        lr0 = lr0*c0 + s0;
        lr1 = lr1*c1 + s1;

#pragma unroll
        for (int n = 0; n < 8; n++) {
            o[n][0] *= c0; o[n][1] *= c0;
            o[n][2] *= c1; o[n][3] *= c1;
        }

        // Store P (tf32) [row][key]
#pragma unroll
        for (int n = 0; n < 8; n++) {
            uint2 p0, p1;
            p0.x = f2tf32(sacc[n][0]); p0.y = f2tf32(sacc[n][1]);
            p1.x = f2tf32(sacc[n][2]); p1.y = f2tf32(sacc[n][3]);
            *(uint2*)&Pb[r0*AP_LD + n*8 + 2*t] = p0;
            *(uint2*)&Pb[r1*AP_LD + n*8 + 2*t] = p1;
        }
        __syncwarp();

        // --- AV ---
#pragma unroll
        for (int kc = 0; kc < 8; kc++) {
            int k0 = kc*8;
            u32 a[4];
            a[0] = Pb[r0*AP_LD + k0 + t];
            a[1] = Pb[r1*AP_LD + k0 + t];
            a[2] = Pb[r0*AP_LD + k0 + t + 4];
            a[3] = Pb[r1*AP_LD + k0 + t + 4];
#pragma unroll
            for (int n = 0; n < 8; n++) {
                u32 b0 = Vb[(k0 + t    )*AVS_LD + n*8 + g];
                u32 b1 = Vb[(k0 + t + 4)*AVS_LD + n*8 + g];
                mma_tf32(o[n], a, b0, b1);
            }
        }
    }

    // Epilogue
    float inv0 = 1.0f / lr0;
    float inv1 = 1.0f / lr1;
    int srow0 = q0 + r0;
    int srow1 = q0 + r1;
#pragma unroll
    for (int n = 0; n < 8; n++) {
        float2 w0, w1;
        w0.x = o[n][0]*inv0; w0.y = o[n][1]*inv0;
        w1.x = o[n][2]*inv1; w1.y = o[n][3]*inv1;
        *(float2*)&g_comb[((long long)(b*Sc + srow0))*Dc + h*HDc + n*8 + 2*t] = w0;
        *(float2*)&g_comb[((long long)(b*Sc + srow1))*Dc + h*HDc + n*8 + 2*t] = w1;
    }
}

// ---------------------------------------------------------------------------
// Launch
// ---------------------------------------------------------------------------
extern "C" void kernel_launch(void* const* d_in, const int* in_sizes, int n_in,
                              void* d_out, int out_size)
{
    const float* inputs = (const float*)d_in[0];
    const float* Wq = (const float*)d_in[1];
    const float* bq = (const float*)d_in[2];
    const float* Wk = (const float*)d_in[3];
    const float* bk = (const float*)d_in[4];
    const float* Wv = (const float*)d_in[5];
    const float* bv = (const float*)d_in[6];
    const float* Wt = (const float*)d_in[7];
    const float* bt = (const float*)d_in[8];
    const float* Wo = (const float*)d_in[9];
    const float* bo = (const float*)d_in[10];
    float* out = (float*)d_out;

    float *p_qkv, *p_comb, *p_up, *p_part, *p_wcat, *p_bcat, *p_woT;
    cudaGetSymbolAddress((void**)&p_qkv,  g_qkv);
    cudaGetSymbolAddress((void**)&p_comb, g_comb);
    cudaGetSymbolAddress((void**)&p_up,   g_up);
    cudaGetSymbolAddress((void**)&p_part, g_part);
    cudaGetSymbolAddress((void**)&p_wcat, g_wcat);
    cudaGetSymbolAddress((void**)&p_bcat, g_bcat);
    cudaGetSymbolAddress((void**)&p_woT,  g_woT);
    (void)in_sizes; (void)n_in; (void)out_size;

    const int attn_smem = ASM_TOT * (int)sizeof(u32);   // 107520 B
    cudaFuncSetAttribute(attn_kernel, cudaFuncAttributeMaxDynamicSharedMemorySize, attn_smem);

    // 1. Pack weights
    {
        int total = Ic*3*Dc + Dc*Ic + 3*Dc;
        pack_kernel<<<(total + 255)/256, 256>>>(Wq, bq, Wk, bk, Wv, bv, Wo);
    }

    // 2. QKV GEMM (tf32 tensor): inputs[8192,512] x wcat[512,1536] -> g_qkv
    {
        dim3 grid(3*Dc/128, (Bc*Sc)/128, 1);   // 12 x 64
        tgemm_kernel<<<grid, 256>>>(inputs, Ic, 0,
                                    p_wcat, 3*Dc, 0,
                                    p_qkv, 3*Dc, 0,
                                    Bc*Sc, 3*Dc, Ic, p_bcat, 1, 1);
    }

    // 3. Attention (tf32 mma, K read in-place) -> g_comb
    attn_kernel<<<dim3(Sc/128, Hc, Bc), 256, attn_smem>>>();

    // 4. Temporal GEMM (tf32 tensor), split-K x4: Wt[720,2048] x comb_b[2048,512]
    {
        dim3 grid(Dc/128, (Pc + 127)/128, Bc*4);   // 4 x 6 x 16
        tgemm_kernel<<<grid, 256>>>(Wt, Sc, 0,
                                    p_comb, Dc, (long long)Sc*Dc,
                                    p_part, Dc, (long long)Pc*Dc,
                                    Pc, Dc, Sc/4, (const float*)0, 0, 4);
        int MN = Pc*Dc;
        int total4 = Bc*MN/4;
        reduce_kernel<<<(total4 + 255)/256, 256>>>(p_up, p_part, bt, 2, Dc, MN, 4, total4);
    }

    // 5. Output GEMM (f32x2, accuracy anchor), split-K x2: up[2880,512] x woT[512,512]
    {
        dim3 grid(Ic/128, (Bc*Pc + 127)/128, 2);   // 4 x 23 x 2
        sgemm128_kernel<<<grid, 256>>>(p_up, Dc, 0,
                                       p_woT, Ic, 0,
                                       p_part, Ic, (long long)(Bc*Pc)*Ic,
                                       Bc*Pc, Ic, Dc/2, (const float*)0, 0, 2);
        int MN = Bc*Pc*Ic;
        int total4 = MN/4;
        reduce_kernel<<<(total4 + 255)/256, 256>>>(out, p_part, bo, 1, Ic, MN, 2, total4);
    }
}

// round 9
// speedup vs baseline: 3.9759x; 1.3121x over previous
#include <cuda_runtime.h>
#include <math.h>

// Problem constants
#define Bc 4
#define Sc 2048
#define Ic 512
#define Dc 512
#define Hc 8
#define HDc 64
#define Pc 720

typedef unsigned long long u64;
typedef unsigned int u32;

// tf32 helpers
__device__ __forceinline__ u32 f2tf32(float x) {
    u32 r; asm("cvt.rna.tf32.f32 %0, %1;" : "=r"(r) : "f"(x)); return r;
}
__device__ __forceinline__ float tf32r(float x) {   // round-to-nearest tf32, as float
    return __uint_as_float(f2tf32(x));
}
__device__ __forceinline__ void mma_tf32(float d[4], const u32 a[4], u32 b0, u32 b1) {
    asm volatile(
        "mma.sync.aligned.m16n8k8.row.col.f32.tf32.tf32.f32 "
        "{%0,%1,%2,%3}, {%4,%5,%6,%7}, {%8,%9}, {%0,%1,%2,%3};\n"
        : "+f"(d[0]), "+f"(d[1]), "+f"(d[2]), "+f"(d[3])
        : "r"(a[0]), "r"(a[1]), "r"(a[2]), "r"(a[3]), "r"(b0), "r"(b1));
}

// cp.async helpers
__device__ __forceinline__ void cpasync16(void* smem_ptr, const void* gptr, int sz) {
    u32 sa = (u32)__cvta_generic_to_shared(smem_ptr);
    asm volatile("cp.async.cg.shared.global [%0], [%1], 16, %2;"
                 :: "r"(sa), "l"(gptr), "r"(sz));
}
#define CP_COMMIT asm volatile("cp.async.commit_group;")
#define CP_WAIT0  asm volatile("cp.async.wait_group 0;")
#define CP_WAIT1  asm volatile("cp.async.wait_group 1;")

// Scratch (device globals — no allocation allowed)
__device__ float g_qkv[Bc*Sc*3*Dc];      // [b,s, q|k|v], tf32-rounded (q pre-scaled 1/64)
__device__ float g_comb[Bc*Sc*Dc];       // [b,s,d], tf32-rounded
__device__ float g_up [Bc*Pc*Dc];        // [b,p,d], tf32-rounded
__device__ float g_part[16*Pc*Dc];       // split-K partials (fp32)
__device__ float g_wcat[Ic*3*Dc];        // tf32-rounded
__device__ float g_bcat[3*Dc];           // fp32
__device__ float g_woT[Dc*Ic];           // tf32-rounded
__device__ float g_wt [Pc*Sc];           // tf32-rounded copy of Wt
__device__ float g_in [Bc*Sc*Ic];        // tf32-rounded copy of inputs

// ---------------------------------------------------------------------------
// Pack + pre-round weights/inputs to tf32 (RNA)
// ---------------------------------------------------------------------------
__global__ void pack_kernel(const float* __restrict__ inputs,
                            const float* __restrict__ Wq, const float* __restrict__ bq,
                            const float* __restrict__ Wk, const float* __restrict__ bk,
                            const float* __restrict__ Wv, const float* __restrict__ bv,
                            const float* __restrict__ Wt, const float* __restrict__ Wo)
{
    const int NW  = Ic*3*Dc;        // 786432
    const int NWO = Dc*Ic;          // 262144
    const int NWT = Pc*Sc;          // 1474560
    const int NIN = Bc*Sc*Ic;       // 4194304
    int gid = blockIdx.x*blockDim.x + threadIdx.x;
    if (gid < NW) {
        int i = gid / (3*Dc);
        int n = gid % (3*Dc);
        int sec = n / Dc;
        int nn  = n % Dc;
        const float* W = (sec==0) ? Wq : (sec==1) ? Wk : Wv;
        int h = nn / HDc, d = nn % HDc;
        g_wcat[gid] = tf32r(W[(h*Ic + i)*HDc + d]);
    } else if (gid < NW + NWO) {
        int t = gid - NW;
        int d = t / Ic, o = t % Ic;
        g_woT[t] = tf32r(Wo[o*Dc + d]);
    } else if (gid < NW + NWO + NWT) {
        int t = gid - NW - NWO;
        g_wt[t] = tf32r(Wt[t]);
    } else if (gid < NW + NWO + NWT + NIN) {
        int t = gid - NW - NWO - NWT;
        g_in[t] = tf32r(inputs[t]);
    } else if (gid < NW + NWO + NWT + NIN + 3*Dc) {
        int n = gid - NW - NWO - NWT - NIN;
        int sec = n / Dc, nn = n % Dc;
        const float* bv_ = (sec==0) ? bq : (sec==1) ? bk : bv;
        g_bcat[n] = bv_[nn];
    }
}

// ---------------------------------------------------------------------------
// tf32 tensor GEMM, cp.async 2-stage pipeline. C[M,N] = A[M,K] x B[K,N].
// Inputs MUST be pre-rounded tf32. 128x128 tile, BK=16, 8 warps (2x4).
// outMode: 0 raw fp32 out; 1 tf32-rounded out; 2 tf32 out, cols<Dc scaled 1/64.
// biasMode: 0 none, 1 per-col, 2 per-row. Split-K: blockIdx.z = bz*nsplit+kc.
// ---------------------------------------------------------------------------
#define TA_LD 20
#define TB_LD 136
__global__ __launch_bounds__(256)
void tgemm_kernel(const float* __restrict__ A, int lda, long long strideA,
                  const float* __restrict__ Bm, int ldb, long long strideB,
                  float* __restrict__ C, int ldc, long long strideC,
                  int M, int N, int K,
                  const float* __restrict__ bias, int biasMode, int nsplit,
                  int outMode)
{
    int bz  = blockIdx.z / nsplit;
    int kcs = blockIdx.z % nsplit;
    A  += (long long)bz * strideA + (long long)kcs * K;
    Bm += (long long)bz * strideB + (long long)kcs * K * ldb;
    C  += (long long)blockIdx.z * strideC;

    __shared__ float As[2][128*TA_LD];   // [m][k] ld 20
    __shared__ float Bs[2][16*TB_LD];    // [k][n] ld 136

    int tid  = threadIdx.x;
    int warp = tid >> 5;
    int lane = tid & 31;
    int g = lane >> 2;
    int t = lane & 3;
    int wm = warp >> 2;
    int wn = warp & 3;
    int m0 = blockIdx.y * 128;
    int n0 = blockIdx.x * 128;

    // load coords (2 x 16B chunks per thread for each of A and B)
    int arow0 = (tid) >> 2,        akc0 = ((tid) & 3) << 2;
    int arow1 = (tid+256) >> 2,    akc1 = ((tid+256) & 3) << 2;
    int bkr0  = (tid) >> 5,        bnc0 = ((tid) & 31) << 2;
    int bkr1  = (tid+256) >> 5,    bnc1 = ((tid+256) & 31) << 2;

    float acc[4][4][4];
#pragma unroll
    for (int mt = 0; mt < 4; mt++)
#pragma unroll
        for (int nt = 0; nt < 4; nt++)
#pragma unroll
            for (int j = 0; j < 4; j++) acc[mt][nt][j] = 0.f;

    int nIter = K >> 4;

    // prologue: prefetch tile 0 into stage 0
    {
        int k0 = 0;
        int gm0 = m0 + arow0; int s0 = (gm0 < M) ? 16 : 0; if (gm0 >= M) gm0 = M-1;
        int gm1 = m0 + arow1; int s1 = (gm1 < M) ? 16 : 0; if (gm1 >= M) gm1 = M-1;
        cpasync16(&As[0][arow0*TA_LD + akc0], &A[(long long)gm0*lda + k0 + akc0], s0);
        cpasync16(&As[0][arow1*TA_LD + akc1], &A[(long long)gm1*lda + k0 + akc1], s1);
        cpasync16(&Bs[0][bkr0*TB_LD + bnc0], &Bm[(long long)(k0+bkr0)*ldb + n0 + bnc0], 16);
        cpasync16(&Bs[0][bkr1*TB_LD + bnc1], &Bm[(long long)(k0+bkr1)*ldb + n0 + bnc1], 16);
        CP_COMMIT;
    }

    for (int it = 0; it < nIter; it++) {
        int cur = it & 1;
        if (it + 1 < nIter) {
            int k0 = (it+1) << 4;
            int nx = cur ^ 1;
            int gm0 = m0 + arow0; int s0 = (gm0 < M) ? 16 : 0; if (gm0 >= M) gm0 = M-1;
            int gm1 = m0 + arow1; int s1 = (gm1 < M) ? 16 : 0; if (gm1 >= M) gm1 = M-1;
            cpasync16(&As[nx][arow0*TA_LD + akc0], &A[(long long)gm0*lda + k0 + akc0], s0);
            cpasync16(&As[nx][arow1*TA_LD + akc1], &A[(long long)gm1*lda + k0 + akc1], s1);
            cpasync16(&Bs[nx][bkr0*TB_LD + bnc0], &Bm[(long long)(k0+bkr0)*ldb + n0 + bnc0], 16);
            cpasync16(&Bs[nx][bkr1*TB_LD + bnc1], &Bm[(long long)(k0+bkr1)*ldb + n0 + bnc1], 16);
            CP_COMMIT;
            CP_WAIT1;
        } else {
            CP_WAIT0;
        }
        __syncthreads();

        const u32* Asu = (const u32*)As[cur];
        const u32* Bsu = (const u32*)Bs[cur];
#pragma unroll
        for (int kc = 0; kc < 2; kc++) {
            int kk = kc*8;
            u32 a[4][4];
#pragma unroll
            for (int mt = 0; mt < 4; mt++) {
                int mrow = wm*64 + mt*16;
                a[mt][0] = Asu[(mrow + g    )*TA_LD + kk + t];
                a[mt][1] = Asu[(mrow + g + 8)*TA_LD + kk + t];
                a[mt][2] = Asu[(mrow + g    )*TA_LD + kk + t + 4];
                a[mt][3] = Asu[(mrow + g + 8)*TA_LD + kk + t + 4];
            }
#pragma unroll
            for (int nt = 0; nt < 4; nt++) {
                int ncol = wn*32 + nt*8;
                u32 b0 = Bsu[(kk + t    )*TB_LD + ncol + g];
                u32 b1 = Bsu[(kk + t + 4)*TB_LD + ncol + g];
#pragma unroll
                for (int mt = 0; mt < 4; mt++)
                    mma_tf32(acc[mt][nt], a[mt], b0, b1);
            }
        }
        __syncthreads();
    }

    // Epilogue
#pragma unroll
    for (int mt = 0; mt < 4; mt++) {
#pragma unroll
        for (int hrow = 0; hrow < 2; hrow++) {
            int m = m0 + wm*64 + mt*16 + g + hrow*8;
            if (m >= M) continue;
            float brow = (biasMode == 2) ? bias[m] : 0.f;
#pragma unroll
            for (int nt = 0; nt < 4; nt++) {
                int c = n0 + wn*32 + nt*8 + 2*t;
                float2 w;
                w.x = acc[mt][nt][hrow*2 + 0] + brow;
                w.y = acc[mt][nt][hrow*2 + 1] + brow;
                if (biasMode == 1) { w.x += bias[c]; w.y += bias[c+1]; }
                if (outMode == 2) {
                    float sc = (c < Dc) ? (1.0f/(float)HDc) : 1.0f;
                    w.x = tf32r(w.x * sc);
                    w.y = tf32r(w.y * sc);
                } else if (outMode == 1) {
                    w.x = tf32r(w.x);
                    w.y = tf32r(w.y);
                }
                *(float2*)&C[(long long)m*ldc + c] = w;
            }
        }
    }
}

// ---------------------------------------------------------------------------
// Reduce split-K partials; cvtOut: round result to tf32 (for downstream mma)
// ---------------------------------------------------------------------------
__global__ void reduce_kernel(float* __restrict__ dst, const float* __restrict__ part,
                              const float* __restrict__ bias, int biasMode,
                              int N, int MN, int G, int total4, int cvtOut)
{
    int e = blockIdx.x*256 + threadIdx.x;
    if (e >= total4) return;
    int MN4 = MN >> 2;
    int b = e / MN4, i4 = e - b*MN4;
    int i = i4 << 2;
    float4 s;
    if (biasMode == 1) {
        s = *(const float4*)&bias[i % N];
    } else if (biasMode == 2) {
        float bv = bias[i / N];
        s = make_float4(bv, bv, bv, bv);
    } else {
        s = make_float4(0.f,0.f,0.f,0.f);
    }
#pragma unroll 4
    for (int g = 0; g < G; g++) {
        float4 p = *(const float4*)&part[((long long)(b*G+g))*MN + i];
        s.x += p.x; s.y += p.y; s.z += p.z; s.w += p.w;
    }
    if (cvtOut) {
        s.x = tf32r(s.x); s.y = tf32r(s.y); s.z = tf32r(s.z); s.w = tf32r(s.w);
    }
    *(float4*)&dst[(long long)b*MN + i] = s;
}

// ---------------------------------------------------------------------------
// Flash attention, tf32 mma.sync: 128 q-rows/CTA, 64-key tiles.
// Q/K/V pre-rounded tf32 in g_qkv (Q pre-scaled 1/64) -> cp.async, zero cvt.
// smem: Qb[128][68] | Kb[64][76] | Vb[64][72] | Pb[128][68]
// ---------------------------------------------------------------------------
#define AQ_LD 68
#define AK_LD 76
#define AVS_LD 72
#define AP_LD 68
#define ASM_Q 0
#define ASM_K (128*AQ_LD)
#define ASM_V (ASM_K + 64*AK_LD)
#define ASM_P (ASM_V + 64*AVS_LD)
#define ASM_TOT (ASM_P + 128*AP_LD)   // 26880 u32 = 107520 bytes

__global__ __launch_bounds__(256, 2)
void attn_kernel()
{
    extern __shared__ u32 smu[];
    u32* Qb = smu + ASM_Q;   // [row][feat] ld 68
    u32* Kb = smu + ASM_K;   // [key][feat] ld 76
    u32* Vb = smu + ASM_V;   // [key][feat] ld 72
    u32* Pb = smu + ASM_P;   // [row][key]  ld 68

    int tid  = threadIdx.x;
    int warp = tid >> 5;
    int lane = tid & 31;
    int g = lane >> 2;
    int t = lane & 3;
    int q0 = blockIdx.x * 128;
    int h  = blockIdx.y;
    int b  = blockIdx.z;
    int r0 = warp*16 + g;
    int r1 = r0 + 8;

    // Q tile via cp.async (already scaled + tf32-rounded)
#pragma unroll
    for (int l = 0; l < 8; l++) {
        int lin = tid + l*256;
        int row = lin >> 4;
        int c4  = (lin & 15) << 2;
        cpasync16(&Qb[row*AQ_LD + c4],
                  &g_qkv[((long long)(b*Sc + q0 + row))*(3*Dc) + h*HDc + c4], 16);
    }
    CP_COMMIT;

    float o[8][4];
#pragma unroll
    for (int n = 0; n < 8; n++)
#pragma unroll
        for (int j = 0; j < 4; j++) o[n][j] = 0.f;
    float mr0 = -1e30f, mr1 = -1e30f, lr0 = 0.f, lr1 = 0.f;

    for (int t0 = 0; t0 < Sc; t0 += 64) {
        __syncthreads();   // prior tile fully consumed

        // K/V tiles via cp.async
#pragma unroll
        for (int l = 0; l < 4; l++) {
            int lin = tid + l*256;
            int tr = lin >> 4;
            int c4 = (lin & 15) << 2;
            cpasync16(&Kb[tr*AK_LD + c4],
                      &g_qkv[((long long)(b*Sc + t0 + tr))*(3*Dc) + Dc + h*HDc + c4], 16);
        }
#pragma unroll
        for (int l = 0; l < 4; l++) {
            int lin = tid + l*256;
            int tr = lin >> 4;
            int c4 = (lin & 15) << 2;
            cpasync16(&Vb[tr*AVS_LD + c4],
                      &g_qkv[((long long)(b*Sc + t0 + tr))*(3*Dc) + 2*Dc + h*HDc + c4], 16);
        }
        CP_COMMIT;
        CP_WAIT0;
        __syncthreads();

        // --- QK^T ---
        float sacc[8][4];
#pragma unroll
        for (int n = 0; n < 8; n++)
#pragma unroll
            for (int j = 0; j < 4; j++) sacc[n][j] = 0.f;

#pragma unroll
        for (int kc = 0; kc < 8; kc++) {
            int k0 = kc*8;
            u32 a[4];
            a[0] = Qb[r0*AQ_LD + k0 + t];
            a[1] = Qb[r1*AQ_LD + k0 + t];
            a[2] = Qb[r0*AQ_LD + k0 + t + 4];
            a[3] = Qb[r1*AQ_LD + k0 + t + 4];
#pragma unroll
            for (int n = 0; n < 8; n++) {
                u32 b0 = Kb[(n*8 + g)*AK_LD + k0 + t];
                u32 b1 = Kb[(n*8 + g)*AK_LD + k0 + t + 4];
                mma_tf32(sacc[n], a, b0, b1);
            }
        }

        // --- Online softmax ---
        float m0 = -1e30f, m1 = -1e30f;
#pragma unroll
        for (int n = 0; n < 8; n++) {
            m0 = fmaxf(m0, fmaxf(sacc[n][0], sacc[n][1]));
            m1 = fmaxf(m1, fmaxf(sacc[n][2], sacc[n][3]));
        }
        m0 = fmaxf(m0, __shfl_xor_sync(0xffffffffu, m0, 1));
        m0 = fmaxf(m0, __shfl_xor_sync(0xffffffffu, m0, 2));
        m1 = fmaxf(m1, __shfl_xor_sync(0xffffffffu, m1, 1));
        m1 = fmaxf(m1, __shfl_xor_sync(0xffffffffu, m1, 2));

        float nm0 = fmaxf(mr0, m0), nm1 = fmaxf(mr1, m1);
        float c0 = __expf(mr0 - nm0), c1 = __expf(mr1 - nm1);
        mr0 = nm0; mr1 = nm1;

        // tf32-round P BEFORE summing l, so P/l normalization is bias-free
        float s0 = 0.f, s1 = 0.f;
#pragma unroll
        for (int n = 0; n < 8; n++) {
            sacc[n][0] = tf32r(__expf(sacc[n][0] - nm0));
            sacc[n][1] = tf32r(__expf(sacc[n][1] - nm0));
            sacc[n][2] = tf32r(__expf(sacc[n][2] - nm1));
            sacc[n][3] = tf32r(__expf(sacc[n][3] - nm1));
            s0 += sacc[n][0] + sacc[n][1];
            s1 += sacc[n][2] + sacc[n][3];
        }
        s0 += __shfl_xor_sync(0xffffffffu, s0, 1);
        s0 += __shfl_xor_sync(0xffffffffu, s0, 2);
        s1 += __shfl_xor_sync(0xffffffffu, s1, 1);
        s1 += __shfl_xor_sync(0xffffffffu, s1, 2);
        lr0 = lr0*c0 + s0;
        lr1 = lr1*c1 + s1;

#pragma unroll
        for (int n = 0; n < 8; n++) {
            o[n][0] *= c0; o[n][1] *= c0;
            o[n][2] *= c1; o[n][3] *= c1;
        }

        // Store P (raw tf32 bits) [row][key]
#pragma unroll
        for (int n = 0; n < 8; n++) {
            uint2 p0, p1;
            p0.x = __float_as_uint(sacc[n][0]); p0.y = __float_as_uint(sacc[n][1]);
            p1.x = __float_as_uint(sacc[n][2]); p1.y = __float_as_uint(sacc[n][3]);
            *(uint2*)&Pb[r0*AP_LD + n*8 + 2*t] = p0;
            *(uint2*)&Pb[r1*AP_LD + n*8 + 2*t] = p1;
        }
        __syncwarp();

        // --- AV ---
#pragma unroll
        for (int kc = 0; kc < 8; kc++) {
            int k0 = kc*8;
            u32 a[4];
            a[0] = Pb[r0*AP_LD + k0 + t];
            a[1] = Pb[r1*AP_LD + k0 + t];
            a[2] = Pb[r0*AP_LD + k0 + t + 4];
            a[3] = Pb[r1*AP_LD + k0 + t + 4];
#pragma unroll
            for (int n = 0; n < 8; n++) {
                u32 b0 = Vb[(k0 + t    )*AVS_LD + n*8 + g];
                u32 b1 = Vb[(k0 + t + 4)*AVS_LD + n*8 + g];
                mma_tf32(o[n], a, b0, b1);
            }
        }
    }

    // Epilogue: normalize, tf32-round (consumed by temporal tgemm)
    float inv0 = 1.0f / lr0;
    float inv1 = 1.0f / lr1;
    int srow0 = q0 + r0;
    int srow1 = q0 + r1;
#pragma unroll
    for (int n = 0; n < 8; n++) {
        float2 w0, w1;
        w0.x = tf32r(o[n][0]*inv0); w0.y = tf32r(o[n][1]*inv0);
        w1.x = tf32r(o[n][2]*inv1); w1.y = tf32r(o[n][3]*inv1);
        *(float2*)&g_comb[((long long)(b*Sc + srow0))*Dc + h*HDc + n*8 + 2*t] = w0;
        *(float2*)&g_comb[((long long)(b*Sc + srow1))*Dc + h*HDc + n*8 + 2*t] = w1;
    }
}

// ---------------------------------------------------------------------------
// Launch
// ---------------------------------------------------------------------------
extern "C" void kernel_launch(void* const* d_in, const int* in_sizes, int n_in,
                              void* d_out, int out_size)
{
    const float* inputs = (const float*)d_in[0];
    const float* Wq = (const float*)d_in[1];
    const float* bq = (const float*)d_in[2];
    const float* Wk = (const float*)d_in[3];
    const float* bk = (const float*)d_in[4];
    const float* Wv = (const float*)d_in[5];
    const float* bv = (const float*)d_in[6];
    const float* Wt = (const float*)d_in[7];
    const float* bt = (const float*)d_in[8];
    const float* Wo = (const float*)d_in[9];
    const float* bo = (const float*)d_in[10];
    float* out = (float*)d_out;

    float *p_qkv, *p_comb, *p_up, *p_part, *p_wcat, *p_bcat, *p_woT, *p_wt, *p_in;
    cudaGetSymbolAddress((void**)&p_qkv,  g_qkv);
    cudaGetSymbolAddress((void**)&p_comb, g_comb);
    cudaGetSymbolAddress((void**)&p_up,   g_up);
    cudaGetSymbolAddress((void**)&p_part, g_part);
    cudaGetSymbolAddress((void**)&p_wcat, g_wcat);
    cudaGetSymbolAddress((void**)&p_bcat, g_bcat);
    cudaGetSymbolAddress((void**)&p_woT,  g_woT);
    cudaGetSymbolAddress((void**)&p_wt,   g_wt);
    cudaGetSymbolAddress((void**)&p_in,   g_in);
    (void)in_sizes; (void)n_in; (void)out_size;

    const int attn_smem = ASM_TOT * (int)sizeof(u32);   // 107520 B
    cudaFuncSetAttribute(attn_kernel, cudaFuncAttributeMaxDynamicSharedMemorySize, attn_smem);

    // 1. Pack + pre-round weights & inputs
    {
        int total = Ic*3*Dc + Dc*Ic + Pc*Sc + Bc*Sc*Ic + 3*Dc;
        pack_kernel<<<(total + 255)/256, 256>>>(inputs, Wq, bq, Wk, bk, Wv, bv, Wt, Wo);
    }

    // 2. QKV GEMM: g_in[8192,512] x wcat[512,1536] -> g_qkv (tf32 out, Q scaled)
    {
        dim3 grid(3*Dc/128, (Bc*Sc)/128, 1);   // 12 x 64
        tgemm_kernel<<<grid, 256>>>(p_in, Ic, 0,
                                    p_wcat, 3*Dc, 0,
                                    p_qkv, 3*Dc, 0,
                                    Bc*Sc, 3*Dc, Ic, p_bcat, 1, 1, /*outMode=*/2);
    }

    // 3. Attention -> g_comb (tf32 out)
    attn_kernel<<<dim3(Sc/128, Hc, Bc), 256, attn_smem>>>();

    // 4. Temporal GEMM, split-K x4: g_wt[720,2048] x comb_b[2048,512] -> partials
    {
        dim3 grid(Dc/128, (Pc + 127)/128, Bc*4);   // 4 x 6 x 16
        tgemm_kernel<<<grid, 256>>>(p_wt, Sc, 0,
                                    p_comb, Dc, (long long)Sc*Dc,
                                    p_part, Dc, (long long)Pc*Dc,
                                    Pc, Dc, Sc/4, (const float*)0, 0, 4, /*outMode=*/0);
        int MN = Pc*Dc;
        int total4 = Bc*MN/4;
        reduce_kernel<<<(total4 + 255)/256, 256>>>(p_up, p_part, bt, 2, Dc, MN, 4, total4, /*cvtOut=*/1);
    }

    // 5. Output GEMM, split-K x2: up[2880,512] x woT[512,512] -> out (+bo)
    {
        dim3 grid(Ic/128, (Bc*Pc + 127)/128, 2);   // 4 x 23 x 2
        tgemm_kernel<<<grid, 256>>>(p_up, Dc, 0,
                                    p_woT, Ic, 0,
                                    p_part, Ic, (long long)(Bc*Pc)*Ic,
                                    Bc*Pc, Ic, Dc/2, (const float*)0, 0, 2, /*outMode=*/0);
        int MN = Bc*Pc*Ic;
        int total4 = MN/4;
        reduce_kernel<<<(total4 + 255)/256, 256>>>(out, p_part, bo, 1, Ic, MN, 2, total4, /*cvtOut=*/0);
    }
}

// round 10
// speedup vs baseline: 4.0733x; 1.0245x over previous
#include <cuda_runtime.h>
#include <math.h>

// Problem constants
#define Bc 4
#define Sc 2048
#define Ic 512
#define Dc 512
#define Hc 8
#define HDc 64
#define Pc 720

typedef unsigned long long u64;
typedef unsigned int u32;

// tf32 helpers
__device__ __forceinline__ u32 f2tf32(float x) {
    u32 r; asm("cvt.rna.tf32.f32 %0, %1;" : "=r"(r) : "f"(x)); return r;
}
__device__ __forceinline__ float tf32r(float x) {
    return __uint_as_float(f2tf32(x));
}
__device__ __forceinline__ void mma_tf32(float d[4], const u32 a[4], u32 b0, u32 b1) {
    asm volatile(
        "mma.sync.aligned.m16n8k8.row.col.f32.tf32.tf32.f32 "
        "{%0,%1,%2,%3}, {%4,%5,%6,%7}, {%8,%9}, {%0,%1,%2,%3};\n"
        : "+f"(d[0]), "+f"(d[1]), "+f"(d[2]), "+f"(d[3])
        : "r"(a[0]), "r"(a[1]), "r"(a[2]), "r"(a[3]), "r"(b0), "r"(b1));
}

// cp.async helpers
__device__ __forceinline__ void cpasync16(void* smem_ptr, const void* gptr, int sz) {
    u32 sa = (u32)__cvta_generic_to_shared(smem_ptr);
    asm volatile("cp.async.cg.shared.global [%0], [%1], 16, %2;"
                 :: "r"(sa), "l"(gptr), "r"(sz));
}
#define CP_COMMIT asm volatile("cp.async.commit_group;")
#define CP_WAIT0  asm volatile("cp.async.wait_group 0;")
#define CP_WAIT1  asm volatile("cp.async.wait_group 1;")

// Scratch (device globals — no allocation allowed)
__device__ float g_qkv[Bc*Sc*3*Dc];      // [b,s, q|k|v], tf32-rounded (q pre-scaled 1/64)
__device__ float g_comb[Bc*Sc*Dc];       // [b,s,d], tf32-rounded
__device__ float g_up [Bc*Pc*Dc];        // [b,p,d], tf32-rounded
__device__ float g_part[16*Pc*Dc];       // split-K partials (fp32)
__device__ float g_wcat[Ic*3*Dc];        // tf32-rounded
__device__ float g_bcat[3*Dc];           // fp32
__device__ float g_woT[Dc*Ic];           // tf32-rounded
__device__ float g_wt [Pc*Sc];           // tf32-rounded copy of Wt
__device__ float g_in [Bc*Sc*Ic];        // tf32-rounded copy of inputs

// ---------------------------------------------------------------------------
// Pack + pre-round weights/inputs to tf32 (RNA)
// ---------------------------------------------------------------------------
__global__ void pack_kernel(const float* __restrict__ inputs,
                            const float* __restrict__ Wq, const float* __restrict__ bq,
                            const float* __restrict__ Wk, const float* __restrict__ bk,
                            const float* __restrict__ Wv, const float* __restrict__ bv,
                            const float* __restrict__ Wt, const float* __restrict__ Wo)
{
    const int NW  = Ic*3*Dc;
    const int NWO = Dc*Ic;
    const int NWT = Pc*Sc;
    const int NIN = Bc*Sc*Ic;
    int gid = blockIdx.x*blockDim.x + threadIdx.x;
    if (gid < NW) {
        int i = gid / (3*Dc);
        int n = gid % (3*Dc);
        int sec = n / Dc;
        int nn  = n % Dc;
        const float* W = (sec==0) ? Wq : (sec==1) ? Wk : Wv;
        int h = nn / HDc, d = nn % HDc;
        g_wcat[gid] = tf32r(W[(h*Ic + i)*HDc + d]);
    } else if (gid < NW + NWO) {
        int t = gid - NW;
        int d = t / Ic, o = t % Ic;
        g_woT[t] = tf32r(Wo[o*Dc + d]);
    } else if (gid < NW + NWO + NWT) {
        int t = gid - NW - NWO;
        g_wt[t] = tf32r(Wt[t]);
    } else if (gid < NW + NWO + NWT + NIN) {
        int t = gid - NW - NWO - NWT;
        g_in[t] = tf32r(inputs[t]);
    } else if (gid < NW + NWO + NWT + NIN + 3*Dc) {
        int n = gid - NW - NWO - NWT - NIN;
        int sec = n / Dc, nn = n % Dc;
        const float* bv_ = (sec==0) ? bq : (sec==1) ? bk : bv;
        g_bcat[n] = bv_[nn];
    }
}

// ---------------------------------------------------------------------------
// tf32 tensor GEMM, cp.async 2-stage pipeline (unchanged from R9)
// ---------------------------------------------------------------------------
#define TA_LD 20
#define TB_LD 136
__global__ __launch_bounds__(256)
void tgemm_kernel(const float* __restrict__ A, int lda, long long strideA,
                  const float* __restrict__ Bm, int ldb, long long strideB,
                  float* __restrict__ C, int ldc, long long strideC,
                  int M, int N, int K,
                  const float* __restrict__ bias, int biasMode, int nsplit,
                  int outMode)
{
    int bz  = blockIdx.z / nsplit;
    int kcs = blockIdx.z % nsplit;
    A  += (long long)bz * strideA + (long long)kcs * K;
    Bm += (long long)bz * strideB + (long long)kcs * K * ldb;
    C  += (long long)blockIdx.z * strideC;

    __shared__ float As[2][128*TA_LD];
    __shared__ float Bs[2][16*TB_LD];

    int tid  = threadIdx.x;
    int warp = tid >> 5;
    int lane = tid & 31;
    int g = lane >> 2;
    int t = lane & 3;
    int wm = warp >> 2;
    int wn = warp & 3;
    int m0 = blockIdx.y * 128;
    int n0 = blockIdx.x * 128;

    int arow0 = (tid) >> 2,        akc0 = ((tid) & 3) << 2;
    int arow1 = (tid+256) >> 2,    akc1 = ((tid+256) & 3) << 2;
    int bkr0  = (tid) >> 5,        bnc0 = ((tid) & 31) << 2;
    int bkr1  = (tid+256) >> 5,    bnc1 = ((tid+256) & 31) << 2;

    float acc[4][4][4];
#pragma unroll
    for (int mt = 0; mt < 4; mt++)
#pragma unroll
        for (int nt = 0; nt < 4; nt++)
#pragma unroll
            for (int j = 0; j < 4; j++) acc[mt][nt][j] = 0.f;

    int nIter = K >> 4;

    {
        int k0 = 0;
        int gm0 = m0 + arow0; int s0 = (gm0 < M) ? 16 : 0; if (gm0 >= M) gm0 = M-1;
        int gm1 = m0 + arow1; int s1 = (gm1 < M) ? 16 : 0; if (gm1 >= M) gm1 = M-1;
        cpasync16(&As[0][arow0*TA_LD + akc0], &A[(long long)gm0*lda + k0 + akc0], s0);
        cpasync16(&As[0][arow1*TA_LD + akc1], &A[(long long)gm1*lda + k0 + akc1], s1);
        cpasync16(&Bs[0][bkr0*TB_LD + bnc0], &Bm[(long long)(k0+bkr0)*ldb + n0 + bnc0], 16);
        cpasync16(&Bs[0][bkr1*TB_LD + bnc1], &Bm[(long long)(k0+bkr1)*ldb + n0 + bnc1], 16);
        CP_COMMIT;
    }

    for (int it = 0; it < nIter; it++) {
        int cur = it & 1;
        if (it + 1 < nIter) {
            int k0 = (it+1) << 4;
            int nx = cur ^ 1;
            int gm0 = m0 + arow0; int s0 = (gm0 < M) ? 16 : 0; if (gm0 >= M) gm0 = M-1;
            int gm1 = m0 + arow1; int s1 = (gm1 < M) ? 16 : 0; if (gm1 >= M) gm1 = M-1;
            cpasync16(&As[nx][arow0*TA_LD + akc0], &A[(long long)gm0*lda + k0 + akc0], s0);
            cpasync16(&As[nx][arow1*TA_LD + akc1], &A[(long long)gm1*lda + k0 + akc1], s1);
            cpasync16(&Bs[nx][bkr0*TB_LD + bnc0], &Bm[(long long)(k0+bkr0)*ldb + n0 + bnc0], 16);
            cpasync16(&Bs[nx][bkr1*TB_LD + bnc1], &Bm[(long long)(k0+bkr1)*ldb + n0 + bnc1], 16);
            CP_COMMIT;
            CP_WAIT1;
        } else {
            CP_WAIT0;
        }
        __syncthreads();

        const u32* Asu = (const u32*)As[cur];
        const u32* Bsu = (const u32*)Bs[cur];
#pragma unroll
        for (int kc = 0; kc < 2; kc++) {
            int kk = kc*8;
            u32 a[4][4];
#pragma unroll
            for (int mt = 0; mt < 4; mt++) {
                int mrow = wm*64 + mt*16;
                a[mt][0] = Asu[(mrow + g    )*TA_LD + kk + t];
                a[mt][1] = Asu[(mrow + g + 8)*TA_LD + kk + t];
                a[mt][2] = Asu[(mrow + g    )*TA_LD + kk + t + 4];
                a[mt][3] = Asu[(mrow + g + 8)*TA_LD + kk + t + 4];
            }
#pragma unroll
            for (int nt = 0; nt < 4; nt++) {
                int ncol = wn*32 + nt*8;
                u32 b0 = Bsu[(kk + t    )*TB_LD + ncol + g];
                u32 b1 = Bsu[(kk + t + 4)*TB_LD + ncol + g];
#pragma unroll
                for (int mt = 0; mt < 4; mt++)
                    mma_tf32(acc[mt][nt], a[mt], b0, b1);
            }
        }
        __syncthreads();
    }

#pragma unroll
    for (int mt = 0; mt < 4; mt++) {
#pragma unroll
        for (int hrow = 0; hrow < 2; hrow++) {
            int m = m0 + wm*64 + mt*16 + g + hrow*8;
            if (m >= M) continue;
            float brow = (biasMode == 2) ? bias[m] : 0.f;
#pragma unroll
            for (int nt = 0; nt < 4; nt++) {
                int c = n0 + wn*32 + nt*8 + 2*t;
                float2 w;
                w.x = acc[mt][nt][hrow*2 + 0] + brow;
                w.y = acc[mt][nt][hrow*2 + 1] + brow;
                if (biasMode == 1) { w.x += bias[c]; w.y += bias[c+1]; }
                if (outMode == 2) {
                    float sc = (c < Dc) ? (1.0f/(float)HDc) : 1.0f;
                    w.x = tf32r(w.x * sc);
                    w.y = tf32r(w.y * sc);
                } else if (outMode == 1) {
                    w.x = tf32r(w.x);
                    w.y = tf32r(w.y);
                }
                *(float2*)&C[(long long)m*ldc + c] = w;
            }
        }
    }
}

// ---------------------------------------------------------------------------
// Reduce split-K partials
// ---------------------------------------------------------------------------
__global__ void reduce_kernel(float* __restrict__ dst, const float* __restrict__ part,
                              const float* __restrict__ bias, int biasMode,
                              int N, int MN, int G, int total4, int cvtOut)
{
    int e = blockIdx.x*256 + threadIdx.x;
    if (e >= total4) return;
    int MN4 = MN >> 2;
    int b = e / MN4, i4 = e - b*MN4;
    int i = i4 << 2;
    float4 s;
    if (biasMode == 1) {
        s = *(const float4*)&bias[i % N];
    } else if (biasMode == 2) {
        float bv = bias[i / N];
        s = make_float4(bv, bv, bv, bv);
    } else {
        s = make_float4(0.f,0.f,0.f,0.f);
    }
#pragma unroll 4
    for (int g = 0; g < G; g++) {
        float4 p = *(const float4*)&part[((long long)(b*G+g))*MN + i];
        s.x += p.x; s.y += p.y; s.z += p.z; s.w += p.w;
    }
    if (cvtOut) {
        s.x = tf32r(s.x); s.y = tf32r(s.y); s.z = tf32r(s.z); s.w = tf32r(s.w);
    }
    *(float4*)&dst[(long long)b*MN + i] = s;
}

// ---------------------------------------------------------------------------
// Flash attention, tf32 mma.sync, fixed-max softmax + split-group pipelining.
// Commit stream: Q | K0 | V0 | K1 | V1 | ...  -> wait_group 1 alternation.
// smem: Qb[128][68] | Kb[64][76] | Vb[64][72] | Pb[128][68]
// ---------------------------------------------------------------------------
#define AQ_LD 68
#define AK_LD 76
#define AVS_LD 72
#define AP_LD 68
#define ASM_Q 0
#define ASM_K (128*AQ_LD)
#define ASM_V (ASM_K + 64*AK_LD)
#define ASM_P (ASM_V + 64*AVS_LD)
#define ASM_TOT (ASM_P + 128*AP_LD)   // 26880 u32 = 107520 bytes

__global__ __launch_bounds__(256, 2)
void attn_kernel()
{
    extern __shared__ u32 smu[];
    u32* Qb = smu + ASM_Q;   // [row][feat] ld 68
    u32* Kb = smu + ASM_K;   // [key][feat] ld 76
    u32* Vb = smu + ASM_V;   // [key][feat] ld 72
    u32* Pb = smu + ASM_P;   // [row][key]  ld 68

    int tid  = threadIdx.x;
    int warp = tid >> 5;
    int lane = tid & 31;
    int g = lane >> 2;
    int t = lane & 3;
    int q0 = blockIdx.x * 128;
    int h  = blockIdx.y;
    int b  = blockIdx.z;
    int r0 = warp*16 + g;
    int r1 = r0 + 8;

    // Prologue: Q group, K(0) group, V(0) group
#pragma unroll
    for (int l = 0; l < 8; l++) {
        int lin = tid + l*256;
        int row = lin >> 4;
        int c4  = (lin & 15) << 2;
        cpasync16(&Qb[row*AQ_LD + c4],
                  &g_qkv[((long long)(b*Sc + q0 + row))*(3*Dc) + h*HDc + c4], 16);
    }
    CP_COMMIT;
#pragma unroll
    for (int l = 0; l < 4; l++) {
        int lin = tid + l*256;
        int tr = lin >> 4;
        int c4 = (lin & 15) << 2;
        cpasync16(&Kb[tr*AK_LD + c4],
                  &g_qkv[((long long)(b*Sc + tr))*(3*Dc) + Dc + h*HDc + c4], 16);
    }
    CP_COMMIT;
#pragma unroll
    for (int l = 0; l < 4; l++) {
        int lin = tid + l*256;
        int tr = lin >> 4;
        int c4 = (lin & 15) << 2;
        cpasync16(&Vb[tr*AVS_LD + c4],
                  &g_qkv[((long long)(b*Sc + tr))*(3*Dc) + 2*Dc + h*HDc + c4], 16);
    }
    CP_COMMIT;

    float o[8][4];
#pragma unroll
    for (int n = 0; n < 8; n++)
#pragma unroll
        for (int j = 0; j < 4; j++) o[n][j] = 0.f;
    float lp0 = 0.f, lp1 = 0.f;   // per-thread partial row sums

    for (int t0 = 0; t0 < Sc; t0 += 64) {
        CP_WAIT1;          // K(t) [and Q on iter 0] arrived; V(t) may be in flight
        __syncthreads();

        // --- QK^T ---
        float sacc[8][4];
#pragma unroll
        for (int n = 0; n < 8; n++)
#pragma unroll
            for (int j = 0; j < 4; j++) sacc[n][j] = 0.f;

#pragma unroll
        for (int kc = 0; kc < 8; kc++) {
            int k0 = kc*8;
            u32 a[4];
            a[0] = Qb[r0*AQ_LD + k0 + t];
            a[1] = Qb[r1*AQ_LD + k0 + t];
            a[2] = Qb[r0*AQ_LD + k0 + t + 4];
            a[3] = Qb[r1*AQ_LD + k0 + t + 4];
#pragma unroll
            for (int n = 0; n < 8; n++) {
                u32 b0 = Kb[(n*8 + g)*AK_LD + k0 + t];
                u32 b1 = Kb[(n*8 + g)*AK_LD + k0 + t + 4];
                mma_tf32(sacc[n], a, b0, b1);
            }
        }

        __syncthreads();   // Kb fully consumed by all warps

        // Prefetch K(t+1) into the freed Kb
        if (t0 + 64 < Sc) {
#pragma unroll
            for (int l = 0; l < 4; l++) {
                int lin = tid + l*256;
                int tr = lin >> 4;
                int c4 = (lin & 15) << 2;
                cpasync16(&Kb[tr*AK_LD + c4],
                          &g_qkv[((long long)(b*Sc + t0 + 64 + tr))*(3*Dc) + Dc + h*HDc + c4], 16);
            }
        }
        CP_COMMIT;         // (empty group on last iter keeps accounting uniform)

        // --- Fixed-max softmax: P = exp(S); accumulate per-thread l ---
#pragma unroll
        for (int n = 0; n < 8; n++) {
            sacc[n][0] = tf32r(__expf(sacc[n][0]));
            sacc[n][1] = tf32r(__expf(sacc[n][1]));
            sacc[n][2] = tf32r(__expf(sacc[n][2]));
            sacc[n][3] = tf32r(__expf(sacc[n][3]));
            lp0 += sacc[n][0] + sacc[n][1];
            lp1 += sacc[n][2] + sacc[n][3];
        }

        // Store P (raw tf32 bits) [row][key]
#pragma unroll
        for (int n = 0; n < 8; n++) {
            uint2 p0, p1;
            p0.x = __float_as_uint(sacc[n][0]); p0.y = __float_as_uint(sacc[n][1]);
            p1.x = __float_as_uint(sacc[n][2]); p1.y = __float_as_uint(sacc[n][3]);
            *(uint2*)&Pb[r0*AP_LD + n*8 + 2*t] = p0;
            *(uint2*)&Pb[r1*AP_LD + n*8 + 2*t] = p1;
        }
        __syncwarp();

        CP_WAIT1;          // V(t) arrived; K(t+1) may be in flight

        // --- AV ---
#pragma unroll
        for (int kc = 0; kc < 8; kc++) {
            int k0 = kc*8;
            u32 a[4];
            a[0] = Pb[r0*AP_LD + k0 + t];
            a[1] = Pb[r1*AP_LD + k0 + t];
            a[2] = Pb[r0*AP_LD + k0 + t + 4];
            a[3] = Pb[r1*AP_LD + k0 + t + 4];
#pragma unroll
            for (int n = 0; n < 8; n++) {
                u32 b0 = Vb[(k0 + t    )*AVS_LD + n*8 + g];
                u32 b1 = Vb[(k0 + t + 4)*AVS_LD + n*8 + g];
                mma_tf32(o[n], a, b0, b1);
            }
        }

        __syncthreads();   // Vb fully consumed

        // Prefetch V(t+1)
        if (t0 + 64 < Sc) {
#pragma unroll
            for (int l = 0; l < 4; l++) {
                int lin = tid + l*256;
                int tr = lin >> 4;
                int c4 = (lin & 15) << 2;
                cpasync16(&Vb[tr*AVS_LD + c4],
                          &g_qkv[((long long)(b*Sc + t0 + 64 + tr))*(3*Dc) + 2*Dc + h*HDc + c4], 16);
            }
        }
        CP_COMMIT;
    }

    // Epilogue: reduce l across the 4 lanes of each row group, normalize
    float lr0 = lp0, lr1 = lp1;
    lr0 += __shfl_xor_sync(0xffffffffu, lr0, 1);
    lr0 += __shfl_xor_sync(0xffffffffu, lr0, 2);
    lr1 += __shfl_xor_sync(0xffffffffu, lr1, 1);
    lr1 += __shfl_xor_sync(0xffffffffu, lr1, 2);
    float inv0 = 1.0f / lr0;
    float inv1 = 1.0f / lr1;
    int srow0 = q0 + r0;
    int srow1 = q0 + r1;
#pragma unroll
    for (int n = 0; n < 8; n++) {
        float2 w0, w1;
        w0.x = tf32r(o[n][0]*inv0); w0.y = tf32r(o[n][1]*inv0);
        w1.x = tf32r(o[n][2]*inv1); w1.y = tf32r(o[n][3]*inv1);
        *(float2*)&g_comb[((long long)(b*Sc + srow0))*Dc + h*HDc + n*8 + 2*t] = w0;
        *(float2*)&g_comb[((long long)(b*Sc + srow1))*Dc + h*HDc + n*8 + 2*t] = w1;
    }
}

// ---------------------------------------------------------------------------
// Launch
// ---------------------------------------------------------------------------
extern "C" void kernel_launch(void* const* d_in, const int* in_sizes, int n_in,
                              void* d_out, int out_size)
{
    const float* inputs = (const float*)d_in[0];
    const float* Wq = (const float*)d_in[1];
    const float* bq = (const float*)d_in[2];
    const float* Wk = (const float*)d_in[3];
    const float* bk = (const float*)d_in[4];
    const float* Wv = (const float*)d_in[5];
    const float* bv = (const float*)d_in[6];
    const float* Wt = (const float*)d_in[7];
    const float* bt = (const float*)d_in[8];
    const float* Wo = (const float*)d_in[9];
    const float* bo = (const float*)d_in[10];
    float* out = (float*)d_out;

    float *p_qkv, *p_comb, *p_up, *p_part, *p_wcat, *p_bcat, *p_woT, *p_wt, *p_in;
    cudaGetSymbolAddress((void**)&p_qkv,  g_qkv);
    cudaGetSymbolAddress((void**)&p_comb, g_comb);
    cudaGetSymbolAddress((void**)&p_up,   g_up);
    cudaGetSymbolAddress((void**)&p_part, g_part);
    cudaGetSymbolAddress((void**)&p_wcat, g_wcat);
    cudaGetSymbolAddress((void**)&p_bcat, g_bcat);
    cudaGetSymbolAddress((void**)&p_woT,  g_woT);
    cudaGetSymbolAddress((void**)&p_wt,   g_wt);
    cudaGetSymbolAddress((void**)&p_in,   g_in);
    (void)in_sizes; (void)n_in; (void)out_size;

    const int attn_smem = ASM_TOT * (int)sizeof(u32);   // 107520 B
    cudaFuncSetAttribute(attn_kernel, cudaFuncAttributeMaxDynamicSharedMemorySize, attn_smem);

    // 1. Pack + pre-round weights & inputs
    {
        int total = Ic*3*Dc + Dc*Ic + Pc*Sc + Bc*Sc*Ic + 3*Dc;
        pack_kernel<<<(total + 255)/256, 256>>>(inputs, Wq, bq, Wk, bk, Wv, bv, Wt, Wo);
    }

    // 2. QKV GEMM: g_in[8192,512] x wcat[512,1536] -> g_qkv (tf32 out, Q scaled)
    {
        dim3 grid(3*Dc/128, (Bc*Sc)/128, 1);
        tgemm_kernel<<<grid, 256>>>(p_in, Ic, 0,
                                    p_wcat, 3*Dc, 0,
                                    p_qkv, 3*Dc, 0,
                                    Bc*Sc, 3*Dc, Ic, p_bcat, 1, 1, /*outMode=*/2);
    }

    // 3. Attention -> g_comb (tf32 out)
    attn_kernel<<<dim3(Sc/128, Hc, Bc), 256, attn_smem>>>();

    // 4. Temporal GEMM, split-K x4
    {
        dim3 grid(Dc/128, (Pc + 127)/128, Bc*4);
        tgemm_kernel<<<grid, 256>>>(p_wt, Sc, 0,
                                    p_comb, Dc, (long long)Sc*Dc,
                                    p_part, Dc, (long long)Pc*Dc,
                                    Pc, Dc, Sc/4, (const float*)0, 0, 4, /*outMode=*/0);
        int MN = Pc*Dc;
        int total4 = Bc*MN/4;
        reduce_kernel<<<(total4 + 255)/256, 256>>>(p_up, p_part, bt, 2, Dc, MN, 4, total4, /*cvtOut=*/1);
    }

    // 5. Output GEMM, split-K x2
    {
        dim3 grid(Ic/128, (Bc*Pc + 127)/128, 2);
        tgemm_kernel<<<grid, 256>>>(p_up, Dc, 0,
                                    p_woT, Ic, 0,
                                    p_part, Ic, (long long)(Bc*Pc)*Ic,
                                    Bc*Pc, Ic, Dc/2, (const float*)0, 0, 2, /*outMode=*/0);
        int MN = Bc*Pc*Ic;
        int total4 = MN/4;
        reduce_kernel<<<(total4 + 255)/256, 256>>>(out, p_part, bo, 1, Ic, MN, 2, total4, /*cvtOut=*/0);
    }
}

// round 11
// speedup vs baseline: 6.9413x; 1.7041x over previous
#include <cuda_runtime.h>
#include <cuda_fp16.h>
#include <math.h>

// Problem constants
#define Bc 4
#define Sc 2048
#define Ic 512
#define Dc 512
#define Hc 8
#define HDc 64
#define Pc 720

typedef unsigned long long u64;
typedef unsigned int u32;

// fp16 mma m16n8k16, f32 accum
__device__ __forceinline__ void mma_f16(float d[4], const u32 a[4], u32 b0, u32 b1) {
    asm volatile(
        "mma.sync.aligned.m16n8k16.row.col.f32.f16.f16.f32 "
        "{%0,%1,%2,%3}, {%4,%5,%6,%7}, {%8,%9}, {%0,%1,%2,%3};\n"
        : "+f"(d[0]), "+f"(d[1]), "+f"(d[2]), "+f"(d[3])
        : "r"(a[0]), "r"(a[1]), "r"(a[2]), "r"(a[3]), "r"(b0), "r"(b1));
}

// ldmatrix x4 transpose (b16): 4 matrices -> 4 regs
__device__ __forceinline__ void ldm_x4_trans(u32 b[4], const void* p) {
    u32 addr = (u32)__cvta_generic_to_shared(p);
    asm volatile("ldmatrix.sync.aligned.m8n8.x4.trans.shared.b16 {%0,%1,%2,%3}, [%4];"
        : "=r"(b[0]), "=r"(b[1]), "=r"(b[2]), "=r"(b[3]) : "r"(addr));
}

// cp.async helpers
__device__ __forceinline__ void cpasync16(void* smem_ptr, const void* gptr, int sz) {
    u32 sa = (u32)__cvta_generic_to_shared(smem_ptr);
    asm volatile("cp.async.cg.shared.global [%0], [%1], 16, %2;"
                 :: "r"(sa), "l"(gptr), "r"(sz));
}
#define CP_COMMIT asm volatile("cp.async.commit_group;")
#define CP_WAIT0  asm volatile("cp.async.wait_group 0;")
#define CP_WAIT1  asm volatile("cp.async.wait_group 1;")

// Scratch (device globals — no allocation allowed)
__device__ __half g_qkv[Bc*Sc*3*Dc];     // [b,s, q|k|v] fp16 (q pre-scaled 1/64)
__device__ __half g_comb[Bc*Sc*Dc];      // [b,s,d] fp16
__device__ __half g_up [Bc*Pc*Dc];       // [b,p,d] fp16
__device__ float  g_part[16*Pc*Dc];      // split-K partials (fp32)
__device__ __half g_wcat[Ic*3*Dc];
__device__ float  g_bcat[3*Dc];
__device__ __half g_woT[Dc*Ic];
__device__ __half g_wt [Pc*Sc];
__device__ __half g_in [Bc*Sc*Ic];

// ---------------------------------------------------------------------------
// Pack + convert weights/inputs to fp16
// ---------------------------------------------------------------------------
__global__ void pack_kernel(const float* __restrict__ inputs,
                            const float* __restrict__ Wq, const float* __restrict__ bq,
                            const float* __restrict__ Wk, const float* __restrict__ bk,
                            const float* __restrict__ Wv, const float* __restrict__ bv,
                            const float* __restrict__ Wt, const float* __restrict__ Wo)
{
    const int NW  = Ic*3*Dc;
    const int NWO = Dc*Ic;
    const int NWT = Pc*Sc;
    const int NIN = Bc*Sc*Ic;
    int gid = blockIdx.x*blockDim.x + threadIdx.x;
    if (gid < NW) {
        int i = gid / (3*Dc);
        int n = gid % (3*Dc);
        int sec = n / Dc;
        int nn  = n % Dc;
        const float* W = (sec==0) ? Wq : (sec==1) ? Wk : Wv;
        int h = nn / HDc, d = nn % HDc;
        g_wcat[gid] = __float2half_rn(W[(h*Ic + i)*HDc + d]);
    } else if (gid < NW + NWO) {
        int t = gid - NW;
        int d = t / Ic, o = t % Ic;
        g_woT[t] = __float2half_rn(Wo[o*Dc + d]);
    } else if (gid < NW + NWO + NWT) {
        int t = gid - NW - NWO;
        g_wt[t] = __float2half_rn(Wt[t]);
    } else if (gid < NW + NWO + NWT + NIN) {
        int t = gid - NW - NWO - NWT;
        g_in[t] = __float2half_rn(inputs[t]);
    } else if (gid < NW + NWO + NWT + NIN + 3*Dc) {
        int n = gid - NW - NWO - NWT - NIN;
        int sec = n / Dc, nn = n % Dc;
        const float* bv_ = (sec==0) ? bq : (sec==1) ? bk : bv;
        g_bcat[n] = bv_[nn];
    }
}

// ---------------------------------------------------------------------------
// fp16 tensor GEMM, cp.async 2-stage pipeline. C[M,N] = A[M,K] x B[K,N].
// 128x128 tile, BK=16, 8 warps (2x4), each 64x32 via m16n8k16.
// A smem [m][k] ld 24 halves (scalar frag loads); B smem [k][n] ld 136
// (ldmatrix.x4.trans). outMode: 0 f32 out; 1 fp16 out; 2 fp16 out w/ cols<Dc
// scaled 1/64. biasMode: 0/1 per-col/2 per-row. blockIdx.z = bz*nsplit + kc.
// ---------------------------------------------------------------------------
#define TA_LDH 24
#define TB_LDH 136
__global__ __launch_bounds__(256)
void tgemm_kernel(const __half* __restrict__ A, int lda, long long strideA,
                  const __half* __restrict__ Bm, int ldb, long long strideB,
                  void* __restrict__ Cv, int ldc, long long strideC,
                  int M, int N, int K,
                  const float* __restrict__ bias, int biasMode, int nsplit,
                  int outMode)
{
    int bz  = blockIdx.z / nsplit;
    int kcs = blockIdx.z % nsplit;
    A  += (long long)bz * strideA + (long long)kcs * K;
    Bm += (long long)bz * strideB + (long long)kcs * K * ldb;

    __shared__ __half As[2][128*TA_LDH];
    __shared__ __half Bs[2][16*TB_LDH];

    int tid  = threadIdx.x;
    int warp = tid >> 5;
    int lane = tid & 31;
    int g = lane >> 2;
    int t = lane & 3;
    int wm = warp >> 2;
    int wn = warp & 3;
    int m0 = blockIdx.y * 128;
    int n0 = blockIdx.x * 128;

    int arow = tid >> 1, aseg = tid & 1;     // A: 128 rows x 2 chunks(16B)
    int brow = tid >> 4, bseg = tid & 15;    // B: 16 rows x 16 chunks

    float acc[4][4][4];
#pragma unroll
    for (int mt = 0; mt < 4; mt++)
#pragma unroll
        for (int nt = 0; nt < 4; nt++)
#pragma unroll
            for (int j = 0; j < 4; j++) acc[mt][nt][j] = 0.f;

    int nIter = K >> 4;

    {
        int gm = m0 + arow; int sz = (gm < M) ? 16 : 0; if (gm >= M) gm = M-1;
        cpasync16(&As[0][arow*TA_LDH + aseg*8], &A[(long long)gm*lda + aseg*8], sz);
        cpasync16(&Bs[0][brow*TB_LDH + bseg*8], &Bm[(long long)brow*ldb + n0 + bseg*8], 16);
        CP_COMMIT;
    }

    for (int it = 0; it < nIter; it++) {
        int cur = it & 1;
        if (it + 1 < nIter) {
            int k0 = (it+1) << 4;
            int nx = cur ^ 1;
            int gm = m0 + arow; int sz = (gm < M) ? 16 : 0; if (gm >= M) gm = M-1;
            cpasync16(&As[nx][arow*TA_LDH + aseg*8], &A[(long long)gm*lda + k0 + aseg*8], sz);
            cpasync16(&Bs[nx][brow*TB_LDH + bseg*8], &Bm[(long long)(k0+brow)*ldb + n0 + bseg*8], 16);
            CP_COMMIT;
            CP_WAIT1;
        } else {
            CP_WAIT0;
        }
        __syncthreads();

        const u32* AsU = (const u32*)As[cur];
        u32 a[4][4];
#pragma unroll
        for (int mt = 0; mt < 4; mt++) {
            int mb = wm*64 + mt*16;
            a[mt][0] = AsU[(mb + g    )*(TA_LDH/2) + t];
            a[mt][1] = AsU[(mb + g + 8)*(TA_LDH/2) + t];
            a[mt][2] = AsU[(mb + g    )*(TA_LDH/2) + t + 4];
            a[mt][3] = AsU[(mb + g + 8)*(TA_LDH/2) + t + 4];
        }
        u32 bq[2][4];
#pragma unroll
        for (int np = 0; np < 2; np++) {
            int ntA = np*2 + (lane >> 4);
            ldm_x4_trans(bq[np], &Bs[cur][(lane & 15)*TB_LDH + wn*32 + ntA*8]);
        }
#pragma unroll
        for (int nt = 0; nt < 4; nt++) {
            u32 b0 = bq[nt >> 1][(nt & 1)*2];
            u32 b1 = bq[nt >> 1][(nt & 1)*2 + 1];
#pragma unroll
            for (int mt = 0; mt < 4; mt++)
                mma_f16(acc[mt][nt], a[mt], b0, b1);
        }
        __syncthreads();
    }

    // Epilogue
#pragma unroll
    for (int mt = 0; mt < 4; mt++) {
#pragma unroll
        for (int hrow = 0; hrow < 2; hrow++) {
            int m = m0 + wm*64 + mt*16 + g + hrow*8;
            if (m >= M) continue;
            float brow_ = (biasMode == 2) ? bias[m] : 0.f;
#pragma unroll
            for (int nt = 0; nt < 4; nt++) {
                int c = n0 + wn*32 + nt*8 + 2*t;
                float wx = acc[mt][nt][hrow*2 + 0] + brow_;
                float wy = acc[mt][nt][hrow*2 + 1] + brow_;
                if (biasMode == 1) { wx += bias[c]; wy += bias[c+1]; }
                if (outMode == 0) {
                    float* C = (float*)Cv + blockIdx.z * strideC;
                    float2 w; w.x = wx; w.y = wy;
                    *(float2*)&C[(long long)m*ldc + c] = w;
                } else {
                    if (outMode == 2 && c < Dc) {
                        wx *= (1.0f/(float)HDc);
                        wy *= (1.0f/(float)HDc);
                    }
                    __half2 hh = __halves2half2(__float2half_rn(wx), __float2half_rn(wy));
                    u32* C = (u32*)Cv + (blockIdx.z * strideC >> 1);
                    C[(long long)m*(ldc>>1) + (c>>1)] = *(u32*)&hh;
                }
            }
        }
    }
}

// ---------------------------------------------------------------------------
// Reduce split-K partials. outKind: 0 f32 dst, 1 fp16 dst.
// ---------------------------------------------------------------------------
__global__ void reduce_kernel(void* __restrict__ dstv, const float* __restrict__ part,
                              const float* __restrict__ bias, int biasMode,
                              int N, int MN, int G, int total4, int outKind)
{
    int e = blockIdx.x*256 + threadIdx.x;
    if (e >= total4) return;
    int MN4 = MN >> 2;
    int b = e / MN4, i4 = e - b*MN4;
    int i = i4 << 2;
    float4 s;
    if (biasMode == 1) {
        s = *(const float4*)&bias[i % N];
    } else if (biasMode == 2) {
        float bv = bias[i / N];
        s = make_float4(bv, bv, bv, bv);
    } else {
        s = make_float4(0.f,0.f,0.f,0.f);
    }
#pragma unroll 4
    for (int g = 0; g < G; g++) {
        float4 p = *(const float4*)&part[((long long)(b*G+g))*MN + i];
        s.x += p.x; s.y += p.y; s.z += p.z; s.w += p.w;
    }
    if (outKind == 1) {
        __half2 h01 = __halves2half2(__float2half_rn(s.x), __float2half_rn(s.y));
        __half2 h23 = __halves2half2(__float2half_rn(s.z), __float2half_rn(s.w));
        u32* d = (u32*)dstv + (((long long)b*MN + i) >> 1);
        d[0] = *(u32*)&h01;
        d[1] = *(u32*)&h23;
    } else {
        *(float4*)&((float*)dstv)[(long long)b*MN + i] = s;
    }
}

// ---------------------------------------------------------------------------
// Flash attention, fp16 m16n8k16, fixed-max softmax, split-group pipelining.
// smem (halves, all ld 72): Qb[128] | Kb[64] | Vb[64] | Pb[128]
// ---------------------------------------------------------------------------
#define AT_LDH 72
#define AT_LD2 36
#define ASM_Q 0
#define ASM_K (128*AT_LDH)
#define ASM_V (ASM_K + 64*AT_LDH)
#define ASM_P (ASM_V + 64*AT_LDH)
#define ASM_TOT (ASM_P + 128*AT_LDH)   // 27648 halves = 55296 bytes

__global__ __launch_bounds__(256, 2)
void attn_kernel()
{
    extern __shared__ __half smh[];
    __half* Qb = smh + ASM_Q;   // [row][feat]
    __half* Kb = smh + ASM_K;   // [key][feat]
    __half* Vb = smh + ASM_V;   // [key][feat]
    __half* Pb = smh + ASM_P;   // [row][key]
    u32* Qb2 = (u32*)Qb;
    u32* Kb2 = (u32*)Kb;
    u32* Pb2 = (u32*)Pb;

    int tid  = threadIdx.x;
    int warp = tid >> 5;
    int lane = tid & 31;
    int g = lane >> 2;
    int t = lane & 3;
    int q0 = blockIdx.x * 128;
    int h  = blockIdx.y;
    int b  = blockIdx.z;
    int r0 = warp*16 + g;
    int r1 = r0 + 8;

    // Prologue: Q (group), K0 (group), V0 (group)
#pragma unroll
    for (int l = 0; l < 4; l++) {
        int lin = tid + l*256;
        int row = lin >> 3;          // 0..127
        int seg = lin & 7;           // 8 halves each
        cpasync16(&Qb[row*AT_LDH + seg*8],
                  &g_qkv[((long long)(b*Sc + q0 + row))*(3*Dc) + h*HDc + seg*8], 16);
    }
    CP_COMMIT;
#pragma unroll
    for (int l = 0; l < 2; l++) {
        int lin = tid + l*256;
        int row = lin >> 3;          // 0..63
        int seg = lin & 7;
        cpasync16(&Kb[row*AT_LDH + seg*8],
                  &g_qkv[((long long)(b*Sc + row))*(3*Dc) + Dc + h*HDc + seg*8], 16);
    }
    CP_COMMIT;
#pragma unroll
    for (int l = 0; l < 2; l++) {
        int lin = tid + l*256;
        int row = lin >> 3;
        int seg = lin & 7;
        cpasync16(&Vb[row*AT_LDH + seg*8],
                  &g_qkv[((long long)(b*Sc + row))*(3*Dc) + 2*Dc + h*HDc + seg*8], 16);
    }
    CP_COMMIT;

    float o[8][4];
#pragma unroll
    for (int n = 0; n < 8; n++)
#pragma unroll
        for (int j = 0; j < 4; j++) o[n][j] = 0.f;
    float lp0 = 0.f, lp1 = 0.f;

    for (int t0 = 0; t0 < Sc; t0 += 64) {
        CP_WAIT1;          // K(t) [and Q first time] done for this thread
        __syncthreads();   // ... and for all threads

        // --- QK^T: 4 k16 chunks over 64 feats ---
        float sacc[8][4];
#pragma unroll
        for (int n = 0; n < 8; n++)
#pragma unroll
            for (int j = 0; j < 4; j++) sacc[n][j] = 0.f;

#pragma unroll
        for (int kc = 0; kc < 4; kc++) {
            int kb = kc*8;   // h2 offset
            u32 a[4];
            a[0] = Qb2[r0*AT_LD2 + kb + t];
            a[1] = Qb2[r1*AT_LD2 + kb + t];
            a[2] = Qb2[r0*AT_LD2 + kb + t + 4];
            a[3] = Qb2[r1*AT_LD2 + kb + t + 4];
#pragma unroll
            for (int n = 0; n < 8; n++) {
                u32 b0 = Kb2[(n*8 + g)*AT_LD2 + kb + t];
                u32 b1 = Kb2[(n*8 + g)*AT_LD2 + kb + t + 4];
                mma_f16(sacc[n], a, b0, b1);
            }
        }

        __syncthreads();   // Kb fully consumed

        // Prefetch K(t+1)
        if (t0 + 64 < Sc) {
#pragma unroll
            for (int l = 0; l < 2; l++) {
                int lin = tid + l*256;
                int row = lin >> 3;
                int seg = lin & 7;
                cpasync16(&Kb[row*AT_LDH + seg*8],
                          &g_qkv[((long long)(b*Sc + t0 + 64 + row))*(3*Dc) + Dc + h*HDc + seg*8], 16);
            }
        }
        CP_COMMIT;

        // --- Fixed-max softmax: P = exp(S), fp16-rounded before l-sum ---
#pragma unroll
        for (int n = 0; n < 8; n++) {
            __half h0 = __float2half_rn(__expf(sacc[n][0]));
            __half h1 = __float2half_rn(__expf(sacc[n][1]));
            __half h2 = __float2half_rn(__expf(sacc[n][2]));
            __half h3 = __float2half_rn(__expf(sacc[n][3]));
            lp0 += __half2float(h0) + __half2float(h1);
            lp1 += __half2float(h2) + __half2float(h3);
            __half2 p0 = __halves2half2(h0, h1);
            __half2 p1 = __halves2half2(h2, h3);
            Pb2[r0*AT_LD2 + n*4 + t] = *(u32*)&p0;
            Pb2[r1*AT_LD2 + n*4 + t] = *(u32*)&p1;
        }
        __syncwarp();      // P is warp-private

        CP_WAIT1;          // V(t) done for this thread
        __syncthreads();   // ... and for all threads (publishes V copies)

        // --- AV: 4 k16 chunks over 64 keys; V B-frags via ldmatrix.trans ---
#pragma unroll
        for (int kc = 0; kc < 4; kc++) {
            int kr = kc*16;
            u32 a[4];
            a[0] = Pb2[r0*AT_LD2 + kc*8 + t];
            a[1] = Pb2[r1*AT_LD2 + kc*8 + t];
            a[2] = Pb2[r0*AT_LD2 + kc*8 + t + 4];
            a[3] = Pb2[r1*AT_LD2 + kc*8 + t + 4];
#pragma unroll
            for (int np = 0; np < 4; np++) {
                int ntA = np*2 + (lane >> 4);
                u32 bq[4];
                ldm_x4_trans(bq, &Vb[(kr + (lane & 15))*AT_LDH + ntA*8]);
                mma_f16(o[np*2],     a, bq[0], bq[1]);
                mma_f16(o[np*2 + 1], a, bq[2], bq[3]);
            }
        }

        __syncthreads();   // Vb fully consumed

        // Prefetch V(t+1)
        if (t0 + 64 < Sc) {
#pragma unroll
            for (int l = 0; l < 2; l++) {
                int lin = tid + l*256;
                int row = lin >> 3;
                int seg = lin & 7;
                cpasync16(&Vb[row*AT_LDH + seg*8],
                          &g_qkv[((long long)(b*Sc + t0 + 64 + row))*(3*Dc) + 2*Dc + h*HDc + seg*8], 16);
            }
        }
        CP_COMMIT;
    }

    // Epilogue: reduce l over quad lanes, normalize, write fp16 comb
    float lr0 = lp0, lr1 = lp1;
    lr0 += __shfl_xor_sync(0xffffffffu, lr0, 1);
    lr0 += __shfl_xor_sync(0xffffffffu, lr0, 2);
    lr1 += __shfl_xor_sync(0xffffffffu, lr1, 1);
    lr1 += __shfl_xor_sync(0xffffffffu, lr1, 2);
    float inv0 = 1.0f / lr0;
    float inv1 = 1.0f / lr1;
    int srow0 = q0 + r0;
    int srow1 = q0 + r1;
    u32* comb2 = (u32*)g_comb;
#pragma unroll
    for (int n = 0; n < 8; n++) {
        __half2 w0 = __halves2half2(__float2half_rn(o[n][0]*inv0), __float2half_rn(o[n][1]*inv0));
        __half2 w1 = __halves2half2(__float2half_rn(o[n][2]*inv1), __float2half_rn(o[n][3]*inv1));
        comb2[((long long)(b*Sc + srow0))*(Dc/2) + h*(HDc/2) + n*4 + t] = *(u32*)&w0;
        comb2[((long long)(b*Sc + srow1))*(Dc/2) + h*(HDc/2) + n*4 + t] = *(u32*)&w1;
    }
}

// ---------------------------------------------------------------------------
// Launch
// ---------------------------------------------------------------------------
extern "C" void kernel_launch(void* const* d_in, const int* in_sizes, int n_in,
                              void* d_out, int out_size)
{
    const float* inputs = (const float*)d_in[0];
    const float* Wq = (const float*)d_in[1];
    const float* bq = (const float*)d_in[2];
    const float* Wk = (const float*)d_in[3];
    const float* bk = (const float*)d_in[4];
    const float* Wv = (const float*)d_in[5];
    const float* bv = (const float*)d_in[6];
    const float* Wt = (const float*)d_in[7];
    const float* bt = (const float*)d_in[8];
    const float* Wo = (const float*)d_in[9];
    const float* bo = (const float*)d_in[10];
    float* out = (float*)d_out;

    __half *p_qkv, *p_comb, *p_up, *p_wcat, *p_woT, *p_wt, *p_in;
    float *p_part, *p_bcat;
    cudaGetSymbolAddress((void**)&p_qkv,  g_qkv);
    cudaGetSymbolAddress((void**)&p_comb, g_comb);
    cudaGetSymbolAddress((void**)&p_up,   g_up);
    cudaGetSymbolAddress((void**)&p_part, g_part);
    cudaGetSymbolAddress((void**)&p_wcat, g_wcat);
    cudaGetSymbolAddress((void**)&p_bcat, g_bcat);
    cudaGetSymbolAddress((void**)&p_woT,  g_woT);
    cudaGetSymbolAddress((void**)&p_wt,   g_wt);
    cudaGetSymbolAddress((void**)&p_in,   g_in);
    (void)in_sizes; (void)n_in; (void)out_size;

    const int attn_smem = ASM_TOT * (int)sizeof(__half);   // 55296 B
    cudaFuncSetAttribute(attn_kernel, cudaFuncAttributeMaxDynamicSharedMemorySize, attn_smem);

    // 1. Pack + convert to fp16
    {
        int total = Ic*3*Dc + Dc*Ic + Pc*Sc + Bc*Sc*Ic + 3*Dc;
        pack_kernel<<<(total + 255)/256, 256>>>(inputs, Wq, bq, Wk, bk, Wv, bv, Wt, Wo);
    }

    // 2. QKV GEMM: g_in[8192,512] x wcat[512,1536] -> g_qkv fp16 (Q scaled)
    {
        dim3 grid(3*Dc/128, (Bc*Sc)/128, 1);
        tgemm_kernel<<<grid, 256>>>(p_in, Ic, 0,
                                    p_wcat, 3*Dc, 0,
                                    p_qkv, 3*Dc, 0,
                                    Bc*Sc, 3*Dc, Ic, p_bcat, 1, 1, /*outMode=*/2);
    }

    // 3. Attention -> g_comb fp16
    attn_kernel<<<dim3(Sc/128, Hc, Bc), 256, attn_smem>>>();

    // 4. Temporal GEMM, split-K x4: g_wt[720,2048] x comb_b[2048,512] -> partials
    {
        dim3 grid(Dc/128, (Pc + 127)/128, Bc*4);
        tgemm_kernel<<<grid, 256>>>(p_wt, Sc, 0,
                                    p_comb, Dc, (long long)Sc*Dc,
                                    p_part, Dc, (long long)Pc*Dc,
                                    Pc, Dc, Sc/4, (const float*)0, 0, 4, /*outMode=*/0);
        int MN = Pc*Dc;
        int total4 = Bc*MN/4;
        reduce_kernel<<<(total4 + 255)/256, 256>>>(p_up, p_part, bt, 2, Dc, MN, 4, total4, /*outKind=*/1);
    }

    // 5. Output GEMM, split-K x2: up[2880,512] x woT[512,512] -> out f32 (+bo)
    {
        dim3 grid(Ic/128, (Bc*Pc + 127)/128, 2);
        tgemm_kernel<<<grid, 256>>>(p_up, Dc, 0,
                                    p_woT, Ic, 0,
                                    p_part, Ic, (long long)(Bc*Pc)*Ic,
                                    Bc*Pc, Ic, Dc/2, (const float*)0, 0, 2, /*outMode=*/0);
        int MN = Bc*Pc*Ic;
        int total4 = MN/4;
        reduce_kernel<<<(total4 + 255)/256, 256>>>(out, p_part, bo, 1, Ic, MN, 2, total4, /*outKind=*/0);
    }
}

// round 13
// speedup vs baseline: 7.2884x; 1.0500x over previous
#include <cuda_runtime.h>
#include <cuda_fp16.h>
#include <math.h>

// Problem constants
#define Bc 4
#define Sc 2048
#define Ic 512
#define Dc 512
#define Hc 8
#define HDc 64
#define Pc 720

typedef unsigned long long u64;
typedef unsigned int u32;

// fp16 mma m16n8k16, f32 accum
__device__ __forceinline__ void mma_f16(float d[4], const u32 a[4], u32 b0, u32 b1) {
    asm volatile(
        "mma.sync.aligned.m16n8k16.row.col.f32.f16.f16.f32 "
        "{%0,%1,%2,%3}, {%4,%5,%6,%7}, {%8,%9}, {%0,%1,%2,%3};\n"
        : "+f"(d[0]), "+f"(d[1]), "+f"(d[2]), "+f"(d[3])
        : "r"(a[0]), "r"(a[1]), "r"(a[2]), "r"(a[3]), "r"(b0), "r"(b1));
}

// ldmatrix x4 transpose (b16)
__device__ __forceinline__ void ldm_x4_trans(u32 b[4], const void* p) {
    u32 addr = (u32)__cvta_generic_to_shared(p);
    asm volatile("ldmatrix.sync.aligned.m8n8.x4.trans.shared.b16 {%0,%1,%2,%3}, [%4];"
        : "=r"(b[0]), "=r"(b[1]), "=r"(b[2]), "=r"(b[3]) : "r"(addr));
}

// cp.async helpers
__device__ __forceinline__ void cpasync16(void* smem_ptr, const void* gptr, int sz) {
    u32 sa = (u32)__cvta_generic_to_shared(smem_ptr);
    asm volatile("cp.async.cg.shared.global [%0], [%1], 16, %2;"
                 :: "r"(sa), "l"(gptr), "r"(sz));
}
#define CP_COMMIT asm volatile("cp.async.commit_group;")
#define CP_WAIT0  asm volatile("cp.async.wait_group 0;")
#define CP_WAIT1  asm volatile("cp.async.wait_group 1;")

// Scratch (device globals — no allocation allowed)
__device__ __half g_qkv[Bc*Sc*3*Dc];     // [b,s, q|k|v] fp16 (q pre-scaled 1/64)
__device__ __half g_comb[Bc*Sc*Dc];      // [b,s,d] fp16
__device__ __half g_up [Bc*Pc*Dc];       // [b,p,d] fp16
__device__ float  g_part[16*Pc*Dc];      // split-K partials (fp32)
__device__ __half g_wcat[Ic*3*Dc];
__device__ float  g_bcat[3*Dc];
__device__ __half g_woT[Dc*Ic];
__device__ __half g_wt [Pc*Sc];
__device__ __half g_in [Bc*Sc*Ic];

// ---------------------------------------------------------------------------
// Pack + convert weights/inputs to fp16
// ---------------------------------------------------------------------------
__global__ void pack_kernel(const float* __restrict__ inputs,
                            const float* __restrict__ Wq, const float* __restrict__ bq,
                            const float* __restrict__ Wk, const float* __restrict__ bk,
                            const float* __restrict__ Wv, const float* __restrict__ bv,
                            const float* __restrict__ Wt, const float* __restrict__ Wo)
{
    const int NW  = Ic*3*Dc;
    const int NWO = Dc*Ic;
    const int NWT = Pc*Sc;
    const int NIN = Bc*Sc*Ic;
    int gid = blockIdx.x*blockDim.x + threadIdx.x;
    if (gid < NW) {
        int i = gid / (3*Dc);
        int n = gid % (3*Dc);
        int sec = n / Dc;
        int nn  = n % Dc;
        const float* W = (sec==0) ? Wq : (sec==1) ? Wk : Wv;
        int h = nn / HDc, d = nn % HDc;
        g_wcat[gid] = __float2half_rn(W[(h*Ic + i)*HDc + d]);
    } else if (gid < NW + NWO) {
        int t = gid - NW;
        int d = t / Ic, o = t % Ic;
        g_woT[t] = __float2half_rn(Wo[o*Dc + d]);
    } else if (gid < NW + NWO + NWT) {
        int t = gid - NW - NWO;
        g_wt[t] = __float2half_rn(Wt[t]);
    } else if (gid < NW + NWO + NWT + NIN) {
        int t = gid - NW - NWO - NWT;
        g_in[t] = __float2half_rn(inputs[t]);
    } else if (gid < NW + NWO + NWT + NIN + 3*Dc) {
        int n = gid - NW - NWO - NWT - NIN;
        int sec = n / Dc, nn = n % Dc;
        const float* bv_ = (sec==0) ? bq : (sec==1) ? bk : bv;
        g_bcat[n] = bv_[nn];
    }
}

// ---------------------------------------------------------------------------
// fp16 tensor GEMM: BK=32, 3-stage cp.async pipeline, 1 sync/iter.
// 128x128 tile, 8 warps (2x4), each 64x32 via m16n8k16.
// A smem [m][k] ld 40 halves; B smem [k][n] ld 136 (ldmatrix.x4.trans).
// outMode: 0 f32 out; 1 fp16 out; 2 fp16 out w/ cols<Dc scaled 1/64.
// biasMode: 0/1 per-col/2 per-row. blockIdx.z = bz*nsplit + kc.
// ---------------------------------------------------------------------------
#define TG_A_LDH 40
#define TG_A_LD2 20
#define TG_B_LDH 136
#define TG_B_OFF (128*TG_A_LDH)                    // 5120 halves
#define TG_STAGE_H (TG_B_OFF + 32*TG_B_LDH)        // 5120+4352=9472 halves
#define TG_SMEM_B (3*TG_STAGE_H*2)                 // 56832 bytes

__global__ __launch_bounds__(256)
void tgemm_kernel(const __half* __restrict__ A, int lda, long long strideA,
                  const __half* __restrict__ Bm, int ldb, long long strideB,
                  void* __restrict__ Cv, int ldc, long long strideC,
                  int M, int N, int K,
                  const float* __restrict__ bias, int biasMode, int nsplit,
                  int outMode)
{
    extern __shared__ __half tgs[];

    int bz  = blockIdx.z / nsplit;
    int kcs = blockIdx.z % nsplit;
    A  += (long long)bz * strideA + (long long)kcs * K;
    Bm += (long long)bz * strideB + (long long)kcs * K * ldb;

    int tid  = threadIdx.x;
    int warp = tid >> 5;
    int lane = tid & 31;
    int g = lane >> 2;
    int t = lane & 3;
    int wm = warp >> 2;
    int wn = warp & 3;
    int m0 = blockIdx.y * 128;
    int n0 = blockIdx.x * 128;

    // per-thread copy coords (BK=32): A 512 chunks, B 512 chunks of 16B
    int ar0 = (tid) >> 2,      as0 = ((tid) & 3) << 3;      // row, half-offset
    int ar1 = (tid+256) >> 2,  as1 = ((tid+256) & 3) << 3;
    int br0 = (tid) >> 4,      bs0 = ((tid) & 15) << 3;
    int br1 = (tid+256) >> 4,  bs1 = ((tid+256) & 15) << 3;

    float acc[4][4][4];
#pragma unroll
    for (int mt = 0; mt < 4; mt++)
#pragma unroll
        for (int nt = 0; nt < 4; nt++)
#pragma unroll
            for (int j = 0; j < 4; j++) acc[mt][nt][j] = 0.f;

    int nIter = K >> 5;

#define TG_ISSUE(stage, k0)                                                          \
    {                                                                                \
        __half* As_ = tgs + (stage)*TG_STAGE_H;                                      \
        __half* Bs_ = As_ + TG_B_OFF;                                                \
        int gm0 = m0 + ar0; int sz0 = (gm0 < M) ? 16 : 0; if (gm0 >= M) gm0 = M-1;   \
        int gm1 = m0 + ar1; int sz1 = (gm1 < M) ? 16 : 0; if (gm1 >= M) gm1 = M-1;   \
        cpasync16(&As_[ar0*TG_A_LDH + as0], &A[(long long)gm0*lda + (k0) + as0], sz0); \
        cpasync16(&As_[ar1*TG_A_LDH + as1], &A[(long long)gm1*lda + (k0) + as1], sz1); \
        cpasync16(&Bs_[br0*TG_B_LDH + bs0], &Bm[(long long)((k0)+br0)*ldb + n0 + bs0], 16); \
        cpasync16(&Bs_[br1*TG_B_LDH + bs1], &Bm[(long long)((k0)+br1)*ldb + n0 + bs1], 16); \
        CP_COMMIT;                                                                   \
    }

    TG_ISSUE(0, 0);
    if (nIter > 1) TG_ISSUE(1, 32);

    for (int it = 0; it < nIter; it++) {
        if (it == nIter - 1) { CP_WAIT0; } else { CP_WAIT1; }
        __syncthreads();

        if (it + 2 < nIter) TG_ISSUE((it+2)%3, (it+2) << 5);

        int cur = it % 3;
        const u32* AsU = (const u32*)(tgs + cur*TG_STAGE_H);
        const __half* BsH = tgs + cur*TG_STAGE_H + TG_B_OFF;

#pragma unroll
        for (int kc = 0; kc < 2; kc++) {
            int kk2 = kc*8;   // u32 k offset
            u32 a[4][4];
#pragma unroll
            for (int mt = 0; mt < 4; mt++) {
                int mb = wm*64 + mt*16;
                a[mt][0] = AsU[(mb + g    )*TG_A_LD2 + kk2 + t];
                a[mt][1] = AsU[(mb + g + 8)*TG_A_LD2 + kk2 + t];
                a[mt][2] = AsU[(mb + g    )*TG_A_LD2 + kk2 + t + 4];
                a[mt][3] = AsU[(mb + g + 8)*TG_A_LD2 + kk2 + t + 4];
            }
            u32 bq[2][4];
#pragma unroll
            for (int np = 0; np < 2; np++) {
                int ntA = np*2 + (lane >> 4);
                ldm_x4_trans(bq[np], &BsH[(kc*16 + (lane & 15))*TG_B_LDH + wn*32 + ntA*8]);
            }
#pragma unroll
            for (int nt = 0; nt < 4; nt++) {
                u32 b0 = bq[nt >> 1][(nt & 1)*2];
                u32 b1 = bq[nt >> 1][(nt & 1)*2 + 1];
#pragma unroll
                for (int mt = 0; mt < 4; mt++)
                    mma_f16(acc[mt][nt], a[mt], b0, b1);
            }
        }
    }

    // Epilogue
#pragma unroll
    for (int mt = 0; mt < 4; mt++) {
#pragma unroll
        for (int hrow = 0; hrow < 2; hrow++) {
            int m = m0 + wm*64 + mt*16 + g + hrow*8;
            if (m >= M) continue;
            float brow_ = (biasMode == 2) ? bias[m] : 0.f;
#pragma unroll
            for (int nt = 0; nt < 4; nt++) {
                int c = n0 + wn*32 + nt*8 + 2*t;
                float wx = acc[mt][nt][hrow*2 + 0] + brow_;
                float wy = acc[mt][nt][hrow*2 + 1] + brow_;
                if (biasMode == 1) { wx += bias[c]; wy += bias[c+1]; }
                if (outMode == 0) {
                    float* C = (float*)Cv + blockIdx.z * strideC;
                    float2 w; w.x = wx; w.y = wy;
                    *(float2*)&C[(long long)m*ldc + c] = w;
                } else {
                    if (outMode == 2 && c < Dc) {
                        wx *= (1.0f/(float)HDc);
                        wy *= (1.0f/(float)HDc);
                    }
                    __half2 hh = __halves2half2(__float2half_rn(wx), __float2half_rn(wy));
                    u32* C = (u32*)Cv + (blockIdx.z * strideC >> 1);
                    C[(long long)m*(ldc>>1) + (c>>1)] = *(u32*)&hh;
                }
            }
        }
    }
}

// ---------------------------------------------------------------------------
// Reduce split-K partials. outKind: 0 f32 dst, 1 fp16 dst.
// ---------------------------------------------------------------------------
__global__ void reduce_kernel(void* __restrict__ dstv, const float* __restrict__ part,
                              const float* __restrict__ bias, int biasMode,
                              int N, int MN, int G, int total4, int outKind)
{
    int e = blockIdx.x*256 + threadIdx.x;
    if (e >= total4) return;
    int MN4 = MN >> 2;
    int b = e / MN4, i4 = e - b*MN4;
    int i = i4 << 2;
    float4 s;
    if (biasMode == 1) {
        s = *(const float4*)&bias[i % N];
    } else if (biasMode == 2) {
        float bv = bias[i / N];
        s = make_float4(bv, bv, bv, bv);
    } else {
        s = make_float4(0.f,0.f,0.f,0.f);
    }
#pragma unroll 4
    for (int g = 0; g < G; g++) {
        float4 p = *(const float4*)&part[((long long)(b*G+g))*MN + i];
        s.x += p.x; s.y += p.y; s.z += p.z; s.w += p.w;
    }
    if (outKind == 1) {
        __half2 h01 = __halves2half2(__float2half_rn(s.x), __float2half_rn(s.y));
        __half2 h23 = __halves2half2(__float2half_rn(s.z), __float2half_rn(s.w));
        u32* d = (u32*)dstv + (((long long)b*MN + i) >> 1);
        d[0] = *(u32*)&h01;
        d[1] = *(u32*)&h23;
    } else {
        *(float4*)&((float*)dstv)[(long long)b*MN + i] = s;
    }
}

// ---------------------------------------------------------------------------
// Flash attention, fp16 m16n8k16 (unchanged from R11)
// smem (halves, all ld 72): Qb[128] | Kb[64] | Vb[64] | Pb[128]
// ---------------------------------------------------------------------------
#define AT_LDH 72
#define AT_LD2 36
#define ASM_Q 0
#define ASM_K (128*AT_LDH)
#define ASM_V (ASM_K + 64*AT_LDH)
#define ASM_P (ASM_V + 64*AT_LDH)
#define ASM_TOT (ASM_P + 128*AT_LDH)   // 27648 halves = 55296 bytes

__global__ __launch_bounds__(256, 2)
void attn_kernel()
{
    extern __shared__ __half smh[];
    __half* Qb = smh + ASM_Q;
    __half* Kb = smh + ASM_K;
    __half* Vb = smh + ASM_V;
    __half* Pb = smh + ASM_P;
    u32* Qb2 = (u32*)Qb;
    u32* Kb2 = (u32*)Kb;
    u32* Pb2 = (u32*)Pb;

    int tid  = threadIdx.x;
    int warp = tid >> 5;
    int lane = tid & 31;
    int g = lane >> 2;
    int t = lane & 3;
    int q0 = blockIdx.x * 128;
    int h  = blockIdx.y;
    int b  = blockIdx.z;
    int r0 = warp*16 + g;
    int r1 = r0 + 8;

#pragma unroll
    for (int l = 0; l < 4; l++) {
        int lin = tid + l*256;
        int row = lin >> 3;
        int seg = lin & 7;
        cpasync16(&Qb[row*AT_LDH + seg*8],
                  &g_qkv[((long long)(b*Sc + q0 + row))*(3*Dc) + h*HDc + seg*8], 16);
    }
    CP_COMMIT;
#pragma unroll
    for (int l = 0; l < 2; l++) {
        int lin = tid + l*256;
        int row = lin >> 3;
        int seg = lin & 7;
        cpasync16(&Kb[row*AT_LDH + seg*8],
                  &g_qkv[((long long)(b*Sc + row))*(3*Dc) + Dc + h*HDc + seg*8], 16);
    }
    CP_COMMIT;
#pragma unroll
    for (int l = 0; l < 2; l++) {
        int lin = tid + l*256;
        int row = lin >> 3;
        int seg = lin & 7;
        cpasync16(&Vb[row*AT_LDH + seg*8],
                  &g_qkv[((long long)(b*Sc + row))*(3*Dc) + 2*Dc + h*HDc + seg*8], 16);
    }
    CP_COMMIT;

    float o[8][4];
#pragma unroll
    for (int n = 0; n < 8; n++)
#pragma unroll
        for (int j = 0; j < 4; j++) o[n][j] = 0.f;
    float lp0 = 0.f, lp1 = 0.f;

    for (int t0 = 0; t0 < Sc; t0 += 64) {
        CP_WAIT1;
        __syncthreads();

        float sacc[8][4];
#pragma unroll
        for (int n = 0; n < 8; n++)
#pragma unroll
            for (int j = 0; j < 4; j++) sacc[n][j] = 0.f;

#pragma unroll
        for (int kc = 0; kc < 4; kc++) {
            int kb = kc*8;
            u32 a[4];
            a[0] = Qb2[r0*AT_LD2 + kb + t];
            a[1] = Qb2[r1*AT_LD2 + kb + t];
            a[2] = Qb2[r0*AT_LD2 + kb + t + 4];
            a[3] = Qb2[r1*AT_LD2 + kb + t + 4];
#pragma unroll
            for (int n = 0; n < 8; n++) {
                u32 b0 = Kb2[(n*8 + g)*AT_LD2 + kb + t];
                u32 b1 = Kb2[(n*8 + g)*AT_LD2 + kb + t + 4];
                mma_f16(sacc[n], a, b0, b1);
            }
        }

        __syncthreads();

        if (t0 + 64 < Sc) {
#pragma unroll
            for (int l = 0; l < 2; l++) {
                int lin = tid + l*256;
                int row = lin >> 3;
                int seg = lin & 7;
                cpasync16(&Kb[row*AT_LDH + seg*8],
                          &g_qkv[((long long)(b*Sc + t0 + 64 + row))*(3*Dc) + Dc + h*HDc + seg*8], 16);
            }
        }
        CP_COMMIT;

#pragma unroll
        for (int n = 0; n < 8; n++) {
            __half h0 = __float2half_rn(__expf(sacc[n][0]));
            __half h1 = __float2half_rn(__expf(sacc[n][1]));
            __half h2 = __float2half_rn(__expf(sacc[n][2]));
            __half h3 = __float2half_rn(__expf(sacc[n][3]));
            lp0 += __half2float(h0) + __half2float(h1);
            lp1 += __half2float(h2) + __half2float(h3);
            __half2 p0 = __halves2half2(h0, h1);
            __half2 p1 = __halves2half2(h2, h3);
            Pb2[r0*AT_LD2 + n*4 + t] = *(u32*)&p0;
            Pb2[r1*AT_LD2 + n*4 + t] = *(u32*)&p1;
        }
        __syncwarp();

        CP_WAIT1;
        __syncthreads();

#pragma unroll
        for (int kc = 0; kc < 4; kc++) {
            int kr = kc*16;
            u32 a[4];
            a[0] = Pb2[r0*AT_LD2 + kc*8 + t];
            a[1] = Pb2[r1*AT_LD2 + kc*8 + t];
            a[2] = Pb2[r0*AT_LD2 + kc*8 + t + 4];
            a[3] = Pb2[r1*AT_LD2 + kc*8 + t + 4];
#pragma unroll
            for (int np = 0; np < 4; np++) {
                int ntA = np*2 + (lane >> 4);
                u32 bq[4];
                ldm_x4_trans(bq, &Vb[(kr + (lane & 15))*AT_LDH + ntA*8]);
                mma_f16(o[np*2],     a, bq[0], bq[1]);
                mma_f16(o[np*2 + 1], a, bq[2], bq[3]);
            }
        }

        __syncthreads();

        if (t0 + 64 < Sc) {
#pragma unroll
            for (int l = 0; l < 2; l++) {
                int lin = tid + l*256;
                int row = lin >> 3;
                int seg = lin & 7;
                cpasync16(&Vb[row*AT_LDH + seg*8],
                          &g_qkv[((long long)(b*Sc + t0 + 64 + row))*(3*Dc) + 2*Dc + h*HDc + seg*8], 16);
            }
        }
        CP_COMMIT;
    }

    float lr0 = lp0, lr1 = lp1;
    lr0 += __shfl_xor_sync(0xffffffffu, lr0, 1);
    lr0 += __shfl_xor_sync(0xffffffffu, lr0, 2);
    lr1 += __shfl_xor_sync(0xffffffffu, lr1, 1);
    lr1 += __shfl_xor_sync(0xffffffffu, lr1, 2);
    float inv0 = 1.0f / lr0;
    float inv1 = 1.0f / lr1;
    int srow0 = q0 + r0;
    int srow1 = q0 + r1;
    u32* comb2 = (u32*)g_comb;
#pragma unroll
    for (int n = 0; n < 8; n++) {
        __half2 w0 = __halves2half2(__float2half_rn(o[n][0]*inv0), __float2half_rn(o[n][1]*inv0));
        __half2 w1 = __halves2half2(__float2half_rn(o[n][2]*inv1), __float2half_rn(o[n][3]*inv1));
        comb2[((long long)(b*Sc + srow0))*(Dc/2) + h*(HDc/2) + n*4 + t] = *(u32*)&w0;
        comb2[((long long)(b*Sc + srow1))*(Dc/2) + h*(HDc/2) + n*4 + t] = *(u32*)&w1;
    }
}

// ---------------------------------------------------------------------------
// Launch
// ---------------------------------------------------------------------------
extern "C" void kernel_launch(void* const* d_in, const int* in_sizes, int n_in,
                              void* d_out, int out_size)
{
    const float* inputs = (const float*)d_in[0];
    const float* Wq = (const float*)d_in[1];
    const float* bq = (const float*)d_in[2];
    const float* Wk = (const float*)d_in[3];
    const float* bk = (const float*)d_in[4];
    const float* Wv = (const float*)d_in[5];
    const float* bv = (const float*)d_in[6];
    const float* Wt = (const float*)d_in[7];
    const float* bt = (const float*)d_in[8];
    const float* Wo = (const float*)d_in[9];
    const float* bo = (const float*)d_in[10];
    float* out = (float*)d_out;

    __half *p_qkv, *p_comb, *p_up, *p_wcat, *p_woT, *p_wt, *p_in;
    float *p_part, *p_bcat;
    cudaGetSymbolAddress((void**)&p_qkv,  g_qkv);
    cudaGetSymbolAddress((void**)&p_comb, g_comb);
    cudaGetSymbolAddress((void**)&p_up,   g_up);
    cudaGetSymbolAddress((void**)&p_part, g_part);
    cudaGetSymbolAddress((void**)&p_wcat, g_wcat);
    cudaGetSymbolAddress((void**)&p_bcat, g_bcat);
    cudaGetSymbolAddress((void**)&p_woT,  g_woT);
    cudaGetSymbolAddress((void**)&p_wt,   g_wt);
    cudaGetSymbolAddress((void**)&p_in,   g_in);
    (void)in_sizes; (void)n_in; (void)out_size;

    const int attn_smem = ASM_TOT * (int)sizeof(__half);   // 55296 B
    cudaFuncSetAttribute(attn_kernel, cudaFuncAttributeMaxDynamicSharedMemorySize, attn_smem);
    cudaFuncSetAttribute(tgemm_kernel, cudaFuncAttributeMaxDynamicSharedMemorySize, TG_SMEM_B);

    // 1. Pack + convert to fp16
    {
        int total = Ic*3*Dc + Dc*Ic + Pc*Sc + Bc*Sc*Ic + 3*Dc;
        pack_kernel<<<(total + 255)/256, 256>>>(inputs, Wq, bq, Wk, bk, Wv, bv, Wt, Wo);
    }

    // 2. QKV GEMM: g_in[8192,512] x wcat[512,1536] -> g_qkv fp16 (Q scaled)
    {
        dim3 grid(3*Dc/128, (Bc*Sc)/128, 1);
        tgemm_kernel<<<grid, 256, TG_SMEM_B>>>(p_in, Ic, 0,
                                    p_wcat, 3*Dc, 0,
                                    p_qkv, 3*Dc, 0,
                                    Bc*Sc, 3*Dc, Ic, p_bcat, 1, 1, /*outMode=*/2);
    }

    // 3. Attention -> g_comb fp16
    attn_kernel<<<dim3(Sc/128, Hc, Bc), 256, attn_smem>>>();

    // 4. Temporal GEMM, split-K x4: g_wt[720,2048] x comb_b[2048,512] -> partials
    {
        dim3 grid(Dc/128, (Pc + 127)/128, Bc*4);
        tgemm_kernel<<<grid, 256, TG_SMEM_B>>>(p_wt, Sc, 0,
                                    p_comb, Dc, (long long)Sc*Dc,
                                    p_part, Dc, (long long)Pc*Dc,
                                    Pc, Dc, Sc/4, (const float*)0, 0, 4, /*outMode=*/0);
        int MN = Pc*Dc;
        int total4 = Bc*MN/4;
        reduce_kernel<<<(total4 + 255)/256, 256>>>(p_up, p_part, bt, 2, Dc, MN, 4, total4, /*outKind=*/1);
    }

    // 5. Output GEMM, split-K x2: up[2880,512] x woT[512,512] -> out f32 (+bo)
    {
        dim3 grid(Ic/128, (Bc*Pc + 127)/128, 2);
        tgemm_kernel<<<grid, 256, TG_SMEM_B>>>(p_up, Dc, 0,
                                    p_woT, Ic, 0,
                                    p_part, Ic, (long long)(Bc*Pc)*Ic,
                                    Bc*Pc, Ic, Dc/2, (const float*)0, 0, 2, /*outMode=*/0);
        int MN = Bc*Pc*Ic;
        int total4 = MN/4;
        reduce_kernel<<<(total4 + 255)/256, 256>>>(out, p_part, bo, 1, Ic, MN, 2, total4, /*outKind=*/0);
    }
}